// round 1
// baseline (speedup 1.0000x reference)
#include <cuda_runtime.h>
#include <math.h>
#include <stdint.h>

// Problem constants
#define kB 8
#define kS 2048
#define kD 1024
#define kC 5
#define kM (kB * kS)  // 16384

// ---------------------------------------------------------------------------
// Scratch (device globals: allocation-free per harness rules)
// ---------------------------------------------------------------------------
__device__ float g_ctx[(size_t)kM * kD];   // 64 MB
__device__ float g_h1 [(size_t)kM * 512];  // 32 MB
__device__ float g_h  [(size_t)kM * kD];   // 64 MB
__device__ float g_hb [(size_t)kM * 256];  // 16 MB
__device__ float g_hc [(size_t)kM * 512];  // 32 MB
__device__ float g_ctbw[kM];

// ---------------------------------------------------------------------------
// ctx kernel: per (b, d) serial scan over t. Coalesced across d.
// ---------------------------------------------------------------------------
__global__ void ctx_kernel(const float* __restrict__ x) {
    const int b = blockIdx.x;
    const int d = blockIdx.y * blockDim.x + threadIdx.x;
    const float* xp = x + (size_t)b * kS * kD + d;
    float* cp = g_ctx + (size_t)b * kS * kD + d;

    float total = 0.f;
    for (int t = 0; t < kS; t++) total += xp[(size_t)t * kD];

    float csum = 0.f;
    const float inv_edge = 1.f / (float)(kS - 1);
    for (int t = 0; t < kS; t++) {
        float xv = xp[(size_t)t * kD];
        float prefix = csum;       // exclusive prefix = csum - x
        csum += xv;
        float suffix = total - csum;
        float val;
        if (t == 0 || t == kS - 1) {
            val = (prefix + suffix) * inv_edge;
        } else {
            float pm = prefix / (float)t;               // t >= 1
            float sm = suffix / (float)(kS - 1 - t);    // >= 1
            val = 0.5f * (pm + sm);
        }
        cp[(size_t)t * kD] = val;
    }
}

// ---------------------------------------------------------------------------
// Generic SGEMM: C[M,N] = act( [A1|A2][M,K1+K2] @ B[K,N] + bias + ct@Wtail )
// 128x128 block tile, BK=8, 256 threads, 8x8 per thread.
// A1/A2 row-major with row strides K1/K2. B row-major stride N.
// Wtail (optional): [5,N]; ct: [M,5] — folds concat([x, ct]) tail columns.
// ---------------------------------------------------------------------------
__global__ __launch_bounds__(256) void sgemm_kernel(
    const float* __restrict__ A1, const float* __restrict__ A2,
    const float* __restrict__ Bm, const float* __restrict__ bias,
    float* __restrict__ Cout,
    int N, int K1, int K2, int relu_flag,
    const float* __restrict__ ct, const float* __restrict__ Wtail)
{
    constexpr int BM = 128, BN = 128, BK = 8;
    __shared__ float As[BK][BM];
    __shared__ float Bs[BK][BN];

    const int tid  = threadIdx.x;
    const int brow = blockIdx.y * BM;
    const int bcol = blockIdx.x * BN;
    const int K    = K1 + K2;

    const int a_m = tid >> 1;          // 0..127
    const int a_k = (tid & 1) * 4;     // 0 or 4
    const int b_k = tid >> 5;          // 0..7
    const int b_n = (tid & 31) * 4;    // 0..124
    const int tr  = (tid >> 4) * 8;    // 0..120
    const int tc  = (tid & 15) * 8;    // 0..120

    const size_t gm = (size_t)(brow + a_m);

    float acc[8][8];
#pragma unroll
    for (int i = 0; i < 8; i++)
#pragma unroll
        for (int j = 0; j < 8; j++) acc[i][j] = 0.f;

    for (int kt = 0; kt < K; kt += BK) {
        const int kg = kt + a_k;
        float4 av;
        if (kg < K1) av = *reinterpret_cast<const float4*>(A1 + gm * K1 + kg);
        else         av = *reinterpret_cast<const float4*>(A2 + gm * K2 + (kg - K1));
        As[a_k + 0][a_m] = av.x;
        As[a_k + 1][a_m] = av.y;
        As[a_k + 2][a_m] = av.z;
        As[a_k + 3][a_m] = av.w;

        float4 bv4 = *reinterpret_cast<const float4*>(
            Bm + (size_t)(kt + b_k) * N + bcol + b_n);
        *reinterpret_cast<float4*>(&Bs[b_k][b_n]) = bv4;

        __syncthreads();
#pragma unroll
        for (int kk = 0; kk < BK; kk++) {
            float ra[8], rb[8];
            *reinterpret_cast<float4*>(ra)     = *reinterpret_cast<const float4*>(&As[kk][tr]);
            *reinterpret_cast<float4*>(ra + 4) = *reinterpret_cast<const float4*>(&As[kk][tr + 4]);
            *reinterpret_cast<float4*>(rb)     = *reinterpret_cast<const float4*>(&Bs[kk][tc]);
            *reinterpret_cast<float4*>(rb + 4) = *reinterpret_cast<const float4*>(&Bs[kk][tc + 4]);
#pragma unroll
            for (int i = 0; i < 8; i++)
#pragma unroll
                for (int j = 0; j < 8; j++)
                    acc[i][j] = fmaf(ra[i], rb[j], acc[i][j]);
        }
        __syncthreads();
    }

    // Epilogue
    float bvv[8];
#pragma unroll
    for (int j = 0; j < 8; j++) bvv[j] = bias[bcol + tc + j];

    float wt[5][8];
    if (Wtail) {
#pragma unroll
        for (int c = 0; c < 5; c++)
#pragma unroll
            for (int j = 0; j < 8; j++) wt[c][j] = Wtail[c * N + bcol + tc + j];
    }

#pragma unroll
    for (int i = 0; i < 8; i++) {
        const size_t m = (size_t)(brow + tr + i);
        float ctm[5];
        if (Wtail) {
#pragma unroll
            for (int c = 0; c < 5; c++) ctm[c] = ct[m * 5 + c];
        }
        float outv[8];
#pragma unroll
        for (int j = 0; j < 8; j++) {
            float v = acc[i][j] + bvv[j];
            if (Wtail) {
#pragma unroll
                for (int c = 0; c < 5; c++) v = fmaf(ctm[c], wt[c][j], v);
            }
            if (relu_flag) v = fmaxf(v, 0.f);
            outv[j] = v;
        }
        *reinterpret_cast<float4*>(Cout + m * N + bcol + tc)     = *reinterpret_cast<float4*>(outv);
        *reinterpret_cast<float4*>(Cout + m * N + bcol + tc + 4) = *reinterpret_cast<float4*>(outv + 4);
    }
}

// ---------------------------------------------------------------------------
// content_types: per-row (128 threads) dot-5 over K=512, softmax(5),
// relevance = 1 - p[3], ctbw = p @ bias_weights
// ---------------------------------------------------------------------------
__global__ __launch_bounds__(128) void content_kernel(
    const float* __restrict__ Wcc2, const float* __restrict__ bcc2,
    float* __restrict__ out_ct, float* __restrict__ out_rel)
{
    const int m = blockIdx.x;
    const float* row = g_h1 + (size_t)m * 512;
    float acc[5] = {0, 0, 0, 0, 0};
    for (int k = threadIdx.x; k < 512; k += 128) {
        float v = row[k];
#pragma unroll
        for (int c = 0; c < 5; c++) acc[c] = fmaf(v, Wcc2[k * 5 + c], acc[c]);
    }
#pragma unroll
    for (int c = 0; c < 5; c++)
#pragma unroll
        for (int o = 16; o; o >>= 1) acc[c] += __shfl_xor_sync(0xffffffffu, acc[c], o);

    __shared__ float s[4][5];
    const int w = threadIdx.x >> 5;
    if ((threadIdx.x & 31) == 0) {
#pragma unroll
        for (int c = 0; c < 5; c++) s[w][c] = acc[c];
    }
    __syncthreads();
    if (threadIdx.x == 0) {
        float t[5];
#pragma unroll
        for (int c = 0; c < 5; c++) t[c] = s[0][c] + s[1][c] + s[2][c] + s[3][c] + bcc2[c];
        float mx = t[0];
#pragma unroll
        for (int c = 1; c < 5; c++) mx = fmaxf(mx, t[c]);
        float e[5], sum = 0.f;
#pragma unroll
        for (int c = 0; c < 5; c++) { e[c] = expf(t[c] - mx); sum += e[c]; }
        const float inv = 1.f / sum;
        const float bw[5] = {0.1f, 1.0f, 0.8f, 0.3f, 0.5f};
        float ws = 0.f;
#pragma unroll
        for (int c = 0; c < 5; c++) {
            float p = e[c] * inv;
            out_ct[(size_t)m * 5 + c] = p;
            ws = fmaf(p, bw[c], ws);
        }
        out_rel[m] = 1.f - e[3] * inv;
        g_ctbw[m] = ws;
    }
}

// ---------------------------------------------------------------------------
// Block-wide sum reduction (256 threads)
// ---------------------------------------------------------------------------
__device__ __forceinline__ float block_reduce_sum(float v, float* sbuf) {
#pragma unroll
    for (int o = 16; o; o >>= 1) v += __shfl_xor_sync(0xffffffffu, v, o);
    const int w = threadIdx.x >> 5;
    __syncthreads();
    if ((threadIdx.x & 31) == 0) sbuf[w] = v;
    __syncthreads();
    if (threadIdx.x == 0) {
        float r = 0.f;
        for (int i = 0; i < (int)(blockDim.x >> 5); i++) r += sbuf[i];
        sbuf[0] = r;
    }
    __syncthreads();
    return sbuf[0];
}

// ---------------------------------------------------------------------------
// LayerNorm + exact GELU + dot(W_cd2) + sigmoid -> enhanced = max(contra, ct[2])
// one block (256 threads) per row of g_h [kM, 1024]
// ---------------------------------------------------------------------------
__global__ __launch_bounds__(256) void ln_head_kernel(
    const float* __restrict__ gln, const float* __restrict__ beln,
    const float* __restrict__ W2, const float* __restrict__ b2,
    const float* __restrict__ ct, float* __restrict__ out_enh)
{
    __shared__ float sbuf[8];
    const int m = blockIdx.x;
    const int t = threadIdx.x;
    const float4 v = reinterpret_cast<const float4*>(g_h + (size_t)m * kD)[t];

    float s = v.x + v.y + v.z + v.w;
    float q = v.x * v.x + v.y * v.y + v.z * v.z + v.w * v.w;
    const float sum = block_reduce_sum(s, sbuf);
    const float sq  = block_reduce_sum(q, sbuf);
    const float mu  = sum * (1.f / (float)kD);
    const float var = sq * (1.f / (float)kD) - mu * mu;
    const float rstd = rsqrtf(var + 1e-5f);

    const float4 gv  = reinterpret_cast<const float4*>(gln)[t];
    const float4 bev = reinterpret_cast<const float4*>(beln)[t];
    const float4 wv  = reinterpret_cast<const float4*>(W2)[t];

    const float kInvSqrt2 = 0.70710678118654752f;
    float dot = 0.f;
    float y;
    y = (v.x - mu) * rstd * gv.x + bev.x; y = 0.5f * y * (1.f + erff(y * kInvSqrt2)); dot = fmaf(y, wv.x, dot);
    y = (v.y - mu) * rstd * gv.y + bev.y; y = 0.5f * y * (1.f + erff(y * kInvSqrt2)); dot = fmaf(y, wv.y, dot);
    y = (v.z - mu) * rstd * gv.z + bev.z; y = 0.5f * y * (1.f + erff(y * kInvSqrt2)); dot = fmaf(y, wv.z, dot);
    y = (v.w - mu) * rstd * gv.w + bev.w; y = 0.5f * y * (1.f + erff(y * kInvSqrt2)); dot = fmaf(y, wv.w, dot);

    dot = block_reduce_sum(dot, sbuf);
    if (t == 0) {
        float cont = 1.f / (1.f + expf(-(dot + b2[0])));
        out_enh[m] = fmaxf(cont, ct[(size_t)m * 5 + 2]);
    }
}

// ---------------------------------------------------------------------------
// weighted_bias: warp-per-row dot over K=256, sigmoid, * ctbw
// ---------------------------------------------------------------------------
__global__ __launch_bounds__(256) void bias_out_kernel(
    const float* __restrict__ W, const float* __restrict__ b,
    float* __restrict__ out_wb)
{
    const int m = blockIdx.x * 8 + (threadIdx.x >> 5);
    const int l = threadIdx.x & 31;
    const float* row = g_hb + (size_t)m * 256;
    float acc = 0.f;
#pragma unroll
    for (int i = 0; i < 8; i++) acc = fmaf(row[l + 32 * i], W[l + 32 * i], acc);
#pragma unroll
    for (int o = 16; o; o >>= 1) acc += __shfl_xor_sync(0xffffffffu, acc, o);
    if (l == 0) {
        float bs = 1.f / (1.f + expf(-(acc + b[0])));
        out_wb[m] = bs * g_ctbw[m];
    }
}

// ---------------------------------------------------------------------------
// credibility: warp-per-row dot over K=512, sigmoid
// ---------------------------------------------------------------------------
__global__ __launch_bounds__(256) void cred_out_kernel(
    const float* __restrict__ W, const float* __restrict__ b,
    float* __restrict__ out_cred)
{
    const int m = blockIdx.x * 8 + (threadIdx.x >> 5);
    const int l = threadIdx.x & 31;
    const float* row = g_hc + (size_t)m * 512;
    float acc = 0.f;
#pragma unroll
    for (int i = 0; i < 16; i++) acc = fmaf(row[l + 32 * i], W[l + 32 * i], acc);
#pragma unroll
    for (int o = 16; o; o >>= 1) acc += __shfl_xor_sync(0xffffffffu, acc, o);
    if (l == 0) out_cred[m] = 1.f / (1.f + expf(-(acc + b[0])));
}

// ---------------------------------------------------------------------------
// Launch
// ---------------------------------------------------------------------------
extern "C" void kernel_launch(void* const* d_in, const int* in_sizes, int n_in,
                              void* d_out, int out_size)
{
    (void)in_sizes; (void)n_in; (void)out_size;

    const float* x    = (const float*)d_in[0];
    const float* Wcc1 = (const float*)d_in[1];
    const float* bcc1 = (const float*)d_in[2];
    const float* Wcc2 = (const float*)d_in[3];
    const float* bcc2 = (const float*)d_in[4];
    const float* Wcd1 = (const float*)d_in[5];
    const float* bcd1 = (const float*)d_in[6];
    const float* gln  = (const float*)d_in[7];
    const float* beln = (const float*)d_in[8];
    const float* Wcd2 = (const float*)d_in[9];
    const float* bcd2 = (const float*)d_in[10];
    const float* Wbe1 = (const float*)d_in[11];
    const float* bbe1 = (const float*)d_in[12];
    const float* Wbe2 = (const float*)d_in[13];
    const float* bbe2 = (const float*)d_in[14];
    const float* Wcr1 = (const float*)d_in[15];
    const float* bcr1 = (const float*)d_in[16];
    const float* Wcr2 = (const float*)d_in[17];
    const float* bcr2 = (const float*)d_in[18];

    float* out_x    = (float*)d_out;
    float* out_ct   = out_x + (size_t)kM * kD;
    float* out_enh  = out_ct + (size_t)kM * kC;
    float* out_wb   = out_enh + kM;
    float* out_rel  = out_wb + kM;
    float* out_cred = out_rel + kM;

    float *ctxp, *h1p, *hp, *hbp, *hcp;
    cudaGetSymbolAddress((void**)&ctxp, g_ctx);
    cudaGetSymbolAddress((void**)&h1p,  g_h1);
    cudaGetSymbolAddress((void**)&hp,   g_h);
    cudaGetSymbolAddress((void**)&hbp,  g_hb);
    cudaGetSymbolAddress((void**)&hcp,  g_hc);

    // x passthrough output
    cudaMemcpyAsync(out_x, x, (size_t)kM * kD * sizeof(float),
                    cudaMemcpyDeviceToDevice, 0);

    // ctx
    ctx_kernel<<<dim3(kB, kD / 256), 256>>>(x);

    // G1: h1 = relu(x @ Wcc1 + bcc1)   [16384,1024]x[1024,512]
    sgemm_kernel<<<dim3(512 / 128, kM / 128), 256>>>(
        x, nullptr, Wcc1, bcc1, h1p, 512, kD, 0, 1, nullptr, nullptr);

    // content types (softmax), relevance, ctbw
    content_kernel<<<kM, 128>>>(Wcc2, bcc2, out_ct, out_rel);

    // G3: h = [x|ctx] @ Wcd1 + bcd1    [16384,2048]x[2048,1024]
    sgemm_kernel<<<dim3(1024 / 128, kM / 128), 256>>>(
        x, ctxp, Wcd1, bcd1, hp, kD, kD, kD, 0, nullptr, nullptr);

    // LN + gelu + head -> enhanced
    ln_head_kernel<<<kM, 256>>>(gln, beln, Wcd2, bcd2, out_ct, out_enh);

    // G4: hb = relu(x @ Wbe1 + bbe1)   [16384,1024]x[1024,256]
    sgemm_kernel<<<dim3(256 / 128, kM / 128), 256>>>(
        x, nullptr, Wbe1, bbe1, hbp, 256, kD, 0, 1, nullptr, nullptr);

    // weighted_bias
    bias_out_kernel<<<kM / 8, 256>>>(Wbe2, bbe2, out_wb);

    // G6: hc = relu([x|ct] @ Wcr1 + bcr1) — ct tail folded into epilogue
    sgemm_kernel<<<dim3(512 / 128, kM / 128), 256>>>(
        x, nullptr, Wcr1, bcr1, hcp, 512, kD, 0, 1,
        out_ct, Wcr1 + (size_t)kD * 512);

    // credibility
    cred_out_kernel<<<kM / 8, 256>>>(Wcr2, bcr2, out_cred);
}

// round 3
// speedup vs baseline: 2.9854x; 2.9854x over previous
#include <cuda_runtime.h>
#include <math.h>
#include <stdint.h>

// Problem constants
#define kB 8
#define kS 2048
#define kD 1024
#define kC 5
#define kM (kB * kS)  // 16384

// ---------------------------------------------------------------------------
// Scratch (device globals)
// ---------------------------------------------------------------------------
__device__ float g_ctx[(size_t)kM * kD];    // 64 MB
__device__ float g_h1 [(size_t)kM * 512];   // 32 MB
__device__ float g_h  [(size_t)kM * kD];    // 64 MB
__device__ float g_hb [(size_t)kM * 256];   // 16 MB
__device__ float g_hc [(size_t)kM * 512];   // 32 MB
__device__ float g_ctbw[kM];
__device__ float g_part[(size_t)kB * 32 * kD];
__device__ float g_wt[(size_t)1024*2048 + 512*1024 + 256*1024 + 512*1024];

#define WT_CD1 0
#define WT_CC1 ((size_t)1024*2048)
#define WT_BE1 (WT_CC1 + (size_t)512*1024)
#define WT_CR1 (WT_BE1 + (size_t)256*1024)

// ---------------------------------------------------------------------------
// tf32 helpers
// ---------------------------------------------------------------------------
__device__ __forceinline__ uint32_t tf32r(float v) {
    uint32_t o;
    asm("cvt.rna.tf32.f32 %0, %1;" : "=r"(o) : "f"(v));
    return o;
}
__device__ __forceinline__ float4 tf32x4f(float4 v) {
    float4 o;
    o.x = __uint_as_float(tf32r(v.x));
    o.y = __uint_as_float(tf32r(v.y));
    o.z = __uint_as_float(tf32r(v.z));
    o.w = __uint_as_float(tf32r(v.w));
    return o;
}

__device__ __forceinline__ void mma_tf32(float* d, const uint32_t* a, const uint32_t* b) {
    asm volatile(
        "mma.sync.aligned.m16n8k8.row.col.f32.tf32.tf32.f32 "
        "{%0,%1,%2,%3}, {%4,%5,%6,%7}, {%8,%9}, {%0,%1,%2,%3};"
        : "+f"(d[0]), "+f"(d[1]), "+f"(d[2]), "+f"(d[3])
        : "r"(a[0]), "r"(a[1]), "r"(a[2]), "r"(a[3]),
          "r"(b[0]), "r"(b[1]));
}

// ---------------------------------------------------------------------------
// mma.sync tf32 GEMM: C[M,N] = act([A1|A2] @ Bt^T + bias (+ ct@Wtail))
// CTA tile 128x128, BK=32, 256 threads (8 warps 2x4), warp tile 64x32.
// A row-major [M,K] (fp32, cvt to tf32 on load); Bt row-major [N,K]
// (already tf32-rounded by transpose_kernel).
// ---------------------------------------------------------------------------
#define BM 128
#define BN 128
#define BK 32
#define LDA 36                        // BK + 4 pad: fragment LDS conflict-free
#define SMEM_SZ (4 * BM * LDA * 4)    // 2 bufs * (A + B) = 73728 B

__global__ __launch_bounds__(256, 1) void gemm_mma(
    const float* __restrict__ A1, const float* __restrict__ A2,
    const float* __restrict__ Bt, const float* __restrict__ bias,
    float* __restrict__ C, int N, int K1, int K2, int relu_flag,
    const float* __restrict__ ct, const float* __restrict__ Wtail, int ldtail)
{
    extern __shared__ float sm[];
    float* As = sm;                   // [2][BM][LDA]
    float* Bs = sm + 2 * BM * LDA;    // [2][BN][LDA]

    const int tid  = threadIdx.x;
    const int lane = tid & 31;
    const int wid  = tid >> 5;
    const int wm   = wid >> 2;        // 0..1
    const int wn   = wid & 3;         // 0..3
    const int brow = blockIdx.y * BM;
    const int bcol = blockIdx.x * BN;
    const int K    = K1 + K2;

    const int ldr = tid >> 1;         // 0..127 (row within tile)
    const int ldc = (tid & 1) * 16;   // 0 or 16 (col base)

    float acc[4][4][4];
#pragma unroll
    for (int i = 0; i < 4; i++)
#pragma unroll
        for (int j = 0; j < 4; j++)
#pragma unroll
            for (int q = 0; q < 4; q++) acc[i][j][q] = 0.f;

    const int iters = K / BK;
    float4 abuf[4], bbuf[4];

    // prologue: load tile 0
    {
        const float* ar = A1 + (size_t)(brow + ldr) * K1 + ldc;  // kt=0 < K1 always
        const float* br = Bt + (size_t)(bcol + ldr) * K + ldc;
#pragma unroll
        for (int j = 0; j < 4; j++) {
            abuf[j] = reinterpret_cast<const float4*>(ar)[j];
            bbuf[j] = reinterpret_cast<const float4*>(br)[j];
        }
        float* ad = As + ldr * LDA + ldc;
        float* bd = Bs + ldr * LDA + ldc;
#pragma unroll
        for (int j = 0; j < 4; j++) {
            reinterpret_cast<float4*>(ad)[j] = tf32x4f(abuf[j]);
            reinterpret_cast<float4*>(bd)[j] = bbuf[j];
        }
    }
    __syncthreads();

    for (int i = 0; i < iters; i++) {
        const int cur = i & 1;

        // prefetch next tile into registers
        if (i + 1 < iters) {
            const int kt = (i + 1) * BK;
            const float* ar = (kt < K1)
                ? A1 + (size_t)(brow + ldr) * K1 + kt + ldc
                : A2 + (size_t)(brow + ldr) * K2 + (kt - K1) + ldc;
            const float* br = Bt + (size_t)(bcol + ldr) * K + kt + ldc;
#pragma unroll
            for (int j = 0; j < 4; j++) {
                abuf[j] = reinterpret_cast<const float4*>(ar)[j];
                bbuf[j] = reinterpret_cast<const float4*>(br)[j];
            }
        }

        // compute on buffer cur
        {
            const float* ab = As + cur * BM * LDA + (wm * 64 + (lane >> 2)) * LDA + (lane & 3);
            const float* bb = Bs + cur * BM * LDA + (wn * 32 + (lane >> 2)) * LDA + (lane & 3);
#pragma unroll
            for (int ks = 0; ks < 4; ks++) {
                uint32_t af[4][4];
#pragma unroll
                for (int mt = 0; mt < 4; mt++) {
                    const float* p = ab + mt * 16 * LDA + ks * 8;
                    af[mt][0] = __float_as_uint(p[0]);
                    af[mt][1] = __float_as_uint(p[8 * LDA]);
                    af[mt][2] = __float_as_uint(p[4]);
                    af[mt][3] = __float_as_uint(p[8 * LDA + 4]);
                }
                uint32_t bf[4][2];
#pragma unroll
                for (int nt = 0; nt < 4; nt++) {
                    const float* p = bb + nt * 8 * LDA + ks * 8;
                    bf[nt][0] = __float_as_uint(p[0]);
                    bf[nt][1] = __float_as_uint(p[4]);
                }
#pragma unroll
                for (int mt = 0; mt < 4; mt++)
#pragma unroll
                    for (int nt = 0; nt < 4; nt++)
                        mma_tf32(acc[mt][nt], af[mt], bf[nt]);
            }
        }
        __syncthreads();

        // store next tile
        if (i + 1 < iters) {
            const int nxt = cur ^ 1;
            float* ad = As + nxt * BM * LDA + ldr * LDA + ldc;
            float* bd = Bs + nxt * BM * LDA + ldr * LDA + ldc;
#pragma unroll
            for (int j = 0; j < 4; j++) {
                reinterpret_cast<float4*>(ad)[j] = tf32x4f(abuf[j]);
                reinterpret_cast<float4*>(bd)[j] = bbuf[j];
            }
            __syncthreads();
        }
    }

    // Epilogue
#pragma unroll
    for (int mt = 0; mt < 4; mt++) {
        const int gr0 = brow + wm * 64 + mt * 16 + (lane >> 2);
#pragma unroll
        for (int h = 0; h < 2; h++) {
            const int row = gr0 + 8 * h;
            float ctm[5];
            if (Wtail) {
#pragma unroll
                for (int c = 0; c < 5; c++) ctm[c] = ct[(size_t)row * 5 + c];
            }
#pragma unroll
            for (int nt = 0; nt < 4; nt++) {
                const int gc = bcol + wn * 32 + nt * 8 + (lane & 3) * 2;
                float v0 = acc[mt][nt][2 * h]     + bias[gc];
                float v1 = acc[mt][nt][2 * h + 1] + bias[gc + 1];
                if (Wtail) {
#pragma unroll
                    for (int c = 0; c < 5; c++) {
                        v0 = fmaf(ctm[c], Wtail[c * ldtail + gc],     v0);
                        v1 = fmaf(ctm[c], Wtail[c * ldtail + gc + 1], v1);
                    }
                }
                if (relu_flag) { v0 = fmaxf(v0, 0.f); v1 = fmaxf(v1, 0.f); }
                float2 o; o.x = v0; o.y = v1;
                *reinterpret_cast<float2*>(C + (size_t)row * N + gc) = o;
            }
        }
    }
}

// ---------------------------------------------------------------------------
// Weight transpose with tf32 rounding: W[K,N] -> Wt[N,K]
// ---------------------------------------------------------------------------
__global__ void transpose_kernel(const float* __restrict__ W, float* __restrict__ Wt,
                                 int K, int N)
{
    __shared__ float tile[32][33];
    const int n0 = blockIdx.x * 32;
    const int k0 = blockIdx.y * 32;
    const int tx = threadIdx.x, ty = threadIdx.y;
#pragma unroll
    for (int i = ty; i < 32; i += 8)
        tile[i][tx] = W[(size_t)(k0 + i) * N + n0 + tx];
    __syncthreads();
#pragma unroll
    for (int i = ty; i < 32; i += 8)
        Wt[(size_t)(n0 + i) * K + k0 + tx] = __uint_as_float(tf32r(tile[tx][i]));
}

// ---------------------------------------------------------------------------
// ctx: chunked scan.  NCH chunks of CH timesteps each.
// ---------------------------------------------------------------------------
#define NCH 32
#define CH 64

__global__ void ctx_partial(const float* __restrict__ x) {
    const int b = blockIdx.x, ch = blockIdx.y;
    const int d = threadIdx.x;
    const float* xp = x + ((size_t)b * kS + (size_t)ch * CH) * kD + d;
    float s0 = 0, s1 = 0, s2 = 0, s3 = 0;
    for (int t = 0; t < CH; t++) {
        const float* row = xp + (size_t)t * kD;
        s0 += row[0]; s1 += row[256]; s2 += row[512]; s3 += row[768];
    }
    float* pp = g_part + ((size_t)b * NCH + ch) * kD + d;
    pp[0] = s0; pp[256] = s1; pp[512] = s2; pp[768] = s3;
}

__global__ void ctx_emit(const float* __restrict__ x) {
    const int b = blockIdx.x, ch = blockIdx.y;
    const int d = threadIdx.x;
    float pre[4] = {0, 0, 0, 0}, tot[4] = {0, 0, 0, 0};
    for (int c = 0; c < NCH; c++) {
        const float* pp = g_part + ((size_t)b * NCH + c) * kD + d;
#pragma unroll
        for (int dd = 0; dd < 4; dd++) {
            float p = pp[dd * 256];
            if (c < ch) pre[dd] += p;
            tot[dd] += p;
        }
    }
    const float inv_edge = 1.f / (float)(kS - 1);
    const float* xp = x + ((size_t)b * kS + (size_t)ch * CH) * kD + d;
    float* cp = g_ctx + ((size_t)b * kS + (size_t)ch * CH) * kD + d;
    for (int t = 0; t < CH; t++) {
        const int tg = ch * CH + t;
        const bool edge = (tg == 0) || (tg == kS - 1);
        const float ip = edge ? inv_edge : (0.5f / fmaxf((float)tg, 1.f));
        const float is = edge ? inv_edge : (0.5f / fmaxf((float)(kS - 1 - tg), 1.f));
#pragma unroll
        for (int dd = 0; dd < 4; dd++) {
            float xv = xp[(size_t)t * kD + dd * 256];
            float prefix = pre[dd];
            pre[dd] += xv;
            float suffix = tot[dd] - pre[dd];
            cp[(size_t)t * kD + dd * 256] = prefix * ip + suffix * is;
        }
    }
}

// ---------------------------------------------------------------------------
// content_types: per-row dot-5 over K=512, softmax(5), relevance, ctbw
// ---------------------------------------------------------------------------
__global__ __launch_bounds__(128) void content_kernel(
    const float* __restrict__ Wcc2, const float* __restrict__ bcc2,
    float* __restrict__ out_ct, float* __restrict__ out_rel)
{
    const int m = blockIdx.x;
    const float* row = g_h1 + (size_t)m * 512;
    float acc[5] = {0, 0, 0, 0, 0};
    for (int k = threadIdx.x; k < 512; k += 128) {
        float v = row[k];
#pragma unroll
        for (int c = 0; c < 5; c++) acc[c] = fmaf(v, Wcc2[k * 5 + c], acc[c]);
    }
#pragma unroll
    for (int c = 0; c < 5; c++)
#pragma unroll
        for (int o = 16; o; o >>= 1) acc[c] += __shfl_xor_sync(0xffffffffu, acc[c], o);

    __shared__ float s[4][5];
    const int w = threadIdx.x >> 5;
    if ((threadIdx.x & 31) == 0) {
#pragma unroll
        for (int c = 0; c < 5; c++) s[w][c] = acc[c];
    }
    __syncthreads();
    if (threadIdx.x == 0) {
        float t[5];
#pragma unroll
        for (int c = 0; c < 5; c++) t[c] = s[0][c] + s[1][c] + s[2][c] + s[3][c] + bcc2[c];
        float mx = t[0];
#pragma unroll
        for (int c = 1; c < 5; c++) mx = fmaxf(mx, t[c]);
        float e[5], sum = 0.f;
#pragma unroll
        for (int c = 0; c < 5; c++) { e[c] = expf(t[c] - mx); sum += e[c]; }
        const float inv = 1.f / sum;
        const float bw[5] = {0.1f, 1.0f, 0.8f, 0.3f, 0.5f};
        float ws = 0.f;
#pragma unroll
        for (int c = 0; c < 5; c++) {
            float p = e[c] * inv;
            out_ct[(size_t)m * 5 + c] = p;
            ws = fmaf(p, bw[c], ws);
        }
        out_rel[m] = 1.f - e[3] * inv;
        g_ctbw[m] = ws;
    }
}

__device__ __forceinline__ float block_reduce_sum(float v, float* sbuf) {
#pragma unroll
    for (int o = 16; o; o >>= 1) v += __shfl_xor_sync(0xffffffffu, v, o);
    const int w = threadIdx.x >> 5;
    __syncthreads();
    if ((threadIdx.x & 31) == 0) sbuf[w] = v;
    __syncthreads();
    if (threadIdx.x == 0) {
        float r = 0.f;
        for (int i = 0; i < (int)(blockDim.x >> 5); i++) r += sbuf[i];
        sbuf[0] = r;
    }
    __syncthreads();
    return sbuf[0];
}

__global__ __launch_bounds__(256) void ln_head_kernel(
    const float* __restrict__ gln, const float* __restrict__ beln,
    const float* __restrict__ W2, const float* __restrict__ b2,
    const float* __restrict__ ct, float* __restrict__ out_enh)
{
    __shared__ float sbuf[8];
    const int m = blockIdx.x;
    const int t = threadIdx.x;
    const float4 v = reinterpret_cast<const float4*>(g_h + (size_t)m * kD)[t];

    float s = v.x + v.y + v.z + v.w;
    float q = v.x * v.x + v.y * v.y + v.z * v.z + v.w * v.w;
    const float sum = block_reduce_sum(s, sbuf);
    const float sq  = block_reduce_sum(q, sbuf);
    const float mu  = sum * (1.f / (float)kD);
    const float var = sq * (1.f / (float)kD) - mu * mu;
    const float rstd = rsqrtf(var + 1e-5f);

    const float4 gv  = reinterpret_cast<const float4*>(gln)[t];
    const float4 bev = reinterpret_cast<const float4*>(beln)[t];
    const float4 wv  = reinterpret_cast<const float4*>(W2)[t];

    const float kInvSqrt2 = 0.70710678118654752f;
    float dot = 0.f;
    float y;
    y = (v.x - mu) * rstd * gv.x + bev.x; y = 0.5f * y * (1.f + erff(y * kInvSqrt2)); dot = fmaf(y, wv.x, dot);
    y = (v.y - mu) * rstd * gv.y + bev.y; y = 0.5f * y * (1.f + erff(y * kInvSqrt2)); dot = fmaf(y, wv.y, dot);
    y = (v.z - mu) * rstd * gv.z + bev.z; y = 0.5f * y * (1.f + erff(y * kInvSqrt2)); dot = fmaf(y, wv.z, dot);
    y = (v.w - mu) * rstd * gv.w + bev.w; y = 0.5f * y * (1.f + erff(y * kInvSqrt2)); dot = fmaf(y, wv.w, dot);

    dot = block_reduce_sum(dot, sbuf);
    if (t == 0) {
        float cont = 1.f / (1.f + expf(-(dot + b2[0])));
        out_enh[m] = fmaxf(cont, ct[(size_t)m * 5 + 2]);
    }
}

__global__ __launch_bounds__(256) void bias_out_kernel(
    const float* __restrict__ W, const float* __restrict__ b,
    float* __restrict__ out_wb)
{
    const int m = blockIdx.x * 8 + (threadIdx.x >> 5);
    const int l = threadIdx.x & 31;
    const float* row = g_hb + (size_t)m * 256;
    float acc = 0.f;
#pragma unroll
    for (int i = 0; i < 8; i++) acc = fmaf(row[l + 32 * i], W[l + 32 * i], acc);
#pragma unroll
    for (int o = 16; o; o >>= 1) acc += __shfl_xor_sync(0xffffffffu, acc, o);
    if (l == 0) {
        float bs = 1.f / (1.f + expf(-(acc + b[0])));
        out_wb[m] = bs * g_ctbw[m];
    }
}

__global__ __launch_bounds__(256) void cred_out_kernel(
    const float* __restrict__ W, const float* __restrict__ b,
    float* __restrict__ out_cred)
{
    const int m = blockIdx.x * 8 + (threadIdx.x >> 5);
    const int l = threadIdx.x & 31;
    const float* row = g_hc + (size_t)m * 512;
    float acc = 0.f;
#pragma unroll
    for (int i = 0; i < 16; i++) acc = fmaf(row[l + 32 * i], W[l + 32 * i], acc);
#pragma unroll
    for (int o = 16; o; o >>= 1) acc += __shfl_xor_sync(0xffffffffu, acc, o);
    if (l == 0) out_cred[m] = 1.f / (1.f + expf(-(acc + b[0])));
}

// ---------------------------------------------------------------------------
// Launch
// ---------------------------------------------------------------------------
extern "C" void kernel_launch(void* const* d_in, const int* in_sizes, int n_in,
                              void* d_out, int out_size)
{
    (void)in_sizes; (void)n_in; (void)out_size;

    const float* x    = (const float*)d_in[0];
    const float* Wcc1 = (const float*)d_in[1];
    const float* bcc1 = (const float*)d_in[2];
    const float* Wcc2 = (const float*)d_in[3];
    const float* bcc2 = (const float*)d_in[4];
    const float* Wcd1 = (const float*)d_in[5];
    const float* bcd1 = (const float*)d_in[6];
    const float* gln  = (const float*)d_in[7];
    const float* beln = (const float*)d_in[8];
    const float* Wcd2 = (const float*)d_in[9];
    const float* bcd2 = (const float*)d_in[10];
    const float* Wbe1 = (const float*)d_in[11];
    const float* bbe1 = (const float*)d_in[12];
    const float* Wbe2 = (const float*)d_in[13];
    const float* bbe2 = (const float*)d_in[14];
    const float* Wcr1 = (const float*)d_in[15];
    const float* bcr1 = (const float*)d_in[16];
    const float* Wcr2 = (const float*)d_in[17];
    const float* bcr2 = (const float*)d_in[18];

    float* out_x    = (float*)d_out;
    float* out_ct   = out_x + (size_t)kM * kD;
    float* out_enh  = out_ct + (size_t)kM * kC;
    float* out_wb   = out_enh + kM;
    float* out_rel  = out_wb + kM;
    float* out_cred = out_rel + kM;

    float *ctxp, *h1p, *hp, *hbp, *hcp, *wtp;
    cudaGetSymbolAddress((void**)&ctxp, g_ctx);
    cudaGetSymbolAddress((void**)&h1p,  g_h1);
    cudaGetSymbolAddress((void**)&hp,   g_h);
    cudaGetSymbolAddress((void**)&hbp,  g_hb);
    cudaGetSymbolAddress((void**)&hcp,  g_hc);
    cudaGetSymbolAddress((void**)&wtp,  g_wt);

    cudaFuncSetAttribute(gemm_mma, cudaFuncAttributeMaxDynamicSharedMemorySize, SMEM_SZ);

    // x passthrough
    cudaMemcpyAsync(out_x, x, (size_t)kM * kD * sizeof(float),
                    cudaMemcpyDeviceToDevice, 0);

    // weight transposes (tf32-rounded)
    transpose_kernel<<<dim3(512/32, 1024/32), dim3(32, 8)>>>(Wcc1, wtp + WT_CC1, 1024, 512);
    transpose_kernel<<<dim3(1024/32, 2048/32), dim3(32, 8)>>>(Wcd1, wtp + WT_CD1, 2048, 1024);
    transpose_kernel<<<dim3(256/32, 1024/32), dim3(32, 8)>>>(Wbe1, wtp + WT_BE1, 1024, 256);
    transpose_kernel<<<dim3(512/32, 1024/32), dim3(32, 8)>>>(Wcr1, wtp + WT_CR1, 1024, 512);

    // ctx
    ctx_partial<<<dim3(kB, NCH), 256>>>(x);
    ctx_emit<<<dim3(kB, NCH), 256>>>(x);

    // G1: h1 = relu(x @ Wcc1 + bcc1)  [16384,1024]x[1024,512]
    gemm_mma<<<dim3(512/BN, kM/BM), 256, SMEM_SZ>>>(
        x, nullptr, wtp + WT_CC1, bcc1, h1p, 512, 1024, 0, 1, nullptr, nullptr, 0);

    content_kernel<<<kM, 128>>>(Wcc2, bcc2, out_ct, out_rel);

    // G3: h = [x|ctx] @ Wcd1 + bcd1   [16384,2048]x[2048,1024]
    gemm_mma<<<dim3(1024/BN, kM/BM), 256, SMEM_SZ>>>(
        x, ctxp, wtp + WT_CD1, bcd1, hp, 1024, 1024, 1024, 0, nullptr, nullptr, 0);

    ln_head_kernel<<<kM, 256>>>(gln, beln, Wcd2, bcd2, out_ct, out_enh);

    // G4: hb = relu(x @ Wbe1 + bbe1)  [16384,1024]x[1024,256]
    gemm_mma<<<dim3(256/BN, kM/BM), 256, SMEM_SZ>>>(
        x, nullptr, wtp + WT_BE1, bbe1, hbp, 256, 1024, 0, 1, nullptr, nullptr, 0);

    bias_out_kernel<<<kM/8, 256>>>(Wbe2, bbe2, out_wb);

    // G6: hc = relu([x|ct] @ Wcr1 + bcr1) — 5-col ct tail folded into epilogue
    gemm_mma<<<dim3(512/BN, kM/BM), 256, SMEM_SZ>>>(
        x, nullptr, wtp + WT_CR1, bcr1, hcp, 512, 1024, 0, 1,
        out_ct, Wcr1 + (size_t)1024 * 512, 512);

    cred_out_kernel<<<kM/8, 256>>>(Wcr2, bcr2, out_cred);
}

// round 4
// speedup vs baseline: 4.0433x; 1.3543x over previous
#include <cuda_runtime.h>
#include <math.h>
#include <stdint.h>

// Problem constants
#define kB 8
#define kS 2048
#define kD 1024
#define kC 5
#define kM (kB * kS)  // 16384

// ---------------------------------------------------------------------------
// Scratch (device globals)
// ---------------------------------------------------------------------------
__device__ float g_ctx[(size_t)kM * kD];    // 64 MB
__device__ float g_h1 [(size_t)kM * 512];   // 32 MB
__device__ float g_h  [(size_t)kM * kD];    // 64 MB
__device__ float g_hb [(size_t)kM * 256];   // 16 MB
__device__ float g_hc [(size_t)kM * 512];   // 32 MB
__device__ float g_ctbw[kM];
__device__ float g_part[(size_t)kB * 32 * kD];
__device__ float g_wt[(size_t)1024*2048 + 512*1024 + 256*1024 + 512*1024];

#define WT_CD1 0
#define WT_CC1 ((size_t)1024*2048)
#define WT_BE1 (WT_CC1 + (size_t)512*1024)
#define WT_CR1 (WT_BE1 + (size_t)256*1024)

// ---------------------------------------------------------------------------
// helpers
// ---------------------------------------------------------------------------
__device__ __forceinline__ uint32_t tf32r(float v) {
    uint32_t o;
    asm("cvt.rna.tf32.f32 %0, %1;" : "=r"(o) : "f"(v));
    return o;
}
__device__ __forceinline__ uint32_t smem_u32(const void* p) {
    uint32_t a;
    asm("{ .reg .u64 t; cvta.to.shared.u64 t, %1; cvt.u32.u64 %0, t; }"
        : "=r"(a) : "l"(p));
    return a;
}
__device__ __forceinline__ void cp_async16(uint32_t dst, const float* src) {
    asm volatile("cp.async.cg.shared.global [%0], [%1], 16;"
                 :: "r"(dst), "l"(src));
}
__device__ __forceinline__ void cp_commit() {
    asm volatile("cp.async.commit_group;" ::: "memory");
}
template <int N>
__device__ __forceinline__ void cp_wait() {
    asm volatile("cp.async.wait_group %0;" :: "n"(N) : "memory");
}

__device__ __forceinline__ void mma_tf32(float* d, const uint32_t* a, const uint32_t* b) {
    asm volatile(
        "mma.sync.aligned.m16n8k8.row.col.f32.tf32.tf32.f32 "
        "{%0,%1,%2,%3}, {%4,%5,%6,%7}, {%8,%9}, {%0,%1,%2,%3};"
        : "+f"(d[0]), "+f"(d[1]), "+f"(d[2]), "+f"(d[3])
        : "r"(a[0]), "r"(a[1]), "r"(a[2]), "r"(a[3]),
          "r"(b[0]), "r"(b[1]));
}

// ---------------------------------------------------------------------------
// mma.sync tf32 GEMM with cp.async 3-stage pipeline.
// C[M,N] = act([A1|A2] @ Bt^T + bias (+ ct@Wtail))
// CTA tile 256x128, BK=32, 512 threads (16 warps, 4x4), warp tile 64x32.
// A row-major fp32 (HW-truncated to tf32); Bt row-major [N,K] (rna-rounded).
// ---------------------------------------------------------------------------
#define BM 256
#define BN 128
#define BK 32
#define LDA 36
#define NS 3
#define ASZ (BM * LDA)            // floats per A stage
#define BSZ (BN * LDA)
#define TILESZ (ASZ + BSZ)        // 13824 floats
#define SMEM_SZ (NS * TILESZ * 4) // 165888 B

__global__ __launch_bounds__(512, 1) void gemm_mma(
    const float* __restrict__ A1, const float* __restrict__ A2,
    const float* __restrict__ Bt, const float* __restrict__ bias,
    float* __restrict__ C, int N, int K1, int K2, int relu_flag,
    const float* __restrict__ ct, const float* __restrict__ Wtail, int ldtail)
{
    extern __shared__ float sm[];
    const uint32_t smb = smem_u32(sm);

    const int tid  = threadIdx.x;
    const int lane = tid & 31;
    const int wid  = tid >> 5;
    const int wm   = wid >> 2;        // 0..3
    const int wn   = wid & 3;         // 0..3
    const int brow = blockIdx.y * BM;
    const int bcol = blockIdx.x * BN;
    const int K    = K1 + K2;
    const int iters = K / BK;

    // ---- tile loader: 384 rows x 32 floats, 6 x 16B chunks per thread -----
    auto load_tile = [&](int stage, int kt) {
        const uint32_t sbase = smb + (uint32_t)(stage * TILESZ) * 4u;
#pragma unroll
        for (int j = 0; j < 6; j++) {
            const int c = tid + 512 * j;
            const int row = c >> 3;
            const int col4 = (c & 7) * 4;
            const uint32_t dst = sbase + (uint32_t)(row * LDA + col4) * 4u;
            const float* src;
            if (row < BM) {
                src = (kt < K1)
                    ? A1 + (size_t)(brow + row) * K1 + kt + col4
                    : A2 + (size_t)(brow + row) * K2 + (kt - K1) + col4;
            } else {
                src = Bt + (size_t)(bcol + row - BM) * K + kt + col4;
            }
            cp_async16(dst, src);
        }
    };

    float acc[4][4][4];
#pragma unroll
    for (int i = 0; i < 4; i++)
#pragma unroll
        for (int j = 0; j < 4; j++)
#pragma unroll
            for (int q = 0; q < 4; q++) acc[i][j][q] = 0.f;

    // prologue: tiles 0..NS-2 in flight
#pragma unroll
    for (int s = 0; s < NS - 1; s++) {
        load_tile(s, s * BK);
        cp_commit();
    }

    for (int i = 0; i < iters; i++) {
        if (i + NS - 1 < iters) load_tile((i + NS - 1) % NS, (i + NS - 1) * BK);
        cp_commit();
        cp_wait<NS - 1>();
        __syncthreads();

        const float* As = sm + (i % NS) * TILESZ;
        const float* Bs = As + ASZ;
        const float* ab = As + (wm * 64 + (lane >> 2)) * LDA + (lane & 3);
        const float* bb = Bs + (wn * 32 + (lane >> 2)) * LDA + (lane & 3);

#pragma unroll
        for (int ks = 0; ks < 4; ks++) {
            uint32_t af[4][4];
#pragma unroll
            for (int mt = 0; mt < 4; mt++) {
                const float* p = ab + mt * 16 * LDA + ks * 8;
                af[mt][0] = __float_as_uint(p[0]);
                af[mt][1] = __float_as_uint(p[8 * LDA]);
                af[mt][2] = __float_as_uint(p[4]);
                af[mt][3] = __float_as_uint(p[8 * LDA + 4]);
            }
            uint32_t bf[4][2];
#pragma unroll
            for (int nt = 0; nt < 4; nt++) {
                const float* p = bb + nt * 8 * LDA + ks * 8;
                bf[nt][0] = __float_as_uint(p[0]);
                bf[nt][1] = __float_as_uint(p[4]);
            }
#pragma unroll
            for (int mt = 0; mt < 4; mt++)
#pragma unroll
                for (int nt = 0; nt < 4; nt++)
                    mma_tf32(acc[mt][nt], af[mt], bf[nt]);
        }
        __syncthreads();
    }

    // Epilogue
#pragma unroll
    for (int mt = 0; mt < 4; mt++) {
        const int gr0 = brow + wm * 64 + mt * 16 + (lane >> 2);
#pragma unroll
        for (int h = 0; h < 2; h++) {
            const int row = gr0 + 8 * h;
            float ctm[5];
            if (Wtail) {
#pragma unroll
                for (int c = 0; c < 5; c++) ctm[c] = ct[(size_t)row * 5 + c];
            }
#pragma unroll
            for (int nt = 0; nt < 4; nt++) {
                const int gc = bcol + wn * 32 + nt * 8 + (lane & 3) * 2;
                float v0 = acc[mt][nt][2 * h]     + bias[gc];
                float v1 = acc[mt][nt][2 * h + 1] + bias[gc + 1];
                if (Wtail) {
#pragma unroll
                    for (int c = 0; c < 5; c++) {
                        v0 = fmaf(ctm[c], Wtail[c * ldtail + gc],     v0);
                        v1 = fmaf(ctm[c], Wtail[c * ldtail + gc + 1], v1);
                    }
                }
                if (relu_flag) { v0 = fmaxf(v0, 0.f); v1 = fmaxf(v1, 0.f); }
                float2 o; o.x = v0; o.y = v1;
                *reinterpret_cast<float2*>(C + (size_t)row * N + gc) = o;
            }
        }
    }
}

// ---------------------------------------------------------------------------
// Weight transpose with tf32 rounding: W[K,N] -> Wt[N,K]
// ---------------------------------------------------------------------------
__global__ void transpose_kernel(const float* __restrict__ W, float* __restrict__ Wt,
                                 int K, int N)
{
    __shared__ float tile[32][33];
    const int n0 = blockIdx.x * 32;
    const int k0 = blockIdx.y * 32;
    const int tx = threadIdx.x, ty = threadIdx.y;
#pragma unroll
    for (int i = ty; i < 32; i += 8)
        tile[i][tx] = W[(size_t)(k0 + i) * N + n0 + tx];
    __syncthreads();
#pragma unroll
    for (int i = ty; i < 32; i += 8)
        Wt[(size_t)(n0 + i) * K + k0 + tx] = __uint_as_float(tf32r(tile[tx][i]));
}

// ---------------------------------------------------------------------------
// ctx: chunked scan.
// ---------------------------------------------------------------------------
#define NCH 32
#define CH 64

__global__ void ctx_partial(const float* __restrict__ x) {
    const int b = blockIdx.x, ch = blockIdx.y;
    const int d = threadIdx.x;
    const float* xp = x + ((size_t)b * kS + (size_t)ch * CH) * kD + d;
    float s0 = 0, s1 = 0, s2 = 0, s3 = 0;
    for (int t = 0; t < CH; t++) {
        const float* row = xp + (size_t)t * kD;
        s0 += row[0]; s1 += row[256]; s2 += row[512]; s3 += row[768];
    }
    float* pp = g_part + ((size_t)b * NCH + ch) * kD + d;
    pp[0] = s0; pp[256] = s1; pp[512] = s2; pp[768] = s3;
}

__global__ void ctx_emit(const float* __restrict__ x) {
    const int b = blockIdx.x, ch = blockIdx.y;
    const int d = threadIdx.x;
    float pre[4] = {0, 0, 0, 0}, tot[4] = {0, 0, 0, 0};
    for (int c = 0; c < NCH; c++) {
        const float* pp = g_part + ((size_t)b * NCH + c) * kD + d;
#pragma unroll
        for (int dd = 0; dd < 4; dd++) {
            float p = pp[dd * 256];
            if (c < ch) pre[dd] += p;
            tot[dd] += p;
        }
    }
    const float inv_edge = 1.f / (float)(kS - 1);
    const float* xp = x + ((size_t)b * kS + (size_t)ch * CH) * kD + d;
    float* cp = g_ctx + ((size_t)b * kS + (size_t)ch * CH) * kD + d;
    for (int t = 0; t < CH; t++) {
        const int tg = ch * CH + t;
        const bool edge = (tg == 0) || (tg == kS - 1);
        const float ip = edge ? inv_edge : (0.5f / fmaxf((float)tg, 1.f));
        const float is = edge ? inv_edge : (0.5f / fmaxf((float)(kS - 1 - tg), 1.f));
#pragma unroll
        for (int dd = 0; dd < 4; dd++) {
            float xv = xp[(size_t)t * kD + dd * 256];
            float prefix = pre[dd];
            pre[dd] += xv;
            float suffix = tot[dd] - pre[dd];
            cp[(size_t)t * kD + dd * 256] = prefix * ip + suffix * is;
        }
    }
}

// ---------------------------------------------------------------------------
// content_types: per-row dot-5 over K=512, softmax(5), relevance, ctbw
// ---------------------------------------------------------------------------
__global__ __launch_bounds__(128) void content_kernel(
    const float* __restrict__ Wcc2, const float* __restrict__ bcc2,
    float* __restrict__ out_ct, float* __restrict__ out_rel)
{
    const int m = blockIdx.x;
    const float* row = g_h1 + (size_t)m * 512;
    float acc[5] = {0, 0, 0, 0, 0};
    for (int k = threadIdx.x; k < 512; k += 128) {
        float v = row[k];
#pragma unroll
        for (int c = 0; c < 5; c++) acc[c] = fmaf(v, Wcc2[k * 5 + c], acc[c]);
    }
#pragma unroll
    for (int c = 0; c < 5; c++)
#pragma unroll
        for (int o = 16; o; o >>= 1) acc[c] += __shfl_xor_sync(0xffffffffu, acc[c], o);

    __shared__ float s[4][5];
    const int w = threadIdx.x >> 5;
    if ((threadIdx.x & 31) == 0) {
#pragma unroll
        for (int c = 0; c < 5; c++) s[w][c] = acc[c];
    }
    __syncthreads();
    if (threadIdx.x == 0) {
        float t[5];
#pragma unroll
        for (int c = 0; c < 5; c++) t[c] = s[0][c] + s[1][c] + s[2][c] + s[3][c] + bcc2[c];
        float mx = t[0];
#pragma unroll
        for (int c = 1; c < 5; c++) mx = fmaxf(mx, t[c]);
        float e[5], sum = 0.f;
#pragma unroll
        for (int c = 0; c < 5; c++) { e[c] = expf(t[c] - mx); sum += e[c]; }
        const float inv = 1.f / sum;
        const float bw[5] = {0.1f, 1.0f, 0.8f, 0.3f, 0.5f};
        float ws = 0.f;
#pragma unroll
        for (int c = 0; c < 5; c++) {
            float p = e[c] * inv;
            out_ct[(size_t)m * 5 + c] = p;
            ws = fmaf(p, bw[c], ws);
        }
        out_rel[m] = 1.f - e[3] * inv;
        g_ctbw[m] = ws;
    }
}

__device__ __forceinline__ float block_reduce_sum(float v, float* sbuf) {
#pragma unroll
    for (int o = 16; o; o >>= 1) v += __shfl_xor_sync(0xffffffffu, v, o);
    const int w = threadIdx.x >> 5;
    __syncthreads();
    if ((threadIdx.x & 31) == 0) sbuf[w] = v;
    __syncthreads();
    if (threadIdx.x == 0) {
        float r = 0.f;
        for (int i = 0; i < (int)(blockDim.x >> 5); i++) r += sbuf[i];
        sbuf[0] = r;
    }
    __syncthreads();
    return sbuf[0];
}

__global__ __launch_bounds__(256) void ln_head_kernel(
    const float* __restrict__ gln, const float* __restrict__ beln,
    const float* __restrict__ W2, const float* __restrict__ b2,
    const float* __restrict__ ct, float* __restrict__ out_enh)
{
    __shared__ float sbuf[8];
    const int m = blockIdx.x;
    const int t = threadIdx.x;
    const float4 v = reinterpret_cast<const float4*>(g_h + (size_t)m * kD)[t];

    float s = v.x + v.y + v.z + v.w;
    float q = v.x * v.x + v.y * v.y + v.z * v.z + v.w * v.w;
    const float sum = block_reduce_sum(s, sbuf);
    const float sq  = block_reduce_sum(q, sbuf);
    const float mu  = sum * (1.f / (float)kD);
    const float var = sq * (1.f / (float)kD) - mu * mu;
    const float rstd = rsqrtf(var + 1e-5f);

    const float4 gv  = reinterpret_cast<const float4*>(gln)[t];
    const float4 bev = reinterpret_cast<const float4*>(beln)[t];
    const float4 wv  = reinterpret_cast<const float4*>(W2)[t];

    const float kInvSqrt2 = 0.70710678118654752f;
    float dot = 0.f;
    float y;
    y = (v.x - mu) * rstd * gv.x + bev.x; y = 0.5f * y * (1.f + erff(y * kInvSqrt2)); dot = fmaf(y, wv.x, dot);
    y = (v.y - mu) * rstd * gv.y + bev.y; y = 0.5f * y * (1.f + erff(y * kInvSqrt2)); dot = fmaf(y, wv.y, dot);
    y = (v.z - mu) * rstd * gv.z + bev.z; y = 0.5f * y * (1.f + erff(y * kInvSqrt2)); dot = fmaf(y, wv.z, dot);
    y = (v.w - mu) * rstd * gv.w + bev.w; y = 0.5f * y * (1.f + erff(y * kInvSqrt2)); dot = fmaf(y, wv.w, dot);

    dot = block_reduce_sum(dot, sbuf);
    if (t == 0) {
        float cont = 1.f / (1.f + expf(-(dot + b2[0])));
        out_enh[m] = fmaxf(cont, ct[(size_t)m * 5 + 2]);
    }
}

__global__ __launch_bounds__(256) void bias_out_kernel(
    const float* __restrict__ W, const float* __restrict__ b,
    float* __restrict__ out_wb)
{
    const int m = blockIdx.x * 8 + (threadIdx.x >> 5);
    const int l = threadIdx.x & 31;
    const float* row = g_hb + (size_t)m * 256;
    float acc = 0.f;
#pragma unroll
    for (int i = 0; i < 8; i++) acc = fmaf(row[l + 32 * i], W[l + 32 * i], acc);
#pragma unroll
    for (int o = 16; o; o >>= 1) acc += __shfl_xor_sync(0xffffffffu, acc, o);
    if (l == 0) {
        float bs = 1.f / (1.f + expf(-(acc + b[0])));
        out_wb[m] = bs * g_ctbw[m];
    }
}

__global__ __launch_bounds__(256) void cred_out_kernel(
    const float* __restrict__ W, const float* __restrict__ b,
    float* __restrict__ out_cred)
{
    const int m = blockIdx.x * 8 + (threadIdx.x >> 5);
    const int l = threadIdx.x & 31;
    const float* row = g_hc + (size_t)m * 512;
    float acc = 0.f;
#pragma unroll
    for (int i = 0; i < 16; i++) acc = fmaf(row[l + 32 * i], W[l + 32 * i], acc);
#pragma unroll
    for (int o = 16; o; o >>= 1) acc += __shfl_xor_sync(0xffffffffu, acc, o);
    if (l == 0) out_cred[m] = 1.f / (1.f + expf(-(acc + b[0])));
}

// ---------------------------------------------------------------------------
// Launch
// ---------------------------------------------------------------------------
extern "C" void kernel_launch(void* const* d_in, const int* in_sizes, int n_in,
                              void* d_out, int out_size)
{
    (void)in_sizes; (void)n_in; (void)out_size;

    const float* x    = (const float*)d_in[0];
    const float* Wcc1 = (const float*)d_in[1];
    const float* bcc1 = (const float*)d_in[2];
    const float* Wcc2 = (const float*)d_in[3];
    const float* bcc2 = (const float*)d_in[4];
    const float* Wcd1 = (const float*)d_in[5];
    const float* bcd1 = (const float*)d_in[6];
    const float* gln  = (const float*)d_in[7];
    const float* beln = (const float*)d_in[8];
    const float* Wcd2 = (const float*)d_in[9];
    const float* bcd2 = (const float*)d_in[10];
    const float* Wbe1 = (const float*)d_in[11];
    const float* bbe1 = (const float*)d_in[12];
    const float* Wbe2 = (const float*)d_in[13];
    const float* bbe2 = (const float*)d_in[14];
    const float* Wcr1 = (const float*)d_in[15];
    const float* bcr1 = (const float*)d_in[16];
    const float* Wcr2 = (const float*)d_in[17];
    const float* bcr2 = (const float*)d_in[18];

    float* out_x    = (float*)d_out;
    float* out_ct   = out_x + (size_t)kM * kD;
    float* out_enh  = out_ct + (size_t)kM * kC;
    float* out_wb   = out_enh + kM;
    float* out_rel  = out_wb + kM;
    float* out_cred = out_rel + kM;

    float *ctxp, *h1p, *hp, *hbp, *hcp, *wtp;
    cudaGetSymbolAddress((void**)&ctxp, g_ctx);
    cudaGetSymbolAddress((void**)&h1p,  g_h1);
    cudaGetSymbolAddress((void**)&hp,   g_h);
    cudaGetSymbolAddress((void**)&hbp,  g_hb);
    cudaGetSymbolAddress((void**)&hcp,  g_hc);
    cudaGetSymbolAddress((void**)&wtp,  g_wt);

    cudaFuncSetAttribute(gemm_mma, cudaFuncAttributeMaxDynamicSharedMemorySize, SMEM_SZ);

    // x passthrough
    cudaMemcpyAsync(out_x, x, (size_t)kM * kD * sizeof(float),
                    cudaMemcpyDeviceToDevice, 0);

    // weight transposes (rna tf32 rounding)
    transpose_kernel<<<dim3(512/32, 1024/32), dim3(32, 8)>>>(Wcc1, wtp + WT_CC1, 1024, 512);
    transpose_kernel<<<dim3(1024/32, 2048/32), dim3(32, 8)>>>(Wcd1, wtp + WT_CD1, 2048, 1024);
    transpose_kernel<<<dim3(256/32, 1024/32), dim3(32, 8)>>>(Wbe1, wtp + WT_BE1, 1024, 256);
    transpose_kernel<<<dim3(512/32, 1024/32), dim3(32, 8)>>>(Wcr1, wtp + WT_CR1, 1024, 512);

    // ctx
    ctx_partial<<<dim3(kB, NCH), 256>>>(x);
    ctx_emit<<<dim3(kB, NCH), 256>>>(x);

    // G1: h1 = relu(x @ Wcc1 + bcc1)  [16384,1024]x[1024,512]
    gemm_mma<<<dim3(512/BN, kM/BM), 512, SMEM_SZ>>>(
        x, nullptr, wtp + WT_CC1, bcc1, h1p, 512, 1024, 0, 1, nullptr, nullptr, 0);

    content_kernel<<<kM, 128>>>(Wcc2, bcc2, out_ct, out_rel);

    // G3: h = [x|ctx] @ Wcd1 + bcd1   [16384,2048]x[2048,1024]
    gemm_mma<<<dim3(1024/BN, kM/BM), 512, SMEM_SZ>>>(
        x, ctxp, wtp + WT_CD1, bcd1, hp, 1024, 1024, 1024, 0, nullptr, nullptr, 0);

    ln_head_kernel<<<kM, 256>>>(gln, beln, Wcd2, bcd2, out_ct, out_enh);

    // G4: hb = relu(x @ Wbe1 + bbe1)  [16384,1024]x[1024,256]
    gemm_mma<<<dim3(256/BN, kM/BM), 512, SMEM_SZ>>>(
        x, nullptr, wtp + WT_BE1, bbe1, hbp, 256, 1024, 0, 1, nullptr, nullptr, 0);

    bias_out_kernel<<<kM/8, 256>>>(Wbe2, bbe2, out_wb);

    // G6: hc = relu([x|ct] @ Wcr1 + bcr1) — 5-col ct tail folded into epilogue
    gemm_mma<<<dim3(512/BN, kM/BM), 512, SMEM_SZ>>>(
        x, nullptr, wtp + WT_CR1, bcr1, hcp, 512, 1024, 0, 1,
        out_ct, Wcr1 + (size_t)1024 * 512, 512);

    cred_out_kernel<<<kM/8, 256>>>(Wcr2, bcr2, out_cred);
}

// round 5
// speedup vs baseline: 5.9020x; 1.4597x over previous
#include <cuda_runtime.h>
#include <cuda_fp16.h>
#include <math.h>
#include <stdint.h>

// Problem constants
#define kB 8
#define kS 2048
#define kD 1024
#define kC 5
#define kM (kB * kS)  // 16384

// ---------------------------------------------------------------------------
// Scratch (device globals)
// ---------------------------------------------------------------------------
__device__ __half g_xh  [(size_t)kM * kD];     // 32 MB  fp16 x
__device__ __half g_ctxh[(size_t)kM * kD];     // 32 MB  fp16 ctx
__device__ float  g_big [(size_t)kM * 1280];   // 84 MB  merged G1|G4|G6 out
__device__ float  g_h   [(size_t)kM * kD];     // 64 MB  G3 out
__device__ float  g_ctbw[kM];
__device__ float  g_part[(size_t)kB * 32 * kD];
__device__ __half g_wth[(size_t)1280*1024 + (size_t)1024*2048]; // transposed half weights
__device__ float  g_biasA[1280];

#define WTH_MERGED 0
#define WTH_CD1 ((size_t)1280 * 1024)

// ---------------------------------------------------------------------------
// helpers
// ---------------------------------------------------------------------------
__device__ __forceinline__ uint32_t smem_u32(const void* p) {
    uint32_t a;
    asm("{ .reg .u64 t; cvta.to.shared.u64 t, %1; cvt.u32.u64 %0, t; }"
        : "=r"(a) : "l"(p));
    return a;
}
__device__ __forceinline__ void cp_async16(uint32_t dst, const void* src) {
    asm volatile("cp.async.cg.shared.global [%0], [%1], 16;"
                 :: "r"(dst), "l"(src));
}
__device__ __forceinline__ void cp_commit() {
    asm volatile("cp.async.commit_group;" ::: "memory");
}
template <int N>
__device__ __forceinline__ void cp_wait() {
    asm volatile("cp.async.wait_group %0;" :: "n"(N) : "memory");
}
__device__ __forceinline__ void ldsm_x4(uint32_t* r, uint32_t addr) {
    asm volatile("ldmatrix.sync.aligned.m8n8.x4.shared.b16 {%0,%1,%2,%3}, [%4];"
                 : "=r"(r[0]), "=r"(r[1]), "=r"(r[2]), "=r"(r[3]) : "r"(addr));
}
__device__ __forceinline__ void mma_f16(float* d, const uint32_t* a, const uint32_t* b) {
    asm volatile(
        "mma.sync.aligned.m16n8k16.row.col.f32.f16.f16.f32 "
        "{%0,%1,%2,%3}, {%4,%5,%6,%7}, {%8,%9}, {%0,%1,%2,%3};"
        : "+f"(d[0]), "+f"(d[1]), "+f"(d[2]), "+f"(d[3])
        : "r"(a[0]), "r"(a[1]), "r"(a[2]), "r"(a[3]),
          "r"(b[0]), "r"(b[1]));
}

// ---------------------------------------------------------------------------
// fp16 mma GEMM with cp.async 3-stage pipeline + ldmatrix.
// C[M,N] = act([A1|A2] @ Bt^T + bias), relu applied for cols < relu_upto.
// CTA tile 256x128, BK=32, 512 threads (16 warps 4x4), warp tile 64x32.
// A1/A2 half row-major; Bt half row-major [N,K].
// ---------------------------------------------------------------------------
#define BM 256
#define BN 128
#define BK 32
#define LDAH 40                        // halves per smem row (80 B)
#define NS 3
#define ASZB (BM * LDAH * 2)           // A stage bytes: 20480
#define TILEB ((BM + BN) * LDAH * 2)   // 30720 B per stage
#define SMEM_SZ (NS * TILEB)           // 92160 B

__global__ __launch_bounds__(512, 1) void gemm_h(
    const __half* __restrict__ A1, const __half* __restrict__ A2,
    const __half* __restrict__ Bt, const float* __restrict__ bias,
    float* __restrict__ C, int N, int K1, int K2, int relu_upto)
{
    extern __shared__ char sm[];
    const uint32_t smb = smem_u32(sm);

    const int tid  = threadIdx.x;
    const int lane = tid & 31;
    const int wid  = tid >> 5;
    const int wm   = wid >> 2;
    const int wn   = wid & 3;
    const int brow = blockIdx.y * BM;
    const int bcol = blockIdx.x * BN;
    const int K    = K1 + K2;
    const int iters = K / BK;

    // ldmatrix per-lane address components
    const int a_row = wm * 64 + ((lane >> 3) & 1) * 8 + (lane & 7);
    const int a_k   = (lane >> 4) * 8;
    const int b_row = wn * 32 + (lane >> 4) * 8 + (lane & 7);
    const int b_k   = ((lane >> 3) & 1) * 8;

    // loader: (BM+BN)=384 rows x 32 halves, 4 x 16B chunks/row, 3/thread
    auto load_tile = [&](int stage, int kt) {
        const uint32_t sbase = smb + (uint32_t)(stage * TILEB);
#pragma unroll
        for (int j = 0; j < 3; j++) {
            const int c = tid + 512 * j;
            const int row = c >> 2;
            const int col = (c & 3) * 8;   // halves
            const uint32_t dst = sbase + (uint32_t)(row * 80 + col * 2);
            const __half* src;
            if (row < BM) {
                src = (kt < K1)
                    ? A1 + (size_t)(brow + row) * K1 + kt + col
                    : A2 + (size_t)(brow + row) * K2 + (kt - K1) + col;
            } else {
                src = Bt + (size_t)(bcol + row - BM) * K + kt + col;
            }
            cp_async16(dst, src);
        }
    };

    float acc[4][4][4];
#pragma unroll
    for (int i = 0; i < 4; i++)
#pragma unroll
        for (int j = 0; j < 4; j++)
#pragma unroll
            for (int q = 0; q < 4; q++) acc[i][j][q] = 0.f;

#pragma unroll
    for (int s = 0; s < NS - 1; s++) {
        load_tile(s, s * BK);
        cp_commit();
    }

    for (int i = 0; i < iters; i++) {
        if (i + NS - 1 < iters) load_tile((i + NS - 1) % NS, (i + NS - 1) * BK);
        cp_commit();
        cp_wait<NS - 1>();
        __syncthreads();

        const uint32_t sa = smb + (uint32_t)((i % NS) * TILEB);
        const uint32_t sbB = sa + ASZB;

#pragma unroll
        for (int ks = 0; ks < 2; ks++) {
            uint32_t af[4][4];
#pragma unroll
            for (int mt = 0; mt < 4; mt++)
                ldsm_x4(af[mt], sa + (uint32_t)((a_row + mt * 16) * 80 + (ks * 16 + a_k) * 2));
            uint32_t bf[2][4];
#pragma unroll
            for (int np = 0; np < 2; np++)
                ldsm_x4(bf[np], sbB + (uint32_t)((b_row + np * 16) * 80 + (ks * 16 + b_k) * 2));
#pragma unroll
            for (int mt = 0; mt < 4; mt++)
#pragma unroll
                for (int nt = 0; nt < 4; nt++)
                    mma_f16(acc[mt][nt], af[mt], &bf[nt >> 1][(nt & 1) * 2]);
        }
        __syncthreads();
    }

    // Epilogue
#pragma unroll
    for (int mt = 0; mt < 4; mt++) {
        const int gr0 = brow + wm * 64 + mt * 16 + (lane >> 2);
#pragma unroll
        for (int h = 0; h < 2; h++) {
            const int row = gr0 + 8 * h;
#pragma unroll
            for (int nt = 0; nt < 4; nt++) {
                const int gc = bcol + wn * 32 + nt * 8 + (lane & 3) * 2;
                float v0 = acc[mt][nt][2 * h]     + bias[gc];
                float v1 = acc[mt][nt][2 * h + 1] + bias[gc + 1];
                if (gc < relu_upto) { v0 = fmaxf(v0, 0.f); v1 = fmaxf(v1, 0.f); }
                float2 o; o.x = v0; o.y = v1;
                *reinterpret_cast<float2*>(C + (size_t)row * N + gc) = o;
            }
        }
    }
}

// ---------------------------------------------------------------------------
// x -> fp16
// ---------------------------------------------------------------------------
__global__ void convert_x(const float4* __restrict__ x, __half* __restrict__ xh) {
    const size_t i = (size_t)blockIdx.x * blockDim.x + threadIdx.x;
    const float4 v = x[i];
    __half2* o = reinterpret_cast<__half2*>(xh + i * 4);
    o[0] = __floats2half2_rn(v.x, v.y);
    o[1] = __floats2half2_rn(v.z, v.w);
}

// ---------------------------------------------------------------------------
// Weight transpose to fp16: W[K,N] -> Wt[N,K]
// ---------------------------------------------------------------------------
__global__ void transpose_h(const float* __restrict__ W, __half* __restrict__ Wt,
                            int K, int N)
{
    __shared__ float tile[32][33];
    const int n0 = blockIdx.x * 32;
    const int k0 = blockIdx.y * 32;
    const int tx = threadIdx.x, ty = threadIdx.y;
#pragma unroll
    for (int i = ty; i < 32; i += 8)
        tile[i][tx] = W[(size_t)(k0 + i) * N + n0 + tx];
    __syncthreads();
#pragma unroll
    for (int i = ty; i < 32; i += 8)
        Wt[(size_t)(n0 + i) * K + k0 + tx] = __float2half(tile[tx][i]);
}

// ---------------------------------------------------------------------------
// ctx: chunked scan -> fp16 ctx
// ---------------------------------------------------------------------------
#define NCH 32
#define CH 64

__global__ void ctx_partial(const float* __restrict__ x) {
    const int b = blockIdx.x, ch = blockIdx.y;
    const int d = threadIdx.x;
    const float* xp = x + ((size_t)b * kS + (size_t)ch * CH) * kD + d;
    float s0 = 0, s1 = 0, s2 = 0, s3 = 0;
    for (int t = 0; t < CH; t++) {
        const float* row = xp + (size_t)t * kD;
        s0 += row[0]; s1 += row[256]; s2 += row[512]; s3 += row[768];
    }
    float* pp = g_part + ((size_t)b * NCH + ch) * kD + d;
    pp[0] = s0; pp[256] = s1; pp[512] = s2; pp[768] = s3;
}

__global__ void ctx_emit(const float* __restrict__ x) {
    const int b = blockIdx.x, ch = blockIdx.y;
    const int d = threadIdx.x;
    float pre[4] = {0, 0, 0, 0}, tot[4] = {0, 0, 0, 0};
    for (int c = 0; c < NCH; c++) {
        const float* pp = g_part + ((size_t)b * NCH + c) * kD + d;
#pragma unroll
        for (int dd = 0; dd < 4; dd++) {
            float p = pp[dd * 256];
            if (c < ch) pre[dd] += p;
            tot[dd] += p;
        }
    }
    const float inv_edge = 1.f / (float)(kS - 1);
    const float* xp = x + ((size_t)b * kS + (size_t)ch * CH) * kD + d;
    __half* cp = g_ctxh + ((size_t)b * kS + (size_t)ch * CH) * kD + d;
    for (int t = 0; t < CH; t++) {
        const int tg = ch * CH + t;
        const bool edge = (tg == 0) || (tg == kS - 1);
        const float ip = edge ? inv_edge : (0.5f / fmaxf((float)tg, 1.f));
        const float is = edge ? inv_edge : (0.5f / fmaxf((float)(kS - 1 - tg), 1.f));
#pragma unroll
        for (int dd = 0; dd < 4; dd++) {
            float xv = xp[(size_t)t * kD + dd * 256];
            float prefix = pre[dd];
            pre[dd] += xv;
            float suffix = tot[dd] - pre[dd];
            cp[(size_t)t * kD + dd * 256] = __float2half(prefix * ip + suffix * is);
        }
    }
}

// ---------------------------------------------------------------------------
// content_types: per-row dot-5 over K=512 (g_big cols 0..511), softmax(5)
// ---------------------------------------------------------------------------
__global__ __launch_bounds__(128) void content_kernel(
    const float* __restrict__ Wcc2, const float* __restrict__ bcc2,
    float* __restrict__ out_ct, float* __restrict__ out_rel)
{
    const int m = blockIdx.x;
    const float* row = g_big + (size_t)m * 1280;
    float acc[5] = {0, 0, 0, 0, 0};
    for (int k = threadIdx.x; k < 512; k += 128) {
        float v = row[k];
#pragma unroll
        for (int c = 0; c < 5; c++) acc[c] = fmaf(v, Wcc2[k * 5 + c], acc[c]);
    }
#pragma unroll
    for (int c = 0; c < 5; c++)
#pragma unroll
        for (int o = 16; o; o >>= 1) acc[c] += __shfl_xor_sync(0xffffffffu, acc[c], o);

    __shared__ float s[4][5];
    const int w = threadIdx.x >> 5;
    if ((threadIdx.x & 31) == 0) {
#pragma unroll
        for (int c = 0; c < 5; c++) s[w][c] = acc[c];
    }
    __syncthreads();
    if (threadIdx.x == 0) {
        float t[5];
#pragma unroll
        for (int c = 0; c < 5; c++) t[c] = s[0][c] + s[1][c] + s[2][c] + s[3][c] + bcc2[c];
        float mx = t[0];
#pragma unroll
        for (int c = 1; c < 5; c++) mx = fmaxf(mx, t[c]);
        float e[5], sum = 0.f;
#pragma unroll
        for (int c = 0; c < 5; c++) { e[c] = expf(t[c] - mx); sum += e[c]; }
        const float inv = 1.f / sum;
        const float bw[5] = {0.1f, 1.0f, 0.8f, 0.3f, 0.5f};
        float ws = 0.f;
#pragma unroll
        for (int c = 0; c < 5; c++) {
            float p = e[c] * inv;
            out_ct[(size_t)m * 5 + c] = p;
            ws = fmaf(p, bw[c], ws);
        }
        out_rel[m] = 1.f - e[3] * inv;
        g_ctbw[m] = ws;
    }
}

__device__ __forceinline__ float block_reduce_sum(float v, float* sbuf) {
#pragma unroll
    for (int o = 16; o; o >>= 1) v += __shfl_xor_sync(0xffffffffu, v, o);
    const int w = threadIdx.x >> 5;
    __syncthreads();
    if ((threadIdx.x & 31) == 0) sbuf[w] = v;
    __syncthreads();
    if (threadIdx.x == 0) {
        float r = 0.f;
        for (int i = 0; i < (int)(blockDim.x >> 5); i++) r += sbuf[i];
        sbuf[0] = r;
    }
    __syncthreads();
    return sbuf[0];
}

// ---------------------------------------------------------------------------
// LN + exact GELU + dot(W_cd2) + sigmoid -> enhanced
// ---------------------------------------------------------------------------
__global__ __launch_bounds__(256) void ln_head_kernel(
    const float* __restrict__ gln, const float* __restrict__ beln,
    const float* __restrict__ W2, const float* __restrict__ b2,
    const float* __restrict__ ct, float* __restrict__ out_enh)
{
    __shared__ float sbuf[8];
    const int m = blockIdx.x;
    const int t = threadIdx.x;
    const float4 v = reinterpret_cast<const float4*>(g_h + (size_t)m * kD)[t];

    float s = v.x + v.y + v.z + v.w;
    float q = v.x * v.x + v.y * v.y + v.z * v.z + v.w * v.w;
    const float sum = block_reduce_sum(s, sbuf);
    const float sq  = block_reduce_sum(q, sbuf);
    const float mu  = sum * (1.f / (float)kD);
    const float var = sq * (1.f / (float)kD) - mu * mu;
    const float rstd = rsqrtf(var + 1e-5f);

    const float4 gv  = reinterpret_cast<const float4*>(gln)[t];
    const float4 bev = reinterpret_cast<const float4*>(beln)[t];
    const float4 wv  = reinterpret_cast<const float4*>(W2)[t];

    const float kInvSqrt2 = 0.70710678118654752f;
    float dot = 0.f;
    float y;
    y = (v.x - mu) * rstd * gv.x + bev.x; y = 0.5f * y * (1.f + erff(y * kInvSqrt2)); dot = fmaf(y, wv.x, dot);
    y = (v.y - mu) * rstd * gv.y + bev.y; y = 0.5f * y * (1.f + erff(y * kInvSqrt2)); dot = fmaf(y, wv.y, dot);
    y = (v.z - mu) * rstd * gv.z + bev.z; y = 0.5f * y * (1.f + erff(y * kInvSqrt2)); dot = fmaf(y, wv.z, dot);
    y = (v.w - mu) * rstd * gv.w + bev.w; y = 0.5f * y * (1.f + erff(y * kInvSqrt2)); dot = fmaf(y, wv.w, dot);

    dot = block_reduce_sum(dot, sbuf);
    if (t == 0) {
        float cont = 1.f / (1.f + expf(-(dot + b2[0])));
        out_enh[m] = fmaxf(cont, ct[(size_t)m * 5 + 2]);
    }
}

// ---------------------------------------------------------------------------
// weighted_bias: warp-per-row dot over K=256 (g_big cols 512..767)
// ---------------------------------------------------------------------------
__global__ __launch_bounds__(256) void bias_out_kernel(
    const float* __restrict__ W, const float* __restrict__ b,
    float* __restrict__ out_wb)
{
    const int m = blockIdx.x * 8 + (threadIdx.x >> 5);
    const int l = threadIdx.x & 31;
    const float* row = g_big + (size_t)m * 1280 + 512;
    float acc = 0.f;
#pragma unroll
    for (int i = 0; i < 8; i++) acc = fmaf(row[l + 32 * i], W[l + 32 * i], acc);
#pragma unroll
    for (int o = 16; o; o >>= 1) acc += __shfl_xor_sync(0xffffffffu, acc, o);
    if (l == 0) {
        float bs = 1.f / (1.f + expf(-(acc + b[0])));
        out_wb[m] = bs * g_ctbw[m];
    }
}

// ---------------------------------------------------------------------------
// credibility: pre-act (g_big cols 768..1279) + ct@Wtail, relu, dot, sigmoid
// block 256 thr = 8 warps, each warp 8 rows; Wtail+Wcr2 cached in smem
// ---------------------------------------------------------------------------
__global__ __launch_bounds__(256) void cred_kernel(
    const float* __restrict__ Wtail,   // [5,512] rows 1024..1028 of W_cr1
    const float* __restrict__ Wcr2, const float* __restrict__ bcr2,
    const float* __restrict__ ct, float* __restrict__ out_cred)
{
    __shared__ float swt[5 * 512 + 512];
    for (int i = threadIdx.x; i < 5 * 512; i += 256) swt[i] = Wtail[i];
    for (int i = threadIdx.x; i < 512; i += 256) swt[5 * 512 + i] = Wcr2[i];
    __syncthreads();

    const int w = threadIdx.x >> 5;
    const int l = threadIdx.x & 31;
    const float b0 = bcr2[0];

#pragma unroll
    for (int r = 0; r < 8; r++) {
        const int m = blockIdx.x * 64 + w * 8 + r;
        const float* pre = g_big + (size_t)m * 1280 + 768;
        float ctm[5];
#pragma unroll
        for (int c = 0; c < 5; c++) ctm[c] = ct[(size_t)m * 5 + c];
        float acc = 0.f;
#pragma unroll
        for (int i = 0; i < 16; i++) {
            const int j = l + 32 * i;
            float v = pre[j];
#pragma unroll
            for (int c = 0; c < 5; c++) v = fmaf(ctm[c], swt[c * 512 + j], v);
            v = fmaxf(v, 0.f);
            acc = fmaf(v, swt[5 * 512 + j], acc);
        }
#pragma unroll
        for (int o = 16; o; o >>= 1) acc += __shfl_xor_sync(0xffffffffu, acc, o);
        if (l == 0) out_cred[m] = 1.f / (1.f + expf(-(acc + b0)));
    }
}

// ---------------------------------------------------------------------------
// Launch
// ---------------------------------------------------------------------------
extern "C" void kernel_launch(void* const* d_in, const int* in_sizes, int n_in,
                              void* d_out, int out_size)
{
    (void)in_sizes; (void)n_in; (void)out_size;

    const float* x    = (const float*)d_in[0];
    const float* Wcc1 = (const float*)d_in[1];
    const float* bcc1 = (const float*)d_in[2];
    const float* Wcc2 = (const float*)d_in[3];
    const float* bcc2 = (const float*)d_in[4];
    const float* Wcd1 = (const float*)d_in[5];
    const float* bcd1 = (const float*)d_in[6];
    const float* gln  = (const float*)d_in[7];
    const float* beln = (const float*)d_in[8];
    const float* Wcd2 = (const float*)d_in[9];
    const float* bcd2 = (const float*)d_in[10];
    const float* Wbe1 = (const float*)d_in[11];
    const float* bbe1 = (const float*)d_in[12];
    const float* Wbe2 = (const float*)d_in[13];
    const float* bbe2 = (const float*)d_in[14];
    const float* Wcr1 = (const float*)d_in[15];
    const float* bcr1 = (const float*)d_in[16];
    const float* Wcr2 = (const float*)d_in[17];
    const float* bcr2 = (const float*)d_in[18];

    float* out_x    = (float*)d_out;
    float* out_ct   = out_x + (size_t)kM * kD;
    float* out_enh  = out_ct + (size_t)kM * kC;
    float* out_wb   = out_enh + kM;
    float* out_rel  = out_wb + kM;
    float* out_cred = out_rel + kM;

    __half *xh, *ctxh, *wth;
    float *bigp, *hp, *biasA;
    cudaGetSymbolAddress((void**)&xh,    g_xh);
    cudaGetSymbolAddress((void**)&ctxh,  g_ctxh);
    cudaGetSymbolAddress((void**)&wth,   g_wth);
    cudaGetSymbolAddress((void**)&bigp,  g_big);
    cudaGetSymbolAddress((void**)&hp,    g_h);
    cudaGetSymbolAddress((void**)&biasA, g_biasA);

    cudaFuncSetAttribute(gemm_h, cudaFuncAttributeMaxDynamicSharedMemorySize, SMEM_SZ);

    // x passthrough + fp16 conversion
    cudaMemcpyAsync(out_x, x, (size_t)kM * kD * sizeof(float),
                    cudaMemcpyDeviceToDevice, 0);
    convert_x<<<(kM * kD / 4) / 256, 256>>>((const float4*)x, xh);

    // merged bias vector [bcc1 | bbe1 | bcr1]
    cudaMemcpyAsync(biasA,       bcc1, 512 * sizeof(float), cudaMemcpyDeviceToDevice, 0);
    cudaMemcpyAsync(biasA + 512, bbe1, 256 * sizeof(float), cudaMemcpyDeviceToDevice, 0);
    cudaMemcpyAsync(biasA + 768, bcr1, 512 * sizeof(float), cudaMemcpyDeviceToDevice, 0);

    // weight transposes -> half, merged layout [cc1 512 | be1 256 | cr1 512] K=1024
    transpose_h<<<dim3(512/32, 1024/32), dim3(32, 8)>>>(Wcc1, wth + WTH_MERGED,                 1024, 512);
    transpose_h<<<dim3(256/32, 1024/32), dim3(32, 8)>>>(Wbe1, wth + WTH_MERGED + (size_t)512*1024, 1024, 256);
    transpose_h<<<dim3(512/32, 1024/32), dim3(32, 8)>>>(Wcr1, wth + WTH_MERGED + (size_t)768*1024, 1024, 512);
    transpose_h<<<dim3(1024/32, 2048/32), dim3(32, 8)>>>(Wcd1, wth + WTH_CD1, 2048, 1024);

    // ctx (fp16 out)
    ctx_partial<<<dim3(kB, NCH), 256>>>(x);
    ctx_emit<<<dim3(kB, NCH), 256>>>(x);

    // merged GEMM: g_big = [relu(x@Wcc1+b) | relu(x@Wbe1+b) | x@Wcr1+b (pre-act)]
    gemm_h<<<dim3(1280/BN, kM/BM), 512, SMEM_SZ>>>(
        xh, nullptr, wth + WTH_MERGED, biasA, bigp, 1280, 1024, 0, 768);

    content_kernel<<<kM, 128>>>(Wcc2, bcc2, out_ct, out_rel);

    // G3: h = [x|ctx] @ Wcd1 + bcd1
    gemm_h<<<dim3(1024/BN, kM/BM), 512, SMEM_SZ>>>(
        xh, ctxh, wth + WTH_CD1, bcd1, hp, 1024, 1024, 1024, 0);

    ln_head_kernel<<<kM, 256>>>(gln, beln, Wcd2, bcd2, out_ct, out_enh);

    bias_out_kernel<<<kM/8, 256>>>(Wbe2, bbe2, out_wb);

    cred_kernel<<<kM/64, 256>>>(Wcr1 + (size_t)1024 * 512, Wcr2, bcr2, out_ct, out_cred);
}

// round 6
// speedup vs baseline: 7.6176x; 1.2907x over previous
#include <cuda_runtime.h>
#include <cuda_fp16.h>
#include <math.h>
#include <stdint.h>

// Problem constants
#define kB 8
#define kS 2048
#define kD 1024
#define kC 5
#define kM (kB * kS)  // 16384

// ---------------------------------------------------------------------------
// Scratch (device globals)
// ---------------------------------------------------------------------------
__device__ __half g_xh  [(size_t)kM * kD];     // 32 MB
__device__ __half g_ctxh[(size_t)kM * kD];     // 32 MB
__device__ float  g_big [(size_t)kM * 1280];   // 84 MB  merged G1|G4|G6
__device__ float  g_h   [(size_t)kM * kD];     // 64 MB  G3 out
__device__ float  g_ctbw[kM];
__device__ float  g_part[(size_t)kB * 64 * kD];
__device__ __half g_wth[(size_t)1280*1024 + (size_t)1024*2048];
__device__ float  g_biasA[1280];

#define WTH_MERGED 0
#define WTH_CD1 ((size_t)1280 * 1024)

// ---------------------------------------------------------------------------
// helpers
// ---------------------------------------------------------------------------
__device__ __forceinline__ uint32_t smem_u32(const void* p) {
    uint32_t a;
    asm("{ .reg .u64 t; cvta.to.shared.u64 t, %1; cvt.u32.u64 %0, t; }"
        : "=r"(a) : "l"(p));
    return a;
}
__device__ __forceinline__ void cp_async16(uint32_t dst, const void* src) {
    asm volatile("cp.async.cg.shared.global [%0], [%1], 16;"
                 :: "r"(dst), "l"(src));
}
__device__ __forceinline__ void cp_commit() {
    asm volatile("cp.async.commit_group;" ::: "memory");
}
template <int N>
__device__ __forceinline__ void cp_wait() {
    asm volatile("cp.async.wait_group %0;" :: "n"(N) : "memory");
}
__device__ __forceinline__ void ldsm_x4(uint32_t* r, uint32_t addr) {
    asm volatile("ldmatrix.sync.aligned.m8n8.x4.shared.b16 {%0,%1,%2,%3}, [%4];"
                 : "=r"(r[0]), "=r"(r[1]), "=r"(r[2]), "=r"(r[3]) : "r"(addr));
}
__device__ __forceinline__ void mma_f16(float* d, const uint32_t* a, const uint32_t* b) {
    asm volatile(
        "mma.sync.aligned.m16n8k16.row.col.f32.f16.f16.f32 "
        "{%0,%1,%2,%3}, {%4,%5,%6,%7}, {%8,%9}, {%0,%1,%2,%3};"
        : "+f"(d[0]), "+f"(d[1]), "+f"(d[2]), "+f"(d[3])
        : "r"(a[0]), "r"(a[1]), "r"(a[2]), "r"(a[3]),
          "r"(b[0]), "r"(b[1]));
}

// ---------------------------------------------------------------------------
// fp16 mma GEMM, cp.async 4-stage pipeline, ONE sync per k-iter.
// C[M,N] = act([A1|A2] @ Bt^T + bias), relu for cols < relu_upto.
// CTA tile 128x256, BK=64, 512 threads (16 warps 4x4), warp tile 32x64.
// ---------------------------------------------------------------------------
#define BM 128
#define BN 256
#define BK 64
#define LDAH 72                      // halves per smem row
#define ROWB (LDAH * 2)              // 144 bytes
#define NS 4
#define ASZB (BM * ROWB)             // 18432
#define TILEB ((BM + BN) * ROWB)     // 55296
#define SMEM_SZ (NS * TILEB)         // 221184

__global__ __launch_bounds__(512, 1) void gemm_h(
    const __half* __restrict__ A1, const __half* __restrict__ A2,
    const __half* __restrict__ Bt, const float* __restrict__ bias,
    float* __restrict__ C, int N, int K1, int K2, int relu_upto)
{
    extern __shared__ char sm[];
    const uint32_t smb = smem_u32(sm);

    const int tid  = threadIdx.x;
    const int lane = tid & 31;
    const int wid  = tid >> 5;
    const int wm   = wid >> 2;        // 0..3  (32-row slice)
    const int wn   = wid & 3;         // 0..3  (64-col slice)
    const int brow = blockIdx.y * BM;
    const int bcol = blockIdx.x * BN;
    const int K    = K1 + K2;
    const int iters = K / BK;

    const int a_row = wm * 32 + ((lane >> 3) & 1) * 8 + (lane & 7);
    const int a_k   = (lane >> 4) * 8;
    const int b_row = wn * 64 + (lane >> 4) * 8 + (lane & 7);
    const int b_k   = ((lane >> 3) & 1) * 8;

    // loader: (BM+BN)=384 rows x 64 halves (128B) = 8 chunks/row, 6/thread
    auto load_tile = [&](int stage, int kt) {
        const uint32_t sbase = smb + (uint32_t)(stage * TILEB);
#pragma unroll
        for (int j = 0; j < 6; j++) {
            const int c = tid + 512 * j;
            const int row = c >> 3;
            const int col = (c & 7) * 8;   // halves
            const uint32_t dst = sbase + (uint32_t)(row * ROWB + col * 2);
            const __half* src;
            if (row < BM) {
                src = (kt < K1)
                    ? A1 + (size_t)(brow + row) * K1 + kt + col
                    : A2 + (size_t)(brow + row) * K2 + (kt - K1) + col;
            } else {
                src = Bt + (size_t)(bcol + row - BM) * K + kt + col;
            }
            cp_async16(dst, src);
        }
    };

    float acc[2][8][4];
#pragma unroll
    for (int i = 0; i < 2; i++)
#pragma unroll
        for (int j = 0; j < 8; j++)
#pragma unroll
            for (int q = 0; q < 4; q++) acc[i][j][q] = 0.f;

#pragma unroll
    for (int s = 0; s < NS - 1; s++) {
        load_tile(s, s * BK);
        cp_commit();
    }

    for (int i = 0; i < iters; i++) {
        cp_wait<NS - 2>();          // tile i resident
        __syncthreads();            // all warps done with stage (i-1)%NS
        if (i + NS - 1 < iters) load_tile((i + NS - 1) % NS, (i + NS - 1) * BK);
        cp_commit();

        const uint32_t sa  = smb + (uint32_t)((i % NS) * TILEB);
        const uint32_t sbB = sa + ASZB;

#pragma unroll
        for (int ks = 0; ks < 4; ks++) {
            uint32_t af[2][4];
#pragma unroll
            for (int mt = 0; mt < 2; mt++)
                ldsm_x4(af[mt], sa + (uint32_t)((a_row + mt * 16) * ROWB + (ks * 16 + a_k) * 2));
            uint32_t bf[4][4];
#pragma unroll
            for (int np = 0; np < 4; np++)
                ldsm_x4(bf[np], sbB + (uint32_t)((b_row + np * 16) * ROWB + (ks * 16 + b_k) * 2));
#pragma unroll
            for (int mt = 0; mt < 2; mt++)
#pragma unroll
                for (int nt = 0; nt < 8; nt++)
                    mma_f16(acc[mt][nt], af[mt], &bf[nt >> 1][(nt & 1) * 2]);
        }
    }

    // Epilogue
#pragma unroll
    for (int mt = 0; mt < 2; mt++) {
        const int gr0 = brow + wm * 32 + mt * 16 + (lane >> 2);
#pragma unroll
        for (int h = 0; h < 2; h++) {
            const int row = gr0 + 8 * h;
#pragma unroll
            for (int nt = 0; nt < 8; nt++) {
                const int gc = bcol + wn * 64 + nt * 8 + (lane & 3) * 2;
                float v0 = acc[mt][nt][2 * h]     + bias[gc];
                float v1 = acc[mt][nt][2 * h + 1] + bias[gc + 1];
                if (gc < relu_upto) { v0 = fmaxf(v0, 0.f); v1 = fmaxf(v1, 0.f); }
                float2 o; o.x = v0; o.y = v1;
                *reinterpret_cast<float2*>(C + (size_t)row * N + gc) = o;
            }
        }
    }
}

// ---------------------------------------------------------------------------
// fused head: out_x copy + fp16 convert + chunk partial sums (reads x ONCE)
// ---------------------------------------------------------------------------
#define NCH 64
#define CH 32

__global__ __launch_bounds__(256) void fuse_head(
    const float* __restrict__ x, float* __restrict__ out_x, __half* __restrict__ xh)
{
    const int b = blockIdx.x, ch = blockIdx.y;
    const int d = threadIdx.x;
    const size_t base = ((size_t)b * kS + (size_t)ch * CH) * kD + d;
    float s[4] = {0, 0, 0, 0};
    for (int t = 0; t < CH; t++) {
#pragma unroll
        for (int dd = 0; dd < 4; dd++) {
            const size_t idx = base + (size_t)t * kD + dd * 256;
            const float v = x[idx];
            out_x[idx] = v;
            xh[idx] = __float2half(v);
            s[dd] += v;
        }
    }
    float* pp = g_part + ((size_t)b * NCH + ch) * kD + d;
#pragma unroll
    for (int dd = 0; dd < 4; dd++) pp[dd * 256] = s[dd];
}

// ---------------------------------------------------------------------------
// ctx_emit: exclusive scan over chunk partials + in-chunk scan (reads xh)
// ---------------------------------------------------------------------------
__global__ __launch_bounds__(256) void ctx_emit(const __half* __restrict__ xh) {
    const int b = blockIdx.x, ch = blockIdx.y;
    const int d = threadIdx.x;
    float pre[4] = {0, 0, 0, 0}, tot[4] = {0, 0, 0, 0};
    for (int c = 0; c < NCH; c++) {
        const float* pp = g_part + ((size_t)b * NCH + c) * kD + d;
#pragma unroll
        for (int dd = 0; dd < 4; dd++) {
            float p = pp[dd * 256];
            if (c < ch) pre[dd] += p;
            tot[dd] += p;
        }
    }
    const float inv_edge = 1.f / (float)(kS - 1);
    const size_t base = ((size_t)b * kS + (size_t)ch * CH) * kD + d;
    __half* cp = g_ctxh + base;
    const __half* xp = xh + base;
    for (int t = 0; t < CH; t++) {
        const int tg = ch * CH + t;
        const bool edge = (tg == 0) || (tg == kS - 1);
        const float ip = edge ? inv_edge : (0.5f / fmaxf((float)tg, 1.f));
        const float is = edge ? inv_edge : (0.5f / fmaxf((float)(kS - 1 - tg), 1.f));
#pragma unroll
        for (int dd = 0; dd < 4; dd++) {
            float xv = __half2float(xp[(size_t)t * kD + dd * 256]);
            float prefix = pre[dd];
            pre[dd] += xv;
            float suffix = tot[dd] - pre[dd];
            cp[(size_t)t * kD + dd * 256] = __float2half(prefix * ip + suffix * is);
        }
    }
}

// ---------------------------------------------------------------------------
// Weight transpose to fp16: W[K,N] -> Wt[N,K]
// ---------------------------------------------------------------------------
__global__ void transpose_h(const float* __restrict__ W, __half* __restrict__ Wt,
                            int K, int N)
{
    __shared__ float tile[32][33];
    const int n0 = blockIdx.x * 32;
    const int k0 = blockIdx.y * 32;
    const int tx = threadIdx.x, ty = threadIdx.y;
#pragma unroll
    for (int i = ty; i < 32; i += 8)
        tile[i][tx] = W[(size_t)(k0 + i) * N + n0 + tx];
    __syncthreads();
#pragma unroll
    for (int i = ty; i < 32; i += 8)
        Wt[(size_t)(n0 + i) * K + k0 + tx] = __float2half(tile[tx][i]);
}

// ---------------------------------------------------------------------------
// content_types: per-row dot-5 over K=512 (g_big cols 0..511), softmax(5)
// ---------------------------------------------------------------------------
__global__ __launch_bounds__(128) void content_kernel(
    const float* __restrict__ Wcc2, const float* __restrict__ bcc2,
    float* __restrict__ out_ct, float* __restrict__ out_rel)
{
    const int m = blockIdx.x;
    const float* row = g_big + (size_t)m * 1280;
    float acc[5] = {0, 0, 0, 0, 0};
    for (int k = threadIdx.x; k < 512; k += 128) {
        float v = row[k];
#pragma unroll
        for (int c = 0; c < 5; c++) acc[c] = fmaf(v, Wcc2[k * 5 + c], acc[c]);
    }
#pragma unroll
    for (int c = 0; c < 5; c++)
#pragma unroll
        for (int o = 16; o; o >>= 1) acc[c] += __shfl_xor_sync(0xffffffffu, acc[c], o);

    __shared__ float s[4][5];
    const int w = threadIdx.x >> 5;
    if ((threadIdx.x & 31) == 0) {
#pragma unroll
        for (int c = 0; c < 5; c++) s[w][c] = acc[c];
    }
    __syncthreads();
    if (threadIdx.x == 0) {
        float t[5];
#pragma unroll
        for (int c = 0; c < 5; c++) t[c] = s[0][c] + s[1][c] + s[2][c] + s[3][c] + bcc2[c];
        float mx = t[0];
#pragma unroll
        for (int c = 1; c < 5; c++) mx = fmaxf(mx, t[c]);
        float e[5], sum = 0.f;
#pragma unroll
        for (int c = 0; c < 5; c++) { e[c] = expf(t[c] - mx); sum += e[c]; }
        const float inv = 1.f / sum;
        const float bw[5] = {0.1f, 1.0f, 0.8f, 0.3f, 0.5f};
        float ws = 0.f;
#pragma unroll
        for (int c = 0; c < 5; c++) {
            float p = e[c] * inv;
            out_ct[(size_t)m * 5 + c] = p;
            ws = fmaf(p, bw[c], ws);
        }
        out_rel[m] = 1.f - e[3] * inv;
        g_ctbw[m] = ws;
    }
}

__device__ __forceinline__ float block_reduce_sum(float v, float* sbuf) {
#pragma unroll
    for (int o = 16; o; o >>= 1) v += __shfl_xor_sync(0xffffffffu, v, o);
    const int w = threadIdx.x >> 5;
    __syncthreads();
    if ((threadIdx.x & 31) == 0) sbuf[w] = v;
    __syncthreads();
    if (threadIdx.x == 0) {
        float r = 0.f;
        for (int i = 0; i < (int)(blockDim.x >> 5); i++) r += sbuf[i];
        sbuf[0] = r;
    }
    __syncthreads();
    return sbuf[0];
}

// ---------------------------------------------------------------------------
// LN + exact GELU + dot(W_cd2) + sigmoid -> enhanced
// ---------------------------------------------------------------------------
__global__ __launch_bounds__(256) void ln_head_kernel(
    const float* __restrict__ gln, const float* __restrict__ beln,
    const float* __restrict__ W2, const float* __restrict__ b2,
    const float* __restrict__ ct, float* __restrict__ out_enh)
{
    __shared__ float sbuf[8];
    const int m = blockIdx.x;
    const int t = threadIdx.x;
    const float4 v = reinterpret_cast<const float4*>(g_h + (size_t)m * kD)[t];

    float s = v.x + v.y + v.z + v.w;
    float q = v.x * v.x + v.y * v.y + v.z * v.z + v.w * v.w;
    const float sum = block_reduce_sum(s, sbuf);
    const float sq  = block_reduce_sum(q, sbuf);
    const float mu  = sum * (1.f / (float)kD);
    const float var = sq * (1.f / (float)kD) - mu * mu;
    const float rstd = rsqrtf(var + 1e-5f);

    const float4 gv  = reinterpret_cast<const float4*>(gln)[t];
    const float4 bev = reinterpret_cast<const float4*>(beln)[t];
    const float4 wv  = reinterpret_cast<const float4*>(W2)[t];

    const float kInvSqrt2 = 0.70710678118654752f;
    float dot = 0.f;
    float y;
    y = (v.x - mu) * rstd * gv.x + bev.x; y = 0.5f * y * (1.f + erff(y * kInvSqrt2)); dot = fmaf(y, wv.x, dot);
    y = (v.y - mu) * rstd * gv.y + bev.y; y = 0.5f * y * (1.f + erff(y * kInvSqrt2)); dot = fmaf(y, wv.y, dot);
    y = (v.z - mu) * rstd * gv.z + bev.z; y = 0.5f * y * (1.f + erff(y * kInvSqrt2)); dot = fmaf(y, wv.z, dot);
    y = (v.w - mu) * rstd * gv.w + bev.w; y = 0.5f * y * (1.f + erff(y * kInvSqrt2)); dot = fmaf(y, wv.w, dot);

    dot = block_reduce_sum(dot, sbuf);
    if (t == 0) {
        float cont = 1.f / (1.f + expf(-(dot + b2[0])));
        out_enh[m] = fmaxf(cont, ct[(size_t)m * 5 + 2]);
    }
}

// ---------------------------------------------------------------------------
// weighted_bias: warp-per-row dot over K=256 (g_big cols 512..767)
// ---------------------------------------------------------------------------
__global__ __launch_bounds__(256) void bias_out_kernel(
    const float* __restrict__ W, const float* __restrict__ b,
    float* __restrict__ out_wb)
{
    const int m = blockIdx.x * 8 + (threadIdx.x >> 5);
    const int l = threadIdx.x & 31;
    const float* row = g_big + (size_t)m * 1280 + 512;
    float acc = 0.f;
#pragma unroll
    for (int i = 0; i < 8; i++) acc = fmaf(row[l + 32 * i], W[l + 32 * i], acc);
#pragma unroll
    for (int o = 16; o; o >>= 1) acc += __shfl_xor_sync(0xffffffffu, acc, o);
    if (l == 0) {
        float bs = 1.f / (1.f + expf(-(acc + b[0])));
        out_wb[m] = bs * g_ctbw[m];
    }
}

// ---------------------------------------------------------------------------
// credibility: pre-act (g_big cols 768..1279) + ct@Wtail, relu, dot, sigmoid
// ---------------------------------------------------------------------------
__global__ __launch_bounds__(256) void cred_kernel(
    const float* __restrict__ Wtail,
    const float* __restrict__ Wcr2, const float* __restrict__ bcr2,
    const float* __restrict__ ct, float* __restrict__ out_cred)
{
    __shared__ float swt[5 * 512 + 512];
    for (int i = threadIdx.x; i < 5 * 512; i += 256) swt[i] = Wtail[i];
    for (int i = threadIdx.x; i < 512; i += 256) swt[5 * 512 + i] = Wcr2[i];
    __syncthreads();

    const int w = threadIdx.x >> 5;
    const int l = threadIdx.x & 31;
    const float b0 = bcr2[0];

#pragma unroll
    for (int r = 0; r < 8; r++) {
        const int m = blockIdx.x * 64 + w * 8 + r;
        const float* pre = g_big + (size_t)m * 1280 + 768;
        float ctm[5];
#pragma unroll
        for (int c = 0; c < 5; c++) ctm[c] = ct[(size_t)m * 5 + c];
        float acc = 0.f;
#pragma unroll
        for (int i = 0; i < 16; i++) {
            const int j = l + 32 * i;
            float v = pre[j];
#pragma unroll
            for (int c = 0; c < 5; c++) v = fmaf(ctm[c], swt[c * 512 + j], v);
            v = fmaxf(v, 0.f);
            acc = fmaf(v, swt[5 * 512 + j], acc);
        }
#pragma unroll
        for (int o = 16; o; o >>= 1) acc += __shfl_xor_sync(0xffffffffu, acc, o);
        if (l == 0) out_cred[m] = 1.f / (1.f + expf(-(acc + b0)));
    }
}

// ---------------------------------------------------------------------------
// Launch
// ---------------------------------------------------------------------------
extern "C" void kernel_launch(void* const* d_in, const int* in_sizes, int n_in,
                              void* d_out, int out_size)
{
    (void)in_sizes; (void)n_in; (void)out_size;

    const float* x    = (const float*)d_in[0];
    const float* Wcc1 = (const float*)d_in[1];
    const float* bcc1 = (const float*)d_in[2];
    const float* Wcc2 = (const float*)d_in[3];
    const float* bcc2 = (const float*)d_in[4];
    const float* Wcd1 = (const float*)d_in[5];
    const float* bcd1 = (const float*)d_in[6];
    const float* gln  = (const float*)d_in[7];
    const float* beln = (const float*)d_in[8];
    const float* Wcd2 = (const float*)d_in[9];
    const float* bcd2 = (const float*)d_in[10];
    const float* Wbe1 = (const float*)d_in[11];
    const float* bbe1 = (const float*)d_in[12];
    const float* Wbe2 = (const float*)d_in[13];
    const float* bbe2 = (const float*)d_in[14];
    const float* Wcr1 = (const float*)d_in[15];
    const float* bcr1 = (const float*)d_in[16];
    const float* Wcr2 = (const float*)d_in[17];
    const float* bcr2 = (const float*)d_in[18];

    float* out_x    = (float*)d_out;
    float* out_ct   = out_x + (size_t)kM * kD;
    float* out_enh  = out_ct + (size_t)kM * kC;
    float* out_wb   = out_enh + kM;
    float* out_rel  = out_wb + kM;
    float* out_cred = out_rel + kM;

    __half *xh, *ctxh, *wth;
    float *bigp, *hp, *biasA;
    cudaGetSymbolAddress((void**)&xh,    g_xh);
    cudaGetSymbolAddress((void**)&ctxh,  g_ctxh);
    cudaGetSymbolAddress((void**)&wth,   g_wth);
    cudaGetSymbolAddress((void**)&bigp,  g_big);
    cudaGetSymbolAddress((void**)&hp,    g_h);
    cudaGetSymbolAddress((void**)&biasA, g_biasA);

    cudaFuncSetAttribute(gemm_h, cudaFuncAttributeMaxDynamicSharedMemorySize, SMEM_SZ);

    // fused: out_x copy + xh convert + chunk partials (x read once)
    fuse_head<<<dim3(kB, NCH), 256>>>(x, out_x, xh);

    // merged bias vector [bcc1 | bbe1 | bcr1]
    cudaMemcpyAsync(biasA,       bcc1, 512 * sizeof(float), cudaMemcpyDeviceToDevice, 0);
    cudaMemcpyAsync(biasA + 512, bbe1, 256 * sizeof(float), cudaMemcpyDeviceToDevice, 0);
    cudaMemcpyAsync(biasA + 768, bcr1, 512 * sizeof(float), cudaMemcpyDeviceToDevice, 0);

    // weight transposes -> half
    transpose_h<<<dim3(512/32, 1024/32), dim3(32, 8)>>>(Wcc1, wth + WTH_MERGED,                    1024, 512);
    transpose_h<<<dim3(256/32, 1024/32), dim3(32, 8)>>>(Wbe1, wth + WTH_MERGED + (size_t)512*1024, 1024, 256);
    transpose_h<<<dim3(512/32, 1024/32), dim3(32, 8)>>>(Wcr1, wth + WTH_MERGED + (size_t)768*1024, 1024, 512);
    transpose_h<<<dim3(1024/32, 2048/32), dim3(32, 8)>>>(Wcd1, wth + WTH_CD1, 2048, 1024);

    // ctx scan (reads xh + partials)
    ctx_emit<<<dim3(kB, NCH), 256>>>(xh);

    // merged GEMM: g_big = [relu(x@Wcc1+b) | relu(x@Wbe1+b) | x@Wcr1+b]
    gemm_h<<<dim3(1280/BN, kM/BM), 512, SMEM_SZ>>>(
        xh, nullptr, wth + WTH_MERGED, biasA, bigp, 1280, 1024, 0, 768);

    content_kernel<<<kM, 128>>>(Wcc2, bcc2, out_ct, out_rel);

    // G3: h = [x|ctx] @ Wcd1 + bcd1
    gemm_h<<<dim3(1024/BN, kM/BM), 512, SMEM_SZ>>>(
        xh, ctxh, wth + WTH_CD1, bcd1, hp, 1024, 1024, 1024, 0);

    ln_head_kernel<<<kM, 256>>>(gln, beln, Wcd2, bcd2, out_ct, out_enh);

    bias_out_kernel<<<kM/8, 256>>>(Wbe2, bbe2, out_wb);

    cred_kernel<<<kM/64, 256>>>(Wcr1 + (size_t)1024 * 512, Wcr2, bcr2, out_ct, out_cred);
}

// round 7
// speedup vs baseline: 8.1705x; 1.0726x over previous
#include <cuda_runtime.h>
#include <cuda_fp16.h>
#include <math.h>
#include <stdint.h>

// Problem constants
#define kB 8
#define kS 2048
#define kD 1024
#define kC 5
#define kM (kB * kS)  // 16384

// ---------------------------------------------------------------------------
// Scratch (device globals)
// ---------------------------------------------------------------------------
__device__ __half g_xh  [(size_t)kM * kD];     // 32 MB
__device__ __half g_ctxh[(size_t)kM * kD];     // 32 MB
__device__ __half g_bigh[(size_t)kM * 1280];   // 42 MB  merged G1|G4|G6
__device__ __half g_hh  [(size_t)kM * kD];     // 32 MB  G3 out
__device__ float  g_ctbw[kM];
__device__ float  g_part[(size_t)kB * 64 * kD];
__device__ __half g_wth[(size_t)1280*1024 + (size_t)1024*2048];
__device__ float  g_biasA[1280];

#define WTH_MERGED 0
#define WTH_CD1 ((size_t)1280 * 1024)

// ---------------------------------------------------------------------------
// helpers
// ---------------------------------------------------------------------------
__device__ __forceinline__ uint32_t smem_u32(const void* p) {
    uint32_t a;
    asm("{ .reg .u64 t; cvta.to.shared.u64 t, %1; cvt.u32.u64 %0, t; }"
        : "=r"(a) : "l"(p));
    return a;
}
__device__ __forceinline__ void cp_async16(uint32_t dst, const void* src) {
    asm volatile("cp.async.cg.shared.global [%0], [%1], 16;"
                 :: "r"(dst), "l"(src));
}
__device__ __forceinline__ void cp_commit() {
    asm volatile("cp.async.commit_group;" ::: "memory");
}
template <int N>
__device__ __forceinline__ void cp_wait() {
    asm volatile("cp.async.wait_group %0;" :: "n"(N) : "memory");
}
__device__ __forceinline__ void ldsm_x4(uint32_t* r, uint32_t addr) {
    asm volatile("ldmatrix.sync.aligned.m8n8.x4.shared.b16 {%0,%1,%2,%3}, [%4];"
                 : "=r"(r[0]), "=r"(r[1]), "=r"(r[2]), "=r"(r[3]) : "r"(addr));
}
__device__ __forceinline__ void mma_f16(float* d, const uint32_t* a, const uint32_t* b) {
    asm volatile(
        "mma.sync.aligned.m16n8k16.row.col.f32.f16.f16.f32 "
        "{%0,%1,%2,%3}, {%4,%5,%6,%7}, {%8,%9}, {%0,%1,%2,%3};"
        : "+f"(d[0]), "+f"(d[1]), "+f"(d[2]), "+f"(d[3])
        : "r"(a[0]), "r"(a[1]), "r"(a[2]), "r"(a[3]),
          "r"(b[0]), "r"(b[1]));
}

// ---------------------------------------------------------------------------
// FUSED fp16 mma GEMM: both GEMMs in one grid.
//   blockIdx.x in [0,4):  G3   h = [xh|ctxh] @ Wcd1^T + bcd1   (N=1024, K=2048)
//   blockIdx.x in [4,9):  MRG  big = act(xh @ Wm^T + bm)       (N=1280, K=1024)
// CTA tile 128x256, BK=64, 512 threads (16 warps 4x4), warp tile 32x64.
// Outputs are fp16.
// ---------------------------------------------------------------------------
#define BM 128
#define BN 256
#define BK 64
#define LDAH 72
#define ROWB (LDAH * 2)              // 144 bytes
#define NS 4
#define ASZB (BM * ROWB)
#define TILEB ((BM + BN) * ROWB)     // 55296
#define SMEM_SZ (NS * TILEB)         // 221184

__global__ __launch_bounds__(512, 1) void gemm_fused(
    const __half* __restrict__ xh, const __half* __restrict__ ctxh,
    const __half* __restrict__ WtM, const float* __restrict__ biasM,
    const __half* __restrict__ Wt3, const float* __restrict__ bias3,
    __half* __restrict__ outM, __half* __restrict__ out3)
{
    extern __shared__ char sm[];
    const uint32_t smb = smem_u32(sm);

    const int tid  = threadIdx.x;
    const int lane = tid & 31;
    const int wid  = tid >> 5;
    const int wm   = wid >> 2;
    const int wn   = wid & 3;

    const bool isG3 = blockIdx.x < 4;
    const int  bcol = (isG3 ? blockIdx.x : (blockIdx.x - 4)) * BN;
    const int  brow = blockIdx.y * BM;
    const int  N    = isG3 ? 1024 : 1280;
    const int  K1   = 1024;
    const int  K    = isG3 ? 2048 : 1024;
    const int  relu_upto = isG3 ? 0 : 768;
    const __half* A2  = ctxh;   // used only when kt >= K1 (G3 only)
    const __half* Bt  = isG3 ? Wt3 : WtM;
    const float*  bias = isG3 ? bias3 : biasM;
    __half* C = isG3 ? out3 : outM;

    const int iters = K / BK;

    const int a_row = wm * 32 + ((lane >> 3) & 1) * 8 + (lane & 7);
    const int a_k   = (lane >> 4) * 8;
    const int b_row = wn * 64 + (lane >> 4) * 8 + (lane & 7);
    const int b_k   = ((lane >> 3) & 1) * 8;

    auto load_tile = [&](int stage, int kt) {
        const uint32_t sbase = smb + (uint32_t)(stage * TILEB);
#pragma unroll
        for (int j = 0; j < 6; j++) {
            const int c = tid + 512 * j;
            const int row = c >> 3;
            const int col = (c & 7) * 8;   // halves
            const uint32_t dst = sbase + (uint32_t)(row * ROWB + col * 2);
            const __half* src;
            if (row < BM) {
                src = (kt < K1)
                    ? xh + (size_t)(brow + row) * K1 + kt + col
                    : A2 + (size_t)(brow + row) * K1 + (kt - K1) + col;
            } else {
                src = Bt + (size_t)(bcol + row - BM) * K + kt + col;
            }
            cp_async16(dst, src);
        }
    };

    float acc[2][8][4];
#pragma unroll
    for (int i = 0; i < 2; i++)
#pragma unroll
        for (int j = 0; j < 8; j++)
#pragma unroll
            for (int q = 0; q < 4; q++) acc[i][j][q] = 0.f;

#pragma unroll
    for (int s = 0; s < NS - 1; s++) {
        load_tile(s, s * BK);
        cp_commit();
    }

    for (int i = 0; i < iters; i++) {
        cp_wait<NS - 2>();
        __syncthreads();
        if (i + NS - 1 < iters) load_tile((i + NS - 1) % NS, (i + NS - 1) * BK);
        cp_commit();

        const uint32_t sa  = smb + (uint32_t)((i % NS) * TILEB);
        const uint32_t sbB = sa + ASZB;

#pragma unroll
        for (int ks = 0; ks < 4; ks++) {
            uint32_t af[2][4];
#pragma unroll
            for (int mt = 0; mt < 2; mt++)
                ldsm_x4(af[mt], sa + (uint32_t)((a_row + mt * 16) * ROWB + (ks * 16 + a_k) * 2));
            uint32_t bf[4][4];
#pragma unroll
            for (int np = 0; np < 4; np++)
                ldsm_x4(bf[np], sbB + (uint32_t)((b_row + np * 16) * ROWB + (ks * 16 + b_k) * 2));
#pragma unroll
            for (int mt = 0; mt < 2; mt++)
#pragma unroll
                for (int nt = 0; nt < 8; nt++)
                    mma_f16(acc[mt][nt], af[mt], &bf[nt >> 1][(nt & 1) * 2]);
        }
    }

    // Epilogue: bias (+relu for cols<relu_upto), fp16 output
#pragma unroll
    for (int mt = 0; mt < 2; mt++) {
        const int gr0 = brow + wm * 32 + mt * 16 + (lane >> 2);
#pragma unroll
        for (int h = 0; h < 2; h++) {
            const int row = gr0 + 8 * h;
#pragma unroll
            for (int nt = 0; nt < 8; nt++) {
                const int gc = bcol + wn * 64 + nt * 8 + (lane & 3) * 2;
                float v0 = acc[mt][nt][2 * h]     + bias[gc];
                float v1 = acc[mt][nt][2 * h + 1] + bias[gc + 1];
                if (gc < relu_upto) { v0 = fmaxf(v0, 0.f); v1 = fmaxf(v1, 0.f); }
                *reinterpret_cast<__half2*>(C + (size_t)row * N + gc) =
                    __floats2half2_rn(v0, v1);
            }
        }
    }
}

// ---------------------------------------------------------------------------
// fused head: out_x copy + fp16 convert + chunk partial sums (reads x ONCE)
// ---------------------------------------------------------------------------
#define NCH 64
#define CH 32

__global__ __launch_bounds__(256) void fuse_head(
    const float* __restrict__ x, float* __restrict__ out_x, __half* __restrict__ xh)
{
    const int b = blockIdx.x, ch = blockIdx.y;
    const int d = threadIdx.x;
    const size_t base = ((size_t)b * kS + (size_t)ch * CH) * kD + d;
    float s[4] = {0, 0, 0, 0};
    for (int t = 0; t < CH; t++) {
#pragma unroll
        for (int dd = 0; dd < 4; dd++) {
            const size_t idx = base + (size_t)t * kD + dd * 256;
            const float v = x[idx];
            out_x[idx] = v;
            xh[idx] = __float2half(v);
            s[dd] += v;
        }
    }
    float* pp = g_part + ((size_t)b * NCH + ch) * kD + d;
#pragma unroll
    for (int dd = 0; dd < 4; dd++) pp[dd * 256] = s[dd];
}

// ---------------------------------------------------------------------------
// ctx_emit: exclusive scan over chunk partials + in-chunk scan (reads xh)
// ---------------------------------------------------------------------------
__global__ __launch_bounds__(256) void ctx_emit(const __half* __restrict__ xh) {
    const int b = blockIdx.x, ch = blockIdx.y;
    const int d = threadIdx.x;
    float pre[4] = {0, 0, 0, 0}, tot[4] = {0, 0, 0, 0};
    for (int c = 0; c < NCH; c++) {
        const float* pp = g_part + ((size_t)b * NCH + c) * kD + d;
#pragma unroll
        for (int dd = 0; dd < 4; dd++) {
            float p = pp[dd * 256];
            if (c < ch) pre[dd] += p;
            tot[dd] += p;
        }
    }
    const float inv_edge = 1.f / (float)(kS - 1);
    const size_t base = ((size_t)b * kS + (size_t)ch * CH) * kD + d;
    __half* cp = g_ctxh + base;
    const __half* xp = xh + base;
    for (int t = 0; t < CH; t++) {
        const int tg = ch * CH + t;
        const bool edge = (tg == 0) || (tg == kS - 1);
        const float ip = edge ? inv_edge : (0.5f / fmaxf((float)tg, 1.f));
        const float is = edge ? inv_edge : (0.5f / fmaxf((float)(kS - 1 - tg), 1.f));
#pragma unroll
        for (int dd = 0; dd < 4; dd++) {
            float xv = __half2float(xp[(size_t)t * kD + dd * 256]);
            float prefix = pre[dd];
            pre[dd] += xv;
            float suffix = tot[dd] - pre[dd];
            cp[(size_t)t * kD + dd * 256] = __float2half(prefix * ip + suffix * is);
        }
    }
}

// ---------------------------------------------------------------------------
// Weight transpose to fp16: W[K,N] -> Wt[N,K]
// ---------------------------------------------------------------------------
__global__ void transpose_h(const float* __restrict__ W, __half* __restrict__ Wt,
                            int K, int N)
{
    __shared__ float tile[32][33];
    const int n0 = blockIdx.x * 32;
    const int k0 = blockIdx.y * 32;
    const int tx = threadIdx.x, ty = threadIdx.y;
#pragma unroll
    for (int i = ty; i < 32; i += 8)
        tile[i][tx] = W[(size_t)(k0 + i) * N + n0 + tx];
    __syncthreads();
#pragma unroll
    for (int i = ty; i < 32; i += 8)
        Wt[(size_t)(n0 + i) * K + k0 + tx] = __float2half(tile[tx][i]);
}

// ---------------------------------------------------------------------------
// content_types: per-row dot-5 over K=512 (g_bigh cols 0..511), softmax(5)
// ---------------------------------------------------------------------------
__global__ __launch_bounds__(128) void content_kernel(
    const float* __restrict__ Wcc2, const float* __restrict__ bcc2,
    float* __restrict__ out_ct, float* __restrict__ out_rel)
{
    const int m = blockIdx.x;
    const __half* row = g_bigh + (size_t)m * 1280;
    float acc[5] = {0, 0, 0, 0, 0};
    for (int k = threadIdx.x; k < 512; k += 128) {
        float v = __half2float(row[k]);
#pragma unroll
        for (int c = 0; c < 5; c++) acc[c] = fmaf(v, Wcc2[k * 5 + c], acc[c]);
    }
#pragma unroll
    for (int c = 0; c < 5; c++)
#pragma unroll
        for (int o = 16; o; o >>= 1) acc[c] += __shfl_xor_sync(0xffffffffu, acc[c], o);

    __shared__ float s[4][5];
    const int w = threadIdx.x >> 5;
    if ((threadIdx.x & 31) == 0) {
#pragma unroll
        for (int c = 0; c < 5; c++) s[w][c] = acc[c];
    }
    __syncthreads();
    if (threadIdx.x == 0) {
        float t[5];
#pragma unroll
        for (int c = 0; c < 5; c++) t[c] = s[0][c] + s[1][c] + s[2][c] + s[3][c] + bcc2[c];
        float mx = t[0];
#pragma unroll
        for (int c = 1; c < 5; c++) mx = fmaxf(mx, t[c]);
        float e[5], sum = 0.f;
#pragma unroll
        for (int c = 0; c < 5; c++) { e[c] = expf(t[c] - mx); sum += e[c]; }
        const float inv = 1.f / sum;
        const float bw[5] = {0.1f, 1.0f, 0.8f, 0.3f, 0.5f};
        float ws = 0.f;
#pragma unroll
        for (int c = 0; c < 5; c++) {
            float p = e[c] * inv;
            out_ct[(size_t)m * 5 + c] = p;
            ws = fmaf(p, bw[c], ws);
        }
        out_rel[m] = 1.f - e[3] * inv;
        g_ctbw[m] = ws;
    }
}

__device__ __forceinline__ float block_reduce_sum(float v, float* sbuf) {
#pragma unroll
    for (int o = 16; o; o >>= 1) v += __shfl_xor_sync(0xffffffffu, v, o);
    const int w = threadIdx.x >> 5;
    __syncthreads();
    if ((threadIdx.x & 31) == 0) sbuf[w] = v;
    __syncthreads();
    if (threadIdx.x == 0) {
        float r = 0.f;
        for (int i = 0; i < (int)(blockDim.x >> 5); i++) r += sbuf[i];
        sbuf[0] = r;
    }
    __syncthreads();
    return sbuf[0];
}

// ---------------------------------------------------------------------------
// LN + exact GELU + dot(W_cd2) + sigmoid -> enhanced   (reads fp16 h)
// ---------------------------------------------------------------------------
__global__ __launch_bounds__(256) void ln_head_kernel(
    const float* __restrict__ gln, const float* __restrict__ beln,
    const float* __restrict__ W2, const float* __restrict__ b2,
    const float* __restrict__ ct, float* __restrict__ out_enh)
{
    __shared__ float sbuf[8];
    const int m = blockIdx.x;
    const int t = threadIdx.x;
    const __half2* hp2 = reinterpret_cast<const __half2*>(g_hh + (size_t)m * kD);
    const float2 p01 = __half22float2(hp2[2 * t]);
    const float2 p23 = __half22float2(hp2[2 * t + 1]);
    float4 v; v.x = p01.x; v.y = p01.y; v.z = p23.x; v.w = p23.y;

    float s = v.x + v.y + v.z + v.w;
    float q = v.x * v.x + v.y * v.y + v.z * v.z + v.w * v.w;
    const float sum = block_reduce_sum(s, sbuf);
    const float sq  = block_reduce_sum(q, sbuf);
    const float mu  = sum * (1.f / (float)kD);
    const float var = sq * (1.f / (float)kD) - mu * mu;
    const float rstd = rsqrtf(var + 1e-5f);

    const float4 gv  = reinterpret_cast<const float4*>(gln)[t];
    const float4 bev = reinterpret_cast<const float4*>(beln)[t];
    const float4 wv  = reinterpret_cast<const float4*>(W2)[t];

    const float kInvSqrt2 = 0.70710678118654752f;
    float dot = 0.f;
    float y;
    y = (v.x - mu) * rstd * gv.x + bev.x; y = 0.5f * y * (1.f + erff(y * kInvSqrt2)); dot = fmaf(y, wv.x, dot);
    y = (v.y - mu) * rstd * gv.y + bev.y; y = 0.5f * y * (1.f + erff(y * kInvSqrt2)); dot = fmaf(y, wv.y, dot);
    y = (v.z - mu) * rstd * gv.z + bev.z; y = 0.5f * y * (1.f + erff(y * kInvSqrt2)); dot = fmaf(y, wv.z, dot);
    y = (v.w - mu) * rstd * gv.w + bev.w; y = 0.5f * y * (1.f + erff(y * kInvSqrt2)); dot = fmaf(y, wv.w, dot);

    dot = block_reduce_sum(dot, sbuf);
    if (t == 0) {
        float cont = 1.f / (1.f + expf(-(dot + b2[0])));
        out_enh[m] = fmaxf(cont, ct[(size_t)m * 5 + 2]);
    }
}

// ---------------------------------------------------------------------------
// weighted_bias: warp-per-row dot over K=256 (g_bigh cols 512..767)
// ---------------------------------------------------------------------------
__global__ __launch_bounds__(256) void bias_out_kernel(
    const float* __restrict__ W, const float* __restrict__ b,
    float* __restrict__ out_wb)
{
    const int m = blockIdx.x * 8 + (threadIdx.x >> 5);
    const int l = threadIdx.x & 31;
    const __half* row = g_bigh + (size_t)m * 1280 + 512;
    float acc = 0.f;
#pragma unroll
    for (int i = 0; i < 8; i++)
        acc = fmaf(__half2float(row[l + 32 * i]), W[l + 32 * i], acc);
#pragma unroll
    for (int o = 16; o; o >>= 1) acc += __shfl_xor_sync(0xffffffffu, acc, o);
    if (l == 0) {
        float bs = 1.f / (1.f + expf(-(acc + b[0])));
        out_wb[m] = bs * g_ctbw[m];
    }
}

// ---------------------------------------------------------------------------
// credibility: pre-act (g_bigh cols 768..1279) + ct@Wtail, relu, dot, sigmoid
// ---------------------------------------------------------------------------
__global__ __launch_bounds__(256) void cred_kernel(
    const float* __restrict__ Wtail,
    const float* __restrict__ Wcr2, const float* __restrict__ bcr2,
    const float* __restrict__ ct, float* __restrict__ out_cred)
{
    __shared__ float swt[5 * 512 + 512];
    for (int i = threadIdx.x; i < 5 * 512; i += 256) swt[i] = Wtail[i];
    for (int i = threadIdx.x; i < 512; i += 256) swt[5 * 512 + i] = Wcr2[i];
    __syncthreads();

    const int w = threadIdx.x >> 5;
    const int l = threadIdx.x & 31;
    const float b0 = bcr2[0];

#pragma unroll
    for (int r = 0; r < 8; r++) {
        const int m = blockIdx.x * 64 + w * 8 + r;
        const __half* pre = g_bigh + (size_t)m * 1280 + 768;
        float ctm[5];
#pragma unroll
        for (int c = 0; c < 5; c++) ctm[c] = ct[(size_t)m * 5 + c];
        float acc = 0.f;
#pragma unroll
        for (int i = 0; i < 16; i++) {
            const int j = l + 32 * i;
            float v = __half2float(pre[j]);
#pragma unroll
            for (int c = 0; c < 5; c++) v = fmaf(ctm[c], swt[c * 512 + j], v);
            v = fmaxf(v, 0.f);
            acc = fmaf(v, swt[5 * 512 + j], acc);
        }
#pragma unroll
        for (int o = 16; o; o >>= 1) acc += __shfl_xor_sync(0xffffffffu, acc, o);
        if (l == 0) out_cred[m] = 1.f / (1.f + expf(-(acc + b0)));
    }
}

// ---------------------------------------------------------------------------
// Launch
// ---------------------------------------------------------------------------
extern "C" void kernel_launch(void* const* d_in, const int* in_sizes, int n_in,
                              void* d_out, int out_size)
{
    (void)in_sizes; (void)n_in; (void)out_size;

    const float* x    = (const float*)d_in[0];
    const float* Wcc1 = (const float*)d_in[1];
    const float* bcc1 = (const float*)d_in[2];
    const float* Wcc2 = (const float*)d_in[3];
    const float* bcc2 = (const float*)d_in[4];
    const float* Wcd1 = (const float*)d_in[5];
    const float* bcd1 = (const float*)d_in[6];
    const float* gln  = (const float*)d_in[7];
    const float* beln = (const float*)d_in[8];
    const float* Wcd2 = (const float*)d_in[9];
    const float* bcd2 = (const float*)d_in[10];
    const float* Wbe1 = (const float*)d_in[11];
    const float* bbe1 = (const float*)d_in[12];
    const float* Wbe2 = (const float*)d_in[13];
    const float* bbe2 = (const float*)d_in[14];
    const float* Wcr1 = (const float*)d_in[15];
    const float* bcr1 = (const float*)d_in[16];
    const float* Wcr2 = (const float*)d_in[17];
    const float* bcr2 = (const float*)d_in[18];

    float* out_x    = (float*)d_out;
    float* out_ct   = out_x + (size_t)kM * kD;
    float* out_enh  = out_ct + (size_t)kM * kC;
    float* out_wb   = out_enh + kM;
    float* out_rel  = out_wb + kM;
    float* out_cred = out_rel + kM;

    __half *xh, *ctxh, *wth, *bigp, *hp;
    float *biasA;
    cudaGetSymbolAddress((void**)&xh,    g_xh);
    cudaGetSymbolAddress((void**)&ctxh,  g_ctxh);
    cudaGetSymbolAddress((void**)&wth,   g_wth);
    cudaGetSymbolAddress((void**)&bigp,  g_bigh);
    cudaGetSymbolAddress((void**)&hp,    g_hh);
    cudaGetSymbolAddress((void**)&biasA, g_biasA);

    cudaFuncSetAttribute(gemm_fused, cudaFuncAttributeMaxDynamicSharedMemorySize, SMEM_SZ);

    // fused: out_x copy + xh convert + chunk partials (x read once)
    fuse_head<<<dim3(kB, NCH), 256>>>(x, out_x, xh);

    // merged bias vector [bcc1 | bbe1 | bcr1]
    cudaMemcpyAsync(biasA,       bcc1, 512 * sizeof(float), cudaMemcpyDeviceToDevice, 0);
    cudaMemcpyAsync(biasA + 512, bbe1, 256 * sizeof(float), cudaMemcpyDeviceToDevice, 0);
    cudaMemcpyAsync(biasA + 768, bcr1, 512 * sizeof(float), cudaMemcpyDeviceToDevice, 0);

    // weight transposes -> half
    transpose_h<<<dim3(512/32, 1024/32), dim3(32, 8)>>>(Wcc1, wth + WTH_MERGED,                    1024, 512);
    transpose_h<<<dim3(256/32, 1024/32), dim3(32, 8)>>>(Wbe1, wth + WTH_MERGED + (size_t)512*1024, 1024, 256);
    transpose_h<<<dim3(512/32, 1024/32), dim3(32, 8)>>>(Wcr1, wth + WTH_MERGED + (size_t)768*1024, 1024, 512);
    transpose_h<<<dim3(1024/32, 2048/32), dim3(32, 8)>>>(Wcd1, wth + WTH_CD1, 2048, 1024);

    // ctx scan
    ctx_emit<<<dim3(kB, NCH), 256>>>(xh);

    // ONE fused GEMM launch: G3 (x<4) + merged (x in 4..8)
    gemm_fused<<<dim3(9, kM/BM), 512, SMEM_SZ>>>(
        xh, ctxh,
        wth + WTH_MERGED, biasA,
        wth + WTH_CD1, bcd1,
        bigp, hp);

    content_kernel<<<kM, 128>>>(Wcc2, bcc2, out_ct, out_rel);

    ln_head_kernel<<<kM, 256>>>(gln, beln, Wcd2, bcd2, out_ct, out_enh);

    bias_out_kernel<<<kM/8, 256>>>(Wbe2, bbe2, out_wb);

    cred_kernel<<<kM/64, 256>>>(Wcr1 + (size_t)1024 * 512, Wcr2, bcr2, out_ct, out_cred);
}

// round 8
// speedup vs baseline: 8.5198x; 1.0427x over previous
#include <cuda_runtime.h>
#include <cuda_fp16.h>
#include <math.h>
#include <stdint.h>

// Problem constants
#define kB 8
#define kS 2048
#define kD 1024
#define kC 5
#define kM (kB * kS)  // 16384

// ---------------------------------------------------------------------------
// Scratch (device globals)
// ---------------------------------------------------------------------------
__device__ __half g_xh  [(size_t)kM * kD];     // 32 MB
__device__ __half g_ctxh[(size_t)kM * kD];     // 32 MB
__device__ __half g_bigh[(size_t)kM * 1280];   // 42 MB  merged G1|G4|G6
__device__ __half g_hh  [(size_t)kM * kD];     // 32 MB  G3 out
__device__ float  g_ctbw[kM];
__device__ float  g_part[(size_t)kB * 64 * kD];
__device__ __half g_wth[(size_t)1280*1024 + (size_t)1024*2048];
__device__ float  g_biasA[1280];

#define WTH_MERGED 0
#define WTH_CD1 ((size_t)1280 * 1024)

// ---------------------------------------------------------------------------
// helpers
// ---------------------------------------------------------------------------
__device__ __forceinline__ uint32_t smem_u32(const void* p) {
    uint32_t a;
    asm("{ .reg .u64 t; cvta.to.shared.u64 t, %1; cvt.u32.u64 %0, t; }"
        : "=r"(a) : "l"(p));
    return a;
}
__device__ __forceinline__ void cp_async16(uint32_t dst, const void* src) {
    asm volatile("cp.async.cg.shared.global [%0], [%1], 16;"
                 :: "r"(dst), "l"(src));
}
__device__ __forceinline__ void cp_commit() {
    asm volatile("cp.async.commit_group;" ::: "memory");
}
template <int N>
__device__ __forceinline__ void cp_wait() {
    asm volatile("cp.async.wait_group %0;" :: "n"(N) : "memory");
}
__device__ __forceinline__ void ldsm_x4(uint32_t* r, uint32_t addr) {
    asm volatile("ldmatrix.sync.aligned.m8n8.x4.shared.b16 {%0,%1,%2,%3}, [%4];"
                 : "=r"(r[0]), "=r"(r[1]), "=r"(r[2]), "=r"(r[3]) : "r"(addr));
}
__device__ __forceinline__ void mma_f16(float* d, const uint32_t* a, const uint32_t* b) {
    asm volatile(
        "mma.sync.aligned.m16n8k16.row.col.f32.f16.f16.f32 "
        "{%0,%1,%2,%3}, {%4,%5,%6,%7}, {%8,%9}, {%0,%1,%2,%3};"
        : "+f"(d[0]), "+f"(d[1]), "+f"(d[2]), "+f"(d[3])
        : "r"(a[0]), "r"(a[1]), "r"(a[2]), "r"(a[3]),
          "r"(b[0]), "r"(b[1]));
}

// ---------------------------------------------------------------------------
// FUSED fp16 mma GEMM, 2 CTAs/SM.
//   blockIdx.x in [0,8):   G3   h = [xh|ctxh] @ Wcd1^T + bcd1  (N=1024, K=2048)
//   blockIdx.x in [8,18):  MRG  big = act(xh @ Wm^T + bm)      (N=1280, K=1024)
// CTA tile 128x128, BK=64, 256 threads (8 warps 2x4), warp tile 64x32.
// ---------------------------------------------------------------------------
#define BM 128
#define BN 128
#define BK 64
#define LDAH 72
#define ROWB (LDAH * 2)              // 144 bytes
#define NS 3
#define ASZB (BM * ROWB)             // 18432
#define TILEB ((BM + BN) * ROWB)     // 36864
#define SMEM_SZ (NS * TILEB)         // 110592 -> 2 CTAs/SM

__global__ __launch_bounds__(256, 2) void gemm_fused(
    const __half* __restrict__ xh, const __half* __restrict__ ctxh,
    const __half* __restrict__ WtM, const float* __restrict__ biasM,
    const __half* __restrict__ Wt3, const float* __restrict__ bias3,
    __half* __restrict__ outM, __half* __restrict__ out3)
{
    extern __shared__ char sm[];
    const uint32_t smb = smem_u32(sm);

    const int tid  = threadIdx.x;
    const int lane = tid & 31;
    const int wid  = tid >> 5;
    const int wm   = wid >> 2;        // 0..1  (64-row slice)
    const int wn   = wid & 3;         // 0..3  (32-col slice)

    const bool isG3 = blockIdx.x < 8;
    const int  bcol = (isG3 ? blockIdx.x : (blockIdx.x - 8)) * BN;
    const int  brow = blockIdx.y * BM;
    const int  N    = isG3 ? 1024 : 1280;
    const int  K1   = 1024;
    const int  K    = isG3 ? 2048 : 1024;
    const int  relu_upto = isG3 ? 0 : 768;
    const __half* A2  = ctxh;
    const __half* Bt  = isG3 ? Wt3 : WtM;
    const float*  bias = isG3 ? bias3 : biasM;
    __half* C = isG3 ? out3 : outM;

    const int iters = K / BK;

    const int a_row = wm * 64 + ((lane >> 3) & 1) * 8 + (lane & 7);
    const int a_k   = (lane >> 4) * 8;
    const int b_row = wn * 32 + (lane >> 4) * 8 + (lane & 7);
    const int b_k   = ((lane >> 3) & 1) * 8;

    // loader: (BM+BN)=256 rows x 64 halves = 8 chunks/row, 8/thread
    auto load_tile = [&](int stage, int kt) {
        const uint32_t sbase = smb + (uint32_t)(stage * TILEB);
#pragma unroll
        for (int j = 0; j < 8; j++) {
            const int c = tid + 256 * j;
            const int row = c >> 3;
            const int col = (c & 7) * 8;   // halves
            const uint32_t dst = sbase + (uint32_t)(row * ROWB + col * 2);
            const __half* src;
            if (row < BM) {
                src = (kt < K1)
                    ? xh + (size_t)(brow + row) * K1 + kt + col
                    : A2 + (size_t)(brow + row) * K1 + (kt - K1) + col;
            } else {
                src = Bt + (size_t)(bcol + row - BM) * K + kt + col;
            }
            cp_async16(dst, src);
        }
    };

    float acc[4][4][4];
#pragma unroll
    for (int i = 0; i < 4; i++)
#pragma unroll
        for (int j = 0; j < 4; j++)
#pragma unroll
            for (int q = 0; q < 4; q++) acc[i][j][q] = 0.f;

#pragma unroll
    for (int s = 0; s < NS - 1; s++) {
        load_tile(s, s * BK);
        cp_commit();
    }

    for (int i = 0; i < iters; i++) {
        cp_wait<NS - 2>();
        __syncthreads();
        if (i + NS - 1 < iters) load_tile((i + NS - 1) % NS, (i + NS - 1) * BK);
        cp_commit();

        const uint32_t sa  = smb + (uint32_t)((i % NS) * TILEB);
        const uint32_t sbB = sa + ASZB;

#pragma unroll
        for (int ks = 0; ks < 4; ks++) {
            uint32_t af[4][4];
#pragma unroll
            for (int mt = 0; mt < 4; mt++)
                ldsm_x4(af[mt], sa + (uint32_t)((a_row + mt * 16) * ROWB + (ks * 16 + a_k) * 2));
            uint32_t bf[2][4];
#pragma unroll
            for (int np = 0; np < 2; np++)
                ldsm_x4(bf[np], sbB + (uint32_t)((b_row + np * 16) * ROWB + (ks * 16 + b_k) * 2));
#pragma unroll
            for (int mt = 0; mt < 4; mt++)
#pragma unroll
                for (int nt = 0; nt < 4; nt++)
                    mma_f16(acc[mt][nt], af[mt], &bf[nt >> 1][(nt & 1) * 2]);
        }
    }

    // Epilogue: bias (+relu for cols<relu_upto), fp16 output
#pragma unroll
    for (int mt = 0; mt < 4; mt++) {
        const int gr0 = brow + wm * 64 + mt * 16 + (lane >> 2);
#pragma unroll
        for (int h = 0; h < 2; h++) {
            const int row = gr0 + 8 * h;
#pragma unroll
            for (int nt = 0; nt < 4; nt++) {
                const int gc = bcol + wn * 32 + nt * 8 + (lane & 3) * 2;
                float v0 = acc[mt][nt][2 * h]     + bias[gc];
                float v1 = acc[mt][nt][2 * h + 1] + bias[gc + 1];
                if (gc < relu_upto) { v0 = fmaxf(v0, 0.f); v1 = fmaxf(v1, 0.f); }
                *reinterpret_cast<__half2*>(C + (size_t)row * N + gc) =
                    __floats2half2_rn(v0, v1);
            }
        }
    }
}

// ---------------------------------------------------------------------------
// fused head: out_x copy + fp16 convert + chunk partial sums (reads x ONCE)
// ---------------------------------------------------------------------------
#define NCH 64
#define CH 32

__global__ __launch_bounds__(256) void fuse_head(
    const float* __restrict__ x, float* __restrict__ out_x, __half* __restrict__ xh)
{
    const int b = blockIdx.x, ch = blockIdx.y;
    const int d = threadIdx.x;
    const size_t base = ((size_t)b * kS + (size_t)ch * CH) * kD + d;
    float s[4] = {0, 0, 0, 0};
    for (int t = 0; t < CH; t++) {
#pragma unroll
        for (int dd = 0; dd < 4; dd++) {
            const size_t idx = base + (size_t)t * kD + dd * 256;
            const float v = x[idx];
            out_x[idx] = v;
            xh[idx] = __float2half(v);
            s[dd] += v;
        }
    }
    float* pp = g_part + ((size_t)b * NCH + ch) * kD + d;
#pragma unroll
    for (int dd = 0; dd < 4; dd++) pp[dd * 256] = s[dd];
}

// ---------------------------------------------------------------------------
// ctx_emit: exclusive scan over chunk partials + in-chunk scan (reads xh)
// ---------------------------------------------------------------------------
__global__ __launch_bounds__(256) void ctx_emit(const __half* __restrict__ xh) {
    const int b = blockIdx.x, ch = blockIdx.y;
    const int d = threadIdx.x;
    float pre[4] = {0, 0, 0, 0}, tot[4] = {0, 0, 0, 0};
    for (int c = 0; c < NCH; c++) {
        const float* pp = g_part + ((size_t)b * NCH + c) * kD + d;
#pragma unroll
        for (int dd = 0; dd < 4; dd++) {
            float p = pp[dd * 256];
            if (c < ch) pre[dd] += p;
            tot[dd] += p;
        }
    }
    const float inv_edge = 1.f / (float)(kS - 1);
    const size_t base = ((size_t)b * kS + (size_t)ch * CH) * kD + d;
    __half* cp = g_ctxh + base;
    const __half* xp = xh + base;
    for (int t = 0; t < CH; t++) {
        const int tg = ch * CH + t;
        const bool edge = (tg == 0) || (tg == kS - 1);
        const float ip = edge ? inv_edge : (0.5f / fmaxf((float)tg, 1.f));
        const float is = edge ? inv_edge : (0.5f / fmaxf((float)(kS - 1 - tg), 1.f));
#pragma unroll
        for (int dd = 0; dd < 4; dd++) {
            float xv = __half2float(xp[(size_t)t * kD + dd * 256]);
            float prefix = pre[dd];
            pre[dd] += xv;
            float suffix = tot[dd] - pre[dd];
            cp[(size_t)t * kD + dd * 256] = __float2half(prefix * ip + suffix * is);
        }
    }
}

// ---------------------------------------------------------------------------
// ONE fused weight transpose: all 4 weights -> fp16 [N,K]
// tile map: [0,512) Wcc1, [512,768) Wbe1, [768,1280) Wcr1, [1280,3328) Wcd1
// ---------------------------------------------------------------------------
__global__ __launch_bounds__(256) void transpose_all(
    const float* __restrict__ Wcc1, const float* __restrict__ Wbe1,
    const float* __restrict__ Wcr1, const float* __restrict__ Wcd1,
    __half* __restrict__ wth)
{
    __shared__ float tile[32][33];
    const int t = blockIdx.x;
    const float* W; __half* Wt; int K, N, tn, tk;
    if (t < 512)       { W = Wcc1; Wt = wth;                           K = 1024; N = 512;  int lt = t;        tn = lt % 16; tk = lt / 16; }
    else if (t < 768)  { W = Wbe1; Wt = wth + (size_t)512 * 1024;      K = 1024; N = 256;  int lt = t - 512;  tn = lt % 8;  tk = lt / 8;  }
    else if (t < 1280) { W = Wcr1; Wt = wth + (size_t)768 * 1024;      K = 1024; N = 512;  int lt = t - 768;  tn = lt % 16; tk = lt / 16; }
    else               { W = Wcd1; Wt = wth + WTH_CD1;                 K = 2048; N = 1024; int lt = t - 1280; tn = lt % 32; tk = lt / 32; }

    const int n0 = tn * 32, k0 = tk * 32;
    const int tx = threadIdx.x & 31, ty = threadIdx.x >> 5;
#pragma unroll
    for (int i = ty; i < 32; i += 8)
        tile[i][tx] = W[(size_t)(k0 + i) * N + n0 + tx];
    __syncthreads();
#pragma unroll
    for (int i = ty; i < 32; i += 8)
        Wt[(size_t)(n0 + i) * K + k0 + tx] = __float2half(tile[tx][i]);
}

// ---------------------------------------------------------------------------
// content_types: per-row dot-5 over K=512 (g_bigh cols 0..511), softmax(5)
// ---------------------------------------------------------------------------
__global__ __launch_bounds__(128) void content_kernel(
    const float* __restrict__ Wcc2, const float* __restrict__ bcc2,
    float* __restrict__ out_ct, float* __restrict__ out_rel)
{
    const int m = blockIdx.x;
    const __half* row = g_bigh + (size_t)m * 1280;
    float acc[5] = {0, 0, 0, 0, 0};
    for (int k = threadIdx.x; k < 512; k += 128) {
        float v = __half2float(row[k]);
#pragma unroll
        for (int c = 0; c < 5; c++) acc[c] = fmaf(v, Wcc2[k * 5 + c], acc[c]);
    }
#pragma unroll
    for (int c = 0; c < 5; c++)
#pragma unroll
        for (int o = 16; o; o >>= 1) acc[c] += __shfl_xor_sync(0xffffffffu, acc[c], o);

    __shared__ float s[4][5];
    const int w = threadIdx.x >> 5;
    if ((threadIdx.x & 31) == 0) {
#pragma unroll
        for (int c = 0; c < 5; c++) s[w][c] = acc[c];
    }
    __syncthreads();
    if (threadIdx.x == 0) {
        float t[5];
#pragma unroll
        for (int c = 0; c < 5; c++) t[c] = s[0][c] + s[1][c] + s[2][c] + s[3][c] + bcc2[c];
        float mx = t[0];
#pragma unroll
        for (int c = 1; c < 5; c++) mx = fmaxf(mx, t[c]);
        float e[5], sum = 0.f;
#pragma unroll
        for (int c = 0; c < 5; c++) { e[c] = expf(t[c] - mx); sum += e[c]; }
        const float inv = 1.f / sum;
        const float bw[5] = {0.1f, 1.0f, 0.8f, 0.3f, 0.5f};
        float ws = 0.f;
#pragma unroll
        for (int c = 0; c < 5; c++) {
            float p = e[c] * inv;
            out_ct[(size_t)m * 5 + c] = p;
            ws = fmaf(p, bw[c], ws);
        }
        out_rel[m] = 1.f - e[3] * inv;
        g_ctbw[m] = ws;
    }
}

__device__ __forceinline__ float block_reduce_sum(float v, float* sbuf) {
#pragma unroll
    for (int o = 16; o; o >>= 1) v += __shfl_xor_sync(0xffffffffu, v, o);
    const int w = threadIdx.x >> 5;
    __syncthreads();
    if ((threadIdx.x & 31) == 0) sbuf[w] = v;
    __syncthreads();
    if (threadIdx.x == 0) {
        float r = 0.f;
        for (int i = 0; i < (int)(blockDim.x >> 5); i++) r += sbuf[i];
        sbuf[0] = r;
    }
    __syncthreads();
    return sbuf[0];
}

// ---------------------------------------------------------------------------
// LN + exact GELU + dot(W_cd2) + sigmoid -> enhanced   (reads fp16 h)
// ---------------------------------------------------------------------------
__global__ __launch_bounds__(256) void ln_head_kernel(
    const float* __restrict__ gln, const float* __restrict__ beln,
    const float* __restrict__ W2, const float* __restrict__ b2,
    const float* __restrict__ ct, float* __restrict__ out_enh)
{
    __shared__ float sbuf[8];
    const int m = blockIdx.x;
    const int t = threadIdx.x;
    const __half2* hp2 = reinterpret_cast<const __half2*>(g_hh + (size_t)m * kD);
    const float2 p01 = __half22float2(hp2[2 * t]);
    const float2 p23 = __half22float2(hp2[2 * t + 1]);
    float4 v; v.x = p01.x; v.y = p01.y; v.z = p23.x; v.w = p23.y;

    float s = v.x + v.y + v.z + v.w;
    float q = v.x * v.x + v.y * v.y + v.z * v.z + v.w * v.w;
    const float sum = block_reduce_sum(s, sbuf);
    const float sq  = block_reduce_sum(q, sbuf);
    const float mu  = sum * (1.f / (float)kD);
    const float var = sq * (1.f / (float)kD) - mu * mu;
    const float rstd = rsqrtf(var + 1e-5f);

    const float4 gv  = reinterpret_cast<const float4*>(gln)[t];
    const float4 bev = reinterpret_cast<const float4*>(beln)[t];
    const float4 wv  = reinterpret_cast<const float4*>(W2)[t];

    const float kInvSqrt2 = 0.70710678118654752f;
    float dot = 0.f;
    float y;
    y = (v.x - mu) * rstd * gv.x + bev.x; y = 0.5f * y * (1.f + erff(y * kInvSqrt2)); dot = fmaf(y, wv.x, dot);
    y = (v.y - mu) * rstd * gv.y + bev.y; y = 0.5f * y * (1.f + erff(y * kInvSqrt2)); dot = fmaf(y, wv.y, dot);
    y = (v.z - mu) * rstd * gv.z + bev.z; y = 0.5f * y * (1.f + erff(y * kInvSqrt2)); dot = fmaf(y, wv.z, dot);
    y = (v.w - mu) * rstd * gv.w + bev.w; y = 0.5f * y * (1.f + erff(y * kInvSqrt2)); dot = fmaf(y, wv.w, dot);

    dot = block_reduce_sum(dot, sbuf);
    if (t == 0) {
        float cont = 1.f / (1.f + expf(-(dot + b2[0])));
        out_enh[m] = fmaxf(cont, ct[(size_t)m * 5 + 2]);
    }
}

// ---------------------------------------------------------------------------
// weighted_bias: warp-per-row dot over K=256 (g_bigh cols 512..767)
// ---------------------------------------------------------------------------
__global__ __launch_bounds__(256) void bias_out_kernel(
    const float* __restrict__ W, const float* __restrict__ b,
    float* __restrict__ out_wb)
{
    const int m = blockIdx.x * 8 + (threadIdx.x >> 5);
    const int l = threadIdx.x & 31;
    const __half* row = g_bigh + (size_t)m * 1280 + 512;
    float acc = 0.f;
#pragma unroll
    for (int i = 0; i < 8; i++)
        acc = fmaf(__half2float(row[l + 32 * i]), W[l + 32 * i], acc);
#pragma unroll
    for (int o = 16; o; o >>= 1) acc += __shfl_xor_sync(0xffffffffu, acc, o);
    if (l == 0) {
        float bs = 1.f / (1.f + expf(-(acc + b[0])));
        out_wb[m] = bs * g_ctbw[m];
    }
}

// ---------------------------------------------------------------------------
// credibility: pre-act (g_bigh cols 768..1279) + ct@Wtail, relu, dot, sigmoid
// ---------------------------------------------------------------------------
__global__ __launch_bounds__(256) void cred_kernel(
    const float* __restrict__ Wtail,
    const float* __restrict__ Wcr2, const float* __restrict__ bcr2,
    const float* __restrict__ ct, float* __restrict__ out_cred)
{
    __shared__ float swt[5 * 512 + 512];
    for (int i = threadIdx.x; i < 5 * 512; i += 256) swt[i] = Wtail[i];
    for (int i = threadIdx.x; i < 512; i += 256) swt[5 * 512 + i] = Wcr2[i];
    __syncthreads();

    const int w = threadIdx.x >> 5;
    const int l = threadIdx.x & 31;
    const float b0 = bcr2[0];

#pragma unroll
    for (int r = 0; r < 8; r++) {
        const int m = blockIdx.x * 64 + w * 8 + r;
        const __half* pre = g_bigh + (size_t)m * 1280 + 768;
        float ctm[5];
#pragma unroll
        for (int c = 0; c < 5; c++) ctm[c] = ct[(size_t)m * 5 + c];
        float acc = 0.f;
#pragma unroll
        for (int i = 0; i < 16; i++) {
            const int j = l + 32 * i;
            float v = __half2float(pre[j]);
#pragma unroll
            for (int c = 0; c < 5; c++) v = fmaf(ctm[c], swt[c * 512 + j], v);
            v = fmaxf(v, 0.f);
            acc = fmaf(v, swt[5 * 512 + j], acc);
        }
#pragma unroll
        for (int o = 16; o; o >>= 1) acc += __shfl_xor_sync(0xffffffffu, acc, o);
        if (l == 0) out_cred[m] = 1.f / (1.f + expf(-(acc + b0)));
    }
}

// ---------------------------------------------------------------------------
// Launch
// ---------------------------------------------------------------------------
extern "C" void kernel_launch(void* const* d_in, const int* in_sizes, int n_in,
                              void* d_out, int out_size)
{
    (void)in_sizes; (void)n_in; (void)out_size;

    const float* x    = (const float*)d_in[0];
    const float* Wcc1 = (const float*)d_in[1];
    const float* bcc1 = (const float*)d_in[2];
    const float* Wcc2 = (const float*)d_in[3];
    const float* bcc2 = (const float*)d_in[4];
    const float* Wcd1 = (const float*)d_in[5];
    const float* bcd1 = (const float*)d_in[6];
    const float* gln  = (const float*)d_in[7];
    const float* beln = (const float*)d_in[8];
    const float* Wcd2 = (const float*)d_in[9];
    const float* bcd2 = (const float*)d_in[10];
    const float* Wbe1 = (const float*)d_in[11];
    const float* bbe1 = (const float*)d_in[12];
    const float* Wbe2 = (const float*)d_in[13];
    const float* bbe2 = (const float*)d_in[14];
    const float* Wcr1 = (const float*)d_in[15];
    const float* bcr1 = (const float*)d_in[16];
    const float* Wcr2 = (const float*)d_in[17];
    const float* bcr2 = (const float*)d_in[18];

    float* out_x    = (float*)d_out;
    float* out_ct   = out_x + (size_t)kM * kD;
    float* out_enh  = out_ct + (size_t)kM * kC;
    float* out_wb   = out_enh + kM;
    float* out_rel  = out_wb + kM;
    float* out_cred = out_rel + kM;

    __half *xh, *ctxh, *wth, *bigp, *hp;
    float *biasA;
    cudaGetSymbolAddress((void**)&xh,    g_xh);
    cudaGetSymbolAddress((void**)&ctxh,  g_ctxh);
    cudaGetSymbolAddress((void**)&wth,   g_wth);
    cudaGetSymbolAddress((void**)&bigp,  g_bigh);
    cudaGetSymbolAddress((void**)&hp,    g_hh);
    cudaGetSymbolAddress((void**)&biasA, g_biasA);

    cudaFuncSetAttribute(gemm_fused, cudaFuncAttributeMaxDynamicSharedMemorySize, SMEM_SZ);

    // fused: out_x copy + xh convert + chunk partials (x read once)
    fuse_head<<<dim3(kB, NCH), 256>>>(x, out_x, xh);

    // merged bias vector [bcc1 | bbe1 | bcr1]
    cudaMemcpyAsync(biasA,       bcc1, 512 * sizeof(float), cudaMemcpyDeviceToDevice, 0);
    cudaMemcpyAsync(biasA + 512, bbe1, 256 * sizeof(float), cudaMemcpyDeviceToDevice, 0);
    cudaMemcpyAsync(biasA + 768, bcr1, 512 * sizeof(float), cudaMemcpyDeviceToDevice, 0);

    // ONE fused transpose launch (all 4 weights)
    transpose_all<<<3328, 256>>>(Wcc1, Wbe1, Wcr1, Wcd1, wth);

    // ctx scan
    ctx_emit<<<dim3(kB, NCH), 256>>>(xh);

    // ONE fused GEMM launch: G3 (x<8) + merged (x in 8..17), 2 CTAs/SM
    gemm_fused<<<dim3(18, kM/BM), 256, SMEM_SZ>>>(
        xh, ctxh,
        wth + WTH_MERGED, biasA,
        wth + WTH_CD1, bcd1,
        bigp, hp);

    content_kernel<<<kM, 128>>>(Wcc2, bcc2, out_ct, out_rel);

    ln_head_kernel<<<kM, 256>>>(gln, beln, Wcd2, bcd2, out_ct, out_enh);

    bias_out_kernel<<<kM/8, 256>>>(Wbe2, bbe2, out_wb);

    cred_kernel<<<kM/64, 256>>>(Wcr1 + (size_t)1024 * 512, Wcr2, bcr2, out_ct, out_cred);
}

// round 9
// speedup vs baseline: 8.8337x; 1.0368x over previous
#include <cuda_runtime.h>
#include <cuda_fp16.h>
#include <math.h>
#include <stdint.h>

// Problem constants
#define kB 8
#define kS 2048
#define kD 1024
#define kC 5
#define kM (kB * kS)  // 16384

// ---------------------------------------------------------------------------
// Scratch (device globals)
// ---------------------------------------------------------------------------
__device__ __half g_xh  [(size_t)kM * kD];     // 32 MB
__device__ __half g_ctxh[(size_t)kM * kD];     // 32 MB
__device__ __half g_bigh[(size_t)kM * 1280];   // 42 MB  merged G1|G4|G6
__device__ __half g_hh  [(size_t)kM * kD];     // 32 MB  G3 out
__device__ float  g_part[(size_t)kB * 64 * kD];
__device__ __half g_wth[(size_t)1280*1024 + (size_t)1024*2048];
__device__ float  g_biasA[1280];

#define WTH_MERGED 0
#define WTH_CD1 ((size_t)1280 * 1024)

// ---------------------------------------------------------------------------
// helpers
// ---------------------------------------------------------------------------
__device__ __forceinline__ uint32_t smem_u32(const void* p) {
    uint32_t a;
    asm("{ .reg .u64 t; cvta.to.shared.u64 t, %1; cvt.u32.u64 %0, t; }"
        : "=r"(a) : "l"(p));
    return a;
}
__device__ __forceinline__ void cp_async16(uint32_t dst, const void* src) {
    asm volatile("cp.async.cg.shared.global [%0], [%1], 16;"
                 :: "r"(dst), "l"(src));
}
__device__ __forceinline__ void cp_commit() {
    asm volatile("cp.async.commit_group;" ::: "memory");
}
template <int N>
__device__ __forceinline__ void cp_wait() {
    asm volatile("cp.async.wait_group %0;" :: "n"(N) : "memory");
}
__device__ __forceinline__ void ldsm_x4(uint32_t* r, uint32_t addr) {
    asm volatile("ldmatrix.sync.aligned.m8n8.x4.shared.b16 {%0,%1,%2,%3}, [%4];"
                 : "=r"(r[0]), "=r"(r[1]), "=r"(r[2]), "=r"(r[3]) : "r"(addr));
}
__device__ __forceinline__ void mma_f16(float* d, const uint32_t* a, const uint32_t* b) {
    asm volatile(
        "mma.sync.aligned.m16n8k16.row.col.f32.f16.f16.f32 "
        "{%0,%1,%2,%3}, {%4,%5,%6,%7}, {%8,%9}, {%0,%1,%2,%3};"
        : "+f"(d[0]), "+f"(d[1]), "+f"(d[2]), "+f"(d[3])
        : "r"(a[0]), "r"(a[1]), "r"(a[2]), "r"(a[3]),
          "r"(b[0]), "r"(b[1]));
}

// ---------------------------------------------------------------------------
// FUSED fp16 mma GEMM, 2 CTAs/SM, register-double-buffered fragments.
//   blockIdx.x in [0,8):   G3   h = [xh|ctxh] @ Wcd1^T + bcd1  (N=1024, K=2048)
//   blockIdx.x in [8,18):  MRG  big = act(xh @ Wm^T + bm)      (N=1280, K=1024)
// CTA tile 128x128, BK=64, 256 threads (8 warps 2x4), warp tile 64x32.
// ---------------------------------------------------------------------------
#define BM 128
#define BN 128
#define BK 64
#define LDAH 72
#define ROWB (LDAH * 2)              // 144 bytes
#define NS 3
#define ASZB (BM * ROWB)             // 18432
#define TILEB ((BM + BN) * ROWB)     // 36864
#define SMEM_SZ (NS * TILEB)         // 110592 -> 2 CTAs/SM

__global__ __launch_bounds__(256, 2) void gemm_fused(
    const __half* __restrict__ xh, const __half* __restrict__ ctxh,
    const __half* __restrict__ WtM, const float* __restrict__ biasM,
    const __half* __restrict__ Wt3, const float* __restrict__ bias3,
    __half* __restrict__ outM, __half* __restrict__ out3)
{
    extern __shared__ char sm[];
    const uint32_t smb = smem_u32(sm);

    const int tid  = threadIdx.x;
    const int lane = tid & 31;
    const int wid  = tid >> 5;
    const int wm   = wid >> 2;
    const int wn   = wid & 3;

    const bool isG3 = blockIdx.x < 8;
    const int  bcol = (isG3 ? blockIdx.x : (blockIdx.x - 8)) * BN;
    const int  brow = blockIdx.y * BM;
    const int  N    = isG3 ? 1024 : 1280;
    const int  K1   = 1024;
    const int  K    = isG3 ? 2048 : 1024;
    const int  relu_upto = isG3 ? 0 : 768;
    const __half* A2  = ctxh;
    const __half* Bt  = isG3 ? Wt3 : WtM;
    const float*  bias = isG3 ? bias3 : biasM;
    __half* C = isG3 ? out3 : outM;

    const int iters = K / BK;

    const int a_row = wm * 64 + ((lane >> 3) & 1) * 8 + (lane & 7);
    const int a_k   = (lane >> 4) * 8;
    const int b_row = wn * 32 + (lane >> 4) * 8 + (lane & 7);
    const int b_k   = ((lane >> 3) & 1) * 8;

    auto load_tile = [&](int stage, int kt) {
        const uint32_t sbase = smb + (uint32_t)(stage * TILEB);
#pragma unroll
        for (int j = 0; j < 8; j++) {
            const int c = tid + 256 * j;
            const int row = c >> 3;
            const int col = (c & 7) * 8;
            const uint32_t dst = sbase + (uint32_t)(row * ROWB + col * 2);
            const __half* src;
            if (row < BM) {
                src = (kt < K1)
                    ? xh + (size_t)(brow + row) * K1 + kt + col
                    : A2 + (size_t)(brow + row) * K1 + (kt - K1) + col;
            } else {
                src = Bt + (size_t)(bcol + row - BM) * K + kt + col;
            }
            cp_async16(dst, src);
        }
    };

    float acc[4][4][4];
#pragma unroll
    for (int i = 0; i < 4; i++)
#pragma unroll
        for (int j = 0; j < 4; j++)
#pragma unroll
            for (int q = 0; q < 4; q++) acc[i][j][q] = 0.f;

#pragma unroll
    for (int s = 0; s < NS - 1; s++) {
        load_tile(s, s * BK);
        cp_commit();
    }

    for (int i = 0; i < iters; i++) {
        cp_wait<NS - 2>();
        __syncthreads();
        if (i + NS - 1 < iters) load_tile((i + NS - 1) % NS, (i + NS - 1) * BK);
        cp_commit();

        const uint32_t sa  = smb + (uint32_t)((i % NS) * TILEB);
        const uint32_t sbB = sa + ASZB;

        // register double-buffered fragments across ks
        uint32_t af[2][4][4], bf[2][2][4];
#pragma unroll
        for (int mt = 0; mt < 4; mt++)
            ldsm_x4(af[0][mt], sa + (uint32_t)((a_row + mt * 16) * ROWB + a_k * 2));
#pragma unroll
        for (int np = 0; np < 2; np++)
            ldsm_x4(bf[0][np], sbB + (uint32_t)((b_row + np * 16) * ROWB + b_k * 2));

#pragma unroll
        for (int ks = 0; ks < 4; ks++) {
            const int cur = ks & 1, nxt = cur ^ 1;
            if (ks < 3) {
#pragma unroll
                for (int mt = 0; mt < 4; mt++)
                    ldsm_x4(af[nxt][mt], sa + (uint32_t)((a_row + mt * 16) * ROWB + ((ks + 1) * 16 + a_k) * 2));
#pragma unroll
                for (int np = 0; np < 2; np++)
                    ldsm_x4(bf[nxt][np], sbB + (uint32_t)((b_row + np * 16) * ROWB + ((ks + 1) * 16 + b_k) * 2));
            }
#pragma unroll
            for (int mt = 0; mt < 4; mt++)
#pragma unroll
                for (int nt = 0; nt < 4; nt++)
                    mma_f16(acc[mt][nt], af[cur][mt], &bf[cur][nt >> 1][(nt & 1) * 2]);
        }
    }

    // Epilogue
#pragma unroll
    for (int mt = 0; mt < 4; mt++) {
        const int gr0 = brow + wm * 64 + mt * 16 + (lane >> 2);
#pragma unroll
        for (int h = 0; h < 2; h++) {
            const int row = gr0 + 8 * h;
#pragma unroll
            for (int nt = 0; nt < 4; nt++) {
                const int gc = bcol + wn * 32 + nt * 8 + (lane & 3) * 2;
                float v0 = acc[mt][nt][2 * h]     + bias[gc];
                float v1 = acc[mt][nt][2 * h + 1] + bias[gc + 1];
                if (gc < relu_upto) { v0 = fmaxf(v0, 0.f); v1 = fmaxf(v1, 0.f); }
                *reinterpret_cast<__half2*>(C + (size_t)row * N + gc) =
                    __floats2half2_rn(v0, v1);
            }
        }
    }
}

// ---------------------------------------------------------------------------
// fused head: out_x copy + fp16 convert + chunk partial sums (reads x ONCE)
// ---------------------------------------------------------------------------
#define NCH 64
#define CH 32

__global__ __launch_bounds__(256) void fuse_head(
    const float* __restrict__ x, float* __restrict__ out_x, __half* __restrict__ xh)
{
    const int b = blockIdx.x, ch = blockIdx.y;
    const int d = threadIdx.x;
    const size_t base = ((size_t)b * kS + (size_t)ch * CH) * kD + d;
    float s[4] = {0, 0, 0, 0};
    for (int t = 0; t < CH; t++) {
#pragma unroll
        for (int dd = 0; dd < 4; dd++) {
            const size_t idx = base + (size_t)t * kD + dd * 256;
            const float v = x[idx];
            out_x[idx] = v;
            xh[idx] = __float2half(v);
            s[dd] += v;
        }
    }
    float* pp = g_part + ((size_t)b * NCH + ch) * kD + d;
#pragma unroll
    for (int dd = 0; dd < 4; dd++) pp[dd * 256] = s[dd];
}

// ---------------------------------------------------------------------------
// ctx_emit: exclusive scan over chunk partials + in-chunk scan (reads xh)
// ---------------------------------------------------------------------------
__global__ __launch_bounds__(256) void ctx_emit(const __half* __restrict__ xh) {
    const int b = blockIdx.x, ch = blockIdx.y;
    const int d = threadIdx.x;
    float pre[4] = {0, 0, 0, 0}, tot[4] = {0, 0, 0, 0};
    for (int c = 0; c < NCH; c++) {
        const float* pp = g_part + ((size_t)b * NCH + c) * kD + d;
#pragma unroll
        for (int dd = 0; dd < 4; dd++) {
            float p = pp[dd * 256];
            if (c < ch) pre[dd] += p;
            tot[dd] += p;
        }
    }
    const float inv_edge = 1.f / (float)(kS - 1);
    const size_t base = ((size_t)b * kS + (size_t)ch * CH) * kD + d;
    __half* cp = g_ctxh + base;
    const __half* xp = xh + base;
    for (int t = 0; t < CH; t++) {
        const int tg = ch * CH + t;
        const bool edge = (tg == 0) || (tg == kS - 1);
        const float ip = edge ? inv_edge : (0.5f / fmaxf((float)tg, 1.f));
        const float is = edge ? inv_edge : (0.5f / fmaxf((float)(kS - 1 - tg), 1.f));
#pragma unroll
        for (int dd = 0; dd < 4; dd++) {
            float xv = __half2float(xp[(size_t)t * kD + dd * 256]);
            float prefix = pre[dd];
            pre[dd] += xv;
            float suffix = tot[dd] - pre[dd];
            cp[(size_t)t * kD + dd * 256] = __float2half(prefix * ip + suffix * is);
        }
    }
}

// ---------------------------------------------------------------------------
// ONE fused weight transpose + bias assembly.
// tiles: [0,512) Wcc1, [512,768) Wbe1, [768,1280) Wcr1, [1280,3328) Wcd1,
//        3328: biasA = [bcc1|bbe1|bcr1]
// ---------------------------------------------------------------------------
__global__ __launch_bounds__(256) void transpose_all(
    const float* __restrict__ Wcc1, const float* __restrict__ Wbe1,
    const float* __restrict__ Wcr1, const float* __restrict__ Wcd1,
    const float* __restrict__ bcc1, const float* __restrict__ bbe1,
    const float* __restrict__ bcr1,
    __half* __restrict__ wth, float* __restrict__ biasA)
{
    const int t = blockIdx.x;
    if (t == 3328) {
        const int i = threadIdx.x;
        if (i < 256) {
            biasA[i]       = bcc1[i];
            biasA[i + 256] = bcc1[i + 256];
            biasA[i + 512] = bbe1[i];
            biasA[i + 768] = bcr1[i];
            biasA[i + 1024] = bcr1[i + 256];
        }
        return;
    }
    __shared__ float tile[32][33];
    const float* W; __half* Wt; int K, N, tn, tk;
    if (t < 512)       { W = Wcc1; Wt = wth;                      K = 1024; N = 512;  int lt = t;        tn = lt % 16; tk = lt / 16; }
    else if (t < 768)  { W = Wbe1; Wt = wth + (size_t)512 * 1024; K = 1024; N = 256;  int lt = t - 512;  tn = lt % 8;  tk = lt / 8;  }
    else if (t < 1280) { W = Wcr1; Wt = wth + (size_t)768 * 1024; K = 1024; N = 512;  int lt = t - 768;  tn = lt % 16; tk = lt / 16; }
    else               { W = Wcd1; Wt = wth + WTH_CD1;            K = 2048; N = 1024; int lt = t - 1280; tn = lt % 32; tk = lt / 32; }

    const int n0 = tn * 32, k0 = tk * 32;
    const int tx = threadIdx.x & 31, ty = threadIdx.x >> 5;
#pragma unroll
    for (int i = ty; i < 32; i += 8)
        tile[i][tx] = W[(size_t)(k0 + i) * N + n0 + tx];
    __syncthreads();
#pragma unroll
    for (int i = ty; i < 32; i += 8)
        Wt[(size_t)(n0 + i) * K + k0 + tx] = __float2half(tile[tx][i]);
}

// ---------------------------------------------------------------------------
// MEGA epilogue: warp-per-row computes EVERYTHING downstream of the GEMMs.
//   content softmax -> ct, rel;  bias head -> wb;  cred head -> cred;
//   LN+GELU head -> enh.
// block = 256 thr (8 warps, 8 rows), grid = kM/8.
// ---------------------------------------------------------------------------
__global__ __launch_bounds__(256) void epilogue_kernel(
    const float* __restrict__ Wcc2, const float* __restrict__ bcc2,
    const float* __restrict__ Wbe2, const float* __restrict__ bbe2,
    const float* __restrict__ Wtail, const float* __restrict__ Wcr2,
    const float* __restrict__ bcr2,
    const float* __restrict__ gln, const float* __restrict__ beln,
    const float* __restrict__ Wcd2, const float* __restrict__ bcd2,
    float* __restrict__ out_ct, float* __restrict__ out_enh,
    float* __restrict__ out_wb, float* __restrict__ out_rel,
    float* __restrict__ out_cred)
{
    // smem: Wcc2[512*5] Wbe2[256] Wtail[5*512] Wcr2[512] gln[1024] beln[1024] Wcd2[1024]
    __shared__ float s_cc2[512 * 5];
    __shared__ float s_be2[256];
    __shared__ float s_tl[5 * 512];
    __shared__ float s_cr2[512];
    __shared__ float s_g[1024], s_b[1024], s_w2[1024];

    for (int i = threadIdx.x; i < 512 * 5; i += 256) s_cc2[i] = Wcc2[i];
    for (int i = threadIdx.x; i < 256; i += 256) s_be2[i] = Wbe2[i];
    for (int i = threadIdx.x; i < 5 * 512; i += 256) s_tl[i] = Wtail[i];
    for (int i = threadIdx.x; i < 512; i += 256) s_cr2[i] = Wcr2[i];
    for (int i = threadIdx.x; i < 1024; i += 256) {
        s_g[i] = gln[i]; s_b[i] = beln[i]; s_w2[i] = Wcd2[i];
    }
    __syncthreads();

    const int w = threadIdx.x >> 5;
    const int l = threadIdx.x & 31;
    const int m = blockIdx.x * 8 + w;

    const __half2* big2 = reinterpret_cast<const __half2*>(g_bigh + (size_t)m * 1280);

    // ---- content: dot-5 over cols [0,512) ----
    float acc[5] = {0, 0, 0, 0, 0};
#pragma unroll
    for (int i = 0; i < 8; i++) {
        const int k2 = l + 32 * i;            // half2 index, covers 512 halves
        const float2 v = __half22float2(big2[k2]);
        const int k = k2 * 2;
#pragma unroll
        for (int c = 0; c < 5; c++)
            acc[c] = fmaf(v.x, s_cc2[k * 5 + c], fmaf(v.y, s_cc2[(k + 1) * 5 + c], acc[c]));
    }
#pragma unroll
    for (int c = 0; c < 5; c++)
#pragma unroll
        for (int o = 16; o; o >>= 1) acc[c] += __shfl_xor_sync(0xffffffffu, acc[c], o);

    // softmax (all lanes redundantly)
    float t5[5];
#pragma unroll
    for (int c = 0; c < 5; c++) t5[c] = acc[c] + bcc2[c];
    float mx = t5[0];
#pragma unroll
    for (int c = 1; c < 5; c++) mx = fmaxf(mx, t5[c]);
    float e[5], sum = 0.f;
#pragma unroll
    for (int c = 0; c < 5; c++) { e[c] = expf(t5[c] - mx); sum += e[c]; }
    const float inv = 1.f / sum;
    float ct[5];
#pragma unroll
    for (int c = 0; c < 5; c++) ct[c] = e[c] * inv;

    if (l < 5) out_ct[(size_t)m * 5 + l] = ct[l];
    if (l == 0) out_rel[m] = 1.f - ct[3];
    const float ctbw = 0.1f * ct[0] + 1.0f * ct[1] + 0.8f * ct[2] + 0.3f * ct[3] + 0.5f * ct[4];

    // ---- bias head: cols [512,768) ----
    float ba = 0.f;
#pragma unroll
    for (int i = 0; i < 4; i++) {
        const int j2 = l + 32 * i;            // 128 half2 = 256 halves
        const float2 v = __half22float2(big2[256 + j2]);
        const int j = j2 * 2;
        ba = fmaf(v.x, s_be2[j], fmaf(v.y, s_be2[j + 1], ba));
    }
#pragma unroll
    for (int o = 16; o; o >>= 1) ba += __shfl_xor_sync(0xffffffffu, ba, o);
    if (l == 0) {
        float bs = 1.f / (1.f + expf(-(ba + bbe2[0])));
        out_wb[m] = bs * ctbw;
    }

    // ---- cred head: cols [768,1280) + ct@Wtail, relu, dot ----
    float ca = 0.f;
#pragma unroll
    for (int i = 0; i < 8; i++) {
        const int j2 = l + 32 * i;            // 256 half2 = 512 halves
        const float2 v = __half22float2(big2[384 + j2]);
        const int j = j2 * 2;
        float v0 = v.x, v1 = v.y;
#pragma unroll
        for (int c = 0; c < 5; c++) {
            v0 = fmaf(ct[c], s_tl[c * 512 + j],     v0);
            v1 = fmaf(ct[c], s_tl[c * 512 + j + 1], v1);
        }
        v0 = fmaxf(v0, 0.f); v1 = fmaxf(v1, 0.f);
        ca = fmaf(v0, s_cr2[j], fmaf(v1, s_cr2[j + 1], ca));
    }
#pragma unroll
    for (int o = 16; o; o >>= 1) ca += __shfl_xor_sync(0xffffffffu, ca, o);
    if (l == 0) out_cred[m] = 1.f / (1.f + expf(-(ca + bcr2[0])));

    // ---- LN + GELU + head: g_hh row ----
    const __half2* hh2 = reinterpret_cast<const __half2*>(g_hh + (size_t)m * kD);
    float hv[32];
    float sm1 = 0.f, sq = 0.f;
#pragma unroll
    for (int i = 0; i < 16; i++) {
        const float2 v = __half22float2(hh2[l + 32 * i]);
        hv[2 * i] = v.x; hv[2 * i + 1] = v.y;
        sm1 += v.x + v.y;
        sq  += v.x * v.x + v.y * v.y;
    }
#pragma unroll
    for (int o = 16; o; o >>= 1) {
        sm1 += __shfl_xor_sync(0xffffffffu, sm1, o);
        sq  += __shfl_xor_sync(0xffffffffu, sq,  o);
    }
    const float mu  = sm1 * (1.f / (float)kD);
    const float var = sq * (1.f / (float)kD) - mu * mu;
    const float rstd = rsqrtf(var + 1e-5f);
    const float kInvSqrt2 = 0.70710678118654752f;
    float dot = 0.f;
#pragma unroll
    for (int i = 0; i < 16; i++) {
        const int j = (l + 32 * i) * 2;
#pragma unroll
        for (int q = 0; q < 2; q++) {
            float y = (hv[2 * i + q] - mu) * rstd * s_g[j + q] + s_b[j + q];
            y = 0.5f * y * (1.f + erff(y * kInvSqrt2));
            dot = fmaf(y, s_w2[j + q], dot);
        }
    }
#pragma unroll
    for (int o = 16; o; o >>= 1) dot += __shfl_xor_sync(0xffffffffu, dot, o);
    if (l == 0) {
        float cont = 1.f / (1.f + expf(-(dot + bcd2[0])));
        out_enh[m] = fmaxf(cont, ct[2]);
    }
}

// ---------------------------------------------------------------------------
// Launch
// ---------------------------------------------------------------------------
extern "C" void kernel_launch(void* const* d_in, const int* in_sizes, int n_in,
                              void* d_out, int out_size)
{
    (void)in_sizes; (void)n_in; (void)out_size;

    const float* x    = (const float*)d_in[0];
    const float* Wcc1 = (const float*)d_in[1];
    const float* bcc1 = (const float*)d_in[2];
    const float* Wcc2 = (const float*)d_in[3];
    const float* bcc2 = (const float*)d_in[4];
    const float* Wcd1 = (const float*)d_in[5];
    const float* bcd1 = (const float*)d_in[6];
    const float* gln  = (const float*)d_in[7];
    const float* beln = (const float*)d_in[8];
    const float* Wcd2 = (const float*)d_in[9];
    const float* bcd2 = (const float*)d_in[10];
    const float* Wbe1 = (const float*)d_in[11];
    const float* bbe1 = (const float*)d_in[12];
    const float* Wbe2 = (const float*)d_in[13];
    const float* bbe2 = (const float*)d_in[14];
    const float* Wcr1 = (const float*)d_in[15];
    const float* bcr1 = (const float*)d_in[16];
    const float* Wcr2 = (const float*)d_in[17];
    const float* bcr2 = (const float*)d_in[18];

    float* out_x    = (float*)d_out;
    float* out_ct   = out_x + (size_t)kM * kD;
    float* out_enh  = out_ct + (size_t)kM * kC;
    float* out_wb   = out_enh + kM;
    float* out_rel  = out_wb + kM;
    float* out_cred = out_rel + kM;

    __half *xh, *ctxh, *wth, *bigp, *hp;
    float *biasA;
    cudaGetSymbolAddress((void**)&xh,    g_xh);
    cudaGetSymbolAddress((void**)&ctxh,  g_ctxh);
    cudaGetSymbolAddress((void**)&wth,   g_wth);
    cudaGetSymbolAddress((void**)&bigp,  g_bigh);
    cudaGetSymbolAddress((void**)&hp,    g_hh);
    cudaGetSymbolAddress((void**)&biasA, g_biasA);

    cudaFuncSetAttribute(gemm_fused, cudaFuncAttributeMaxDynamicSharedMemorySize, SMEM_SZ);

    // fused: out_x copy + xh convert + chunk partials (x read once)
    fuse_head<<<dim3(kB, NCH), 256>>>(x, out_x, xh);

    // ONE transpose/bias-assembly launch
    transpose_all<<<3329, 256>>>(Wcc1, Wbe1, Wcr1, Wcd1, bcc1, bbe1, bcr1, wth, biasA);

    // ctx scan
    ctx_emit<<<dim3(kB, NCH), 256>>>(xh);

    // ONE fused GEMM launch: G3 (x<8) + merged (x in 8..17), 2 CTAs/SM
    gemm_fused<<<dim3(18, kM/BM), 256, SMEM_SZ>>>(
        xh, ctxh,
        wth + WTH_MERGED, biasA,
        wth + WTH_CD1, bcd1,
        bigp, hp);

    // ONE mega epilogue
    epilogue_kernel<<<kM/8, 256>>>(
        Wcc2, bcc2, Wbe2, bbe2,
        Wcr1 + (size_t)1024 * 512, Wcr2, bcr2,
        gln, beln, Wcd2, bcd2,
        out_ct, out_enh, out_wb, out_rel, out_cred);
}

// round 10
// speedup vs baseline: 9.1454x; 1.0353x over previous
#include <cuda_runtime.h>
#include <cuda_fp16.h>
#include <math.h>
#include <stdint.h>

// Problem constants
#define kB 8
#define kS 2048
#define kD 1024
#define kC 5
#define kM (kB * kS)  // 16384

// ---------------------------------------------------------------------------
// Scratch (device globals)
// ---------------------------------------------------------------------------
__device__ __half g_xh  [(size_t)kM * kD];     // 32 MB
__device__ __half g_ctxh[(size_t)kM * kD];     // 32 MB
__device__ __half g_bigh[(size_t)kM * 1280];   // 42 MB  merged G1|G4|G6
__device__ __half g_hh  [(size_t)kM * kD];     // 32 MB  G3 out
__device__ float  g_part[(size_t)kB * 64 * kD];
__device__ __half g_wth[(size_t)1280*1024 + (size_t)1024*2048];
__device__ float  g_biasA[1280];

#define WTH_MERGED 0
#define WTH_CD1 ((size_t)1280 * 1024)

// ---------------------------------------------------------------------------
// helpers
// ---------------------------------------------------------------------------
__device__ __forceinline__ uint32_t smem_u32(const void* p) {
    uint32_t a;
    asm("{ .reg .u64 t; cvta.to.shared.u64 t, %1; cvt.u32.u64 %0, t; }"
        : "=r"(a) : "l"(p));
    return a;
}
__device__ __forceinline__ void cp_async16(uint32_t dst, const void* src) {
    asm volatile("cp.async.cg.shared.global [%0], [%1], 16;"
                 :: "r"(dst), "l"(src));
}
__device__ __forceinline__ void cp_commit() {
    asm volatile("cp.async.commit_group;" ::: "memory");
}
template <int N>
__device__ __forceinline__ void cp_wait() {
    asm volatile("cp.async.wait_group %0;" :: "n"(N) : "memory");
}
__device__ __forceinline__ void ldsm_x4(uint32_t* r, uint32_t addr) {
    asm volatile("ldmatrix.sync.aligned.m8n8.x4.shared.b16 {%0,%1,%2,%3}, [%4];"
                 : "=r"(r[0]), "=r"(r[1]), "=r"(r[2]), "=r"(r[3]) : "r"(addr));
}
__device__ __forceinline__ void mma_f16(float* d, const uint32_t* a, const uint32_t* b) {
    asm volatile(
        "mma.sync.aligned.m16n8k16.row.col.f32.f16.f16.f32 "
        "{%0,%1,%2,%3}, {%4,%5,%6,%7}, {%8,%9}, {%0,%1,%2,%3};"
        : "+f"(d[0]), "+f"(d[1]), "+f"(d[2]), "+f"(d[3])
        : "r"(a[0]), "r"(a[1]), "r"(a[2]), "r"(a[3]),
          "r"(b[0]), "r"(b[1]));
}

// ---------------------------------------------------------------------------
// FUSED fp16 mma GEMM, 2 CTAs/SM, 64x64 warp tiles (4 warps/CTA).
//   blockIdx.x in [0,8):   G3   h = [xh|ctxh] @ Wcd1^T + bcd1  (N=1024, K=2048)
//   blockIdx.x in [8,18):  MRG  big = act(xh @ Wm^T + bm)      (N=1280, K=1024)
// CTA tile 128x128, BK=64, 128 threads (2x2 warps), warp tile 64x64.
// Fragments double-buffered across ks (reg budget 256/thread).
// ---------------------------------------------------------------------------
#define BM 128
#define BN 128
#define BK 64
#define LDAH 72
#define ROWB (LDAH * 2)              // 144 bytes
#define NS 3
#define ASZB (BM * ROWB)             // 18432
#define TILEB ((BM + BN) * ROWB)     // 36864
#define SMEM_SZ (NS * TILEB)         // 110592 -> 2 CTAs/SM

__global__ __launch_bounds__(128, 2) void gemm_fused(
    const __half* __restrict__ xh, const __half* __restrict__ ctxh,
    const __half* __restrict__ WtM, const float* __restrict__ biasM,
    const __half* __restrict__ Wt3, const float* __restrict__ bias3,
    __half* __restrict__ outM, __half* __restrict__ out3)
{
    extern __shared__ char sm[];
    const uint32_t smb = smem_u32(sm);

    const int tid  = threadIdx.x;
    const int lane = tid & 31;
    const int wid  = tid >> 5;
    const int wm   = wid >> 1;        // 0..1  (64-row slice)
    const int wn   = wid & 1;         // 0..1  (64-col slice)

    const bool isG3 = blockIdx.x < 8;
    const int  bcol = (isG3 ? blockIdx.x : (blockIdx.x - 8)) * BN;
    const int  brow = blockIdx.y * BM;
    const int  N    = isG3 ? 1024 : 1280;
    const int  K1   = 1024;
    const int  K    = isG3 ? 2048 : 1024;
    const int  relu_upto = isG3 ? 0 : 768;
    const __half* A2  = ctxh;
    const __half* Bt  = isG3 ? Wt3 : WtM;
    const float*  bias = isG3 ? bias3 : biasM;
    __half* C = isG3 ? out3 : outM;

    const int iters = K / BK;

    const int a_row = wm * 64 + ((lane >> 3) & 1) * 8 + (lane & 7);
    const int a_k   = (lane >> 4) * 8;
    const int b_row = wn * 64 + (lane >> 4) * 8 + (lane & 7);
    const int b_k   = ((lane >> 3) & 1) * 8;

    // loader: 256 rows x 64 halves = 8 chunks/row = 2048 chunks, 16/thread
    auto load_tile = [&](int stage, int kt) {
        const uint32_t sbase = smb + (uint32_t)(stage * TILEB);
#pragma unroll
        for (int j = 0; j < 16; j++) {
            const int c = tid + 128 * j;
            const int row = c >> 3;
            const int col = (c & 7) * 8;
            const uint32_t dst = sbase + (uint32_t)(row * ROWB + col * 2);
            const __half* src;
            if (row < BM) {
                src = (kt < K1)
                    ? xh + (size_t)(brow + row) * K1 + kt + col
                    : A2 + (size_t)(brow + row) * K1 + (kt - K1) + col;
            } else {
                src = Bt + (size_t)(bcol + row - BM) * K + kt + col;
            }
            cp_async16(dst, src);
        }
    };

    float acc[4][8][4];
#pragma unroll
    for (int i = 0; i < 4; i++)
#pragma unroll
        for (int j = 0; j < 8; j++)
#pragma unroll
            for (int q = 0; q < 4; q++) acc[i][j][q] = 0.f;

#pragma unroll
    for (int s = 0; s < NS - 1; s++) {
        load_tile(s, s * BK);
        cp_commit();
    }

    for (int i = 0; i < iters; i++) {
        cp_wait<NS - 2>();
        __syncthreads();
        if (i + NS - 1 < iters) load_tile((i + NS - 1) % NS, (i + NS - 1) * BK);
        cp_commit();

        const uint32_t sa  = smb + (uint32_t)((i % NS) * TILEB);
        const uint32_t sbB = sa + ASZB;

        // double-buffered fragments across ks
        uint32_t af[2][4][4], bf[2][4][4];
#pragma unroll
        for (int mt = 0; mt < 4; mt++)
            ldsm_x4(af[0][mt], sa + (uint32_t)((a_row + mt * 16) * ROWB + a_k * 2));
#pragma unroll
        for (int np = 0; np < 4; np++)
            ldsm_x4(bf[0][np], sbB + (uint32_t)((b_row + np * 16) * ROWB + b_k * 2));

#pragma unroll
        for (int ks = 0; ks < 4; ks++) {
            const int cur = ks & 1, nxt = cur ^ 1;
            if (ks < 3) {
#pragma unroll
                for (int mt = 0; mt < 4; mt++)
                    ldsm_x4(af[nxt][mt], sa + (uint32_t)((a_row + mt * 16) * ROWB + ((ks + 1) * 16 + a_k) * 2));
#pragma unroll
                for (int np = 0; np < 4; np++)
                    ldsm_x4(bf[nxt][np], sbB + (uint32_t)((b_row + np * 16) * ROWB + ((ks + 1) * 16 + b_k) * 2));
            }
#pragma unroll
            for (int mt = 0; mt < 4; mt++)
#pragma unroll
                for (int nt = 0; nt < 8; nt++)
                    mma_f16(acc[mt][nt], af[cur][mt], &bf[cur][nt >> 1][(nt & 1) * 2]);
        }
    }

    // Epilogue: bias (+relu for cols<relu_upto), fp16 output
#pragma unroll
    for (int mt = 0; mt < 4; mt++) {
        const int gr0 = brow + wm * 64 + mt * 16 + (lane >> 2);
#pragma unroll
        for (int h = 0; h < 2; h++) {
            const int row = gr0 + 8 * h;
#pragma unroll
            for (int nt = 0; nt < 8; nt++) {
                const int gc = bcol + wn * 64 + nt * 8 + (lane & 3) * 2;
                float v0 = acc[mt][nt][2 * h]     + bias[gc];
                float v1 = acc[mt][nt][2 * h + 1] + bias[gc + 1];
                if (gc < relu_upto) { v0 = fmaxf(v0, 0.f); v1 = fmaxf(v1, 0.f); }
                *reinterpret_cast<__half2*>(C + (size_t)row * N + gc) =
                    __floats2half2_rn(v0, v1);
            }
        }
    }
}

// ---------------------------------------------------------------------------
// fused head: out_x copy + fp16 convert + chunk partial sums (reads x ONCE)
// ---------------------------------------------------------------------------
#define NCH 64
#define CH 32

__global__ __launch_bounds__(256) void fuse_head(
    const float* __restrict__ x, float* __restrict__ out_x, __half* __restrict__ xh)
{
    const int b = blockIdx.x, ch = blockIdx.y;
    const int d = threadIdx.x;
    const size_t base = ((size_t)b * kS + (size_t)ch * CH) * kD + d;
    float s[4] = {0, 0, 0, 0};
    for (int t = 0; t < CH; t++) {
#pragma unroll
        for (int dd = 0; dd < 4; dd++) {
            const size_t idx = base + (size_t)t * kD + dd * 256;
            const float v = x[idx];
            out_x[idx] = v;
            xh[idx] = __float2half(v);
            s[dd] += v;
        }
    }
    float* pp = g_part + ((size_t)b * NCH + ch) * kD + d;
#pragma unroll
    for (int dd = 0; dd < 4; dd++) pp[dd * 256] = s[dd];
}

// ---------------------------------------------------------------------------
// ctx_emit: exclusive scan over chunk partials + in-chunk scan (reads xh)
// ---------------------------------------------------------------------------
__global__ __launch_bounds__(256) void ctx_emit(const __half* __restrict__ xh) {
    const int b = blockIdx.x, ch = blockIdx.y;
    const int d = threadIdx.x;
    float pre[4] = {0, 0, 0, 0}, tot[4] = {0, 0, 0, 0};
    for (int c = 0; c < NCH; c++) {
        const float* pp = g_part + ((size_t)b * NCH + c) * kD + d;
#pragma unroll
        for (int dd = 0; dd < 4; dd++) {
            float p = pp[dd * 256];
            if (c < ch) pre[dd] += p;
            tot[dd] += p;
        }
    }
    const float inv_edge = 1.f / (float)(kS - 1);
    const size_t base = ((size_t)b * kS + (size_t)ch * CH) * kD + d;
    __half* cp = g_ctxh + base;
    const __half* xp = xh + base;
    for (int t = 0; t < CH; t++) {
        const int tg = ch * CH + t;
        const bool edge = (tg == 0) || (tg == kS - 1);
        const float ip = edge ? inv_edge : (0.5f / fmaxf((float)tg, 1.f));
        const float is = edge ? inv_edge : (0.5f / fmaxf((float)(kS - 1 - tg), 1.f));
#pragma unroll
        for (int dd = 0; dd < 4; dd++) {
            float xv = __half2float(xp[(size_t)t * kD + dd * 256]);
            float prefix = pre[dd];
            pre[dd] += xv;
            float suffix = tot[dd] - pre[dd];
            cp[(size_t)t * kD + dd * 256] = __float2half(prefix * ip + suffix * is);
        }
    }
}

// ---------------------------------------------------------------------------
// ONE fused weight transpose + bias assembly.
// ---------------------------------------------------------------------------
__global__ __launch_bounds__(256) void transpose_all(
    const float* __restrict__ Wcc1, const float* __restrict__ Wbe1,
    const float* __restrict__ Wcr1, const float* __restrict__ Wcd1,
    const float* __restrict__ bcc1, const float* __restrict__ bbe1,
    const float* __restrict__ bcr1,
    __half* __restrict__ wth, float* __restrict__ biasA)
{
    const int t = blockIdx.x;
    if (t == 3328) {
        const int i = threadIdx.x;
        if (i < 256) {
            biasA[i]       = bcc1[i];
            biasA[i + 256] = bcc1[i + 256];
            biasA[i + 512] = bbe1[i];
            biasA[i + 768] = bcr1[i];
            biasA[i + 1024] = bcr1[i + 256];
        }
        return;
    }
    __shared__ float tile[32][33];
    const float* W; __half* Wt; int K, N, tn, tk;
    if (t < 512)       { W = Wcc1; Wt = wth;                      K = 1024; N = 512;  int lt = t;        tn = lt % 16; tk = lt / 16; }
    else if (t < 768)  { W = Wbe1; Wt = wth + (size_t)512 * 1024; K = 1024; N = 256;  int lt = t - 512;  tn = lt % 8;  tk = lt / 8;  }
    else if (t < 1280) { W = Wcr1; Wt = wth + (size_t)768 * 1024; K = 1024; N = 512;  int lt = t - 768;  tn = lt % 16; tk = lt / 16; }
    else               { W = Wcd1; Wt = wth + WTH_CD1;            K = 2048; N = 1024; int lt = t - 1280; tn = lt % 32; tk = lt / 32; }

    const int n0 = tn * 32, k0 = tk * 32;
    const int tx = threadIdx.x & 31, ty = threadIdx.x >> 5;
#pragma unroll
    for (int i = ty; i < 32; i += 8)
        tile[i][tx] = W[(size_t)(k0 + i) * N + n0 + tx];
    __syncthreads();
#pragma unroll
    for (int i = ty; i < 32; i += 8)
        Wt[(size_t)(n0 + i) * K + k0 + tx] = __float2half(tile[tx][i]);
}

// ---------------------------------------------------------------------------
// MEGA epilogue: warp-per-row computes everything downstream of the GEMMs.
// ---------------------------------------------------------------------------
__global__ __launch_bounds__(256) void epilogue_kernel(
    const float* __restrict__ Wcc2, const float* __restrict__ bcc2,
    const float* __restrict__ Wbe2, const float* __restrict__ bbe2,
    const float* __restrict__ Wtail, const float* __restrict__ Wcr2,
    const float* __restrict__ bcr2,
    const float* __restrict__ gln, const float* __restrict__ beln,
    const float* __restrict__ Wcd2, const float* __restrict__ bcd2,
    float* __restrict__ out_ct, float* __restrict__ out_enh,
    float* __restrict__ out_wb, float* __restrict__ out_rel,
    float* __restrict__ out_cred)
{
    __shared__ float s_cc2[512 * 5];
    __shared__ float s_be2[256];
    __shared__ float s_tl[5 * 512];
    __shared__ float s_cr2[512];
    __shared__ float s_g[1024], s_b[1024], s_w2[1024];

    for (int i = threadIdx.x; i < 512 * 5; i += 256) s_cc2[i] = Wcc2[i];
    for (int i = threadIdx.x; i < 256; i += 256) s_be2[i] = Wbe2[i];
    for (int i = threadIdx.x; i < 5 * 512; i += 256) s_tl[i] = Wtail[i];
    for (int i = threadIdx.x; i < 512; i += 256) s_cr2[i] = Wcr2[i];
    for (int i = threadIdx.x; i < 1024; i += 256) {
        s_g[i] = gln[i]; s_b[i] = beln[i]; s_w2[i] = Wcd2[i];
    }
    __syncthreads();

    const int w = threadIdx.x >> 5;
    const int l = threadIdx.x & 31;
    const int m = blockIdx.x * 8 + w;

    const __half2* big2 = reinterpret_cast<const __half2*>(g_bigh + (size_t)m * 1280);

    // content: dot-5 over cols [0,512)
    float acc[5] = {0, 0, 0, 0, 0};
#pragma unroll
    for (int i = 0; i < 8; i++) {
        const int k2 = l + 32 * i;
        const float2 v = __half22float2(big2[k2]);
        const int k = k2 * 2;
#pragma unroll
        for (int c = 0; c < 5; c++)
            acc[c] = fmaf(v.x, s_cc2[k * 5 + c], fmaf(v.y, s_cc2[(k + 1) * 5 + c], acc[c]));
    }
#pragma unroll
    for (int c = 0; c < 5; c++)
#pragma unroll
        for (int o = 16; o; o >>= 1) acc[c] += __shfl_xor_sync(0xffffffffu, acc[c], o);

    float t5[5];
#pragma unroll
    for (int c = 0; c < 5; c++) t5[c] = acc[c] + bcc2[c];
    float mx = t5[0];
#pragma unroll
    for (int c = 1; c < 5; c++) mx = fmaxf(mx, t5[c]);
    float e[5], sum = 0.f;
#pragma unroll
    for (int c = 0; c < 5; c++) { e[c] = expf(t5[c] - mx); sum += e[c]; }
    const float inv = 1.f / sum;
    float ct[5];
#pragma unroll
    for (int c = 0; c < 5; c++) ct[c] = e[c] * inv;

    if (l < 5) out_ct[(size_t)m * 5 + l] = ct[l];
    if (l == 0) out_rel[m] = 1.f - ct[3];
    const float ctbw = 0.1f * ct[0] + 1.0f * ct[1] + 0.8f * ct[2] + 0.3f * ct[3] + 0.5f * ct[4];

    // bias head: cols [512,768)
    float ba = 0.f;
#pragma unroll
    for (int i = 0; i < 4; i++) {
        const int j2 = l + 32 * i;
        const float2 v = __half22float2(big2[256 + j2]);
        const int j = j2 * 2;
        ba = fmaf(v.x, s_be2[j], fmaf(v.y, s_be2[j + 1], ba));
    }
#pragma unroll
    for (int o = 16; o; o >>= 1) ba += __shfl_xor_sync(0xffffffffu, ba, o);
    if (l == 0) {
        float bs = 1.f / (1.f + expf(-(ba + bbe2[0])));
        out_wb[m] = bs * ctbw;
    }

    // cred head: cols [768,1280) + ct@Wtail, relu, dot
    float ca = 0.f;
#pragma unroll
    for (int i = 0; i < 8; i++) {
        const int j2 = l + 32 * i;
        const float2 v = __half22float2(big2[384 + j2]);
        const int j = j2 * 2;
        float v0 = v.x, v1 = v.y;
#pragma unroll
        for (int c = 0; c < 5; c++) {
            v0 = fmaf(ct[c], s_tl[c * 512 + j],     v0);
            v1 = fmaf(ct[c], s_tl[c * 512 + j + 1], v1);
        }
        v0 = fmaxf(v0, 0.f); v1 = fmaxf(v1, 0.f);
        ca = fmaf(v0, s_cr2[j], fmaf(v1, s_cr2[j + 1], ca));
    }
#pragma unroll
    for (int o = 16; o; o >>= 1) ca += __shfl_xor_sync(0xffffffffu, ca, o);
    if (l == 0) out_cred[m] = 1.f / (1.f + expf(-(ca + bcr2[0])));

    // LN + GELU + head
    const __half2* hh2 = reinterpret_cast<const __half2*>(g_hh + (size_t)m * kD);
    float hv[32];
    float sm1 = 0.f, sq = 0.f;
#pragma unroll
    for (int i = 0; i < 16; i++) {
        const float2 v = __half22float2(hh2[l + 32 * i]);
        hv[2 * i] = v.x; hv[2 * i + 1] = v.y;
        sm1 += v.x + v.y;
        sq  += v.x * v.x + v.y * v.y;
    }
#pragma unroll
    for (int o = 16; o; o >>= 1) {
        sm1 += __shfl_xor_sync(0xffffffffu, sm1, o);
        sq  += __shfl_xor_sync(0xffffffffu, sq,  o);
    }
    const float mu  = sm1 * (1.f / (float)kD);
    const float var = sq * (1.f / (float)kD) - mu * mu;
    const float rstd = rsqrtf(var + 1e-5f);
    const float kInvSqrt2 = 0.70710678118654752f;
    float dot = 0.f;
#pragma unroll
    for (int i = 0; i < 16; i++) {
        const int j = (l + 32 * i) * 2;
#pragma unroll
        for (int q = 0; q < 2; q++) {
            float y = (hv[2 * i + q] - mu) * rstd * s_g[j + q] + s_b[j + q];
            y = 0.5f * y * (1.f + erff(y * kInvSqrt2));
            dot = fmaf(y, s_w2[j + q], dot);
        }
    }
#pragma unroll
    for (int o = 16; o; o >>= 1) dot += __shfl_xor_sync(0xffffffffu, dot, o);
    if (l == 0) {
        float cont = 1.f / (1.f + expf(-(dot + bcd2[0])));
        out_enh[m] = fmaxf(cont, ct[2]);
    }
}

// ---------------------------------------------------------------------------
// Launch
// ---------------------------------------------------------------------------
extern "C" void kernel_launch(void* const* d_in, const int* in_sizes, int n_in,
                              void* d_out, int out_size)
{
    (void)in_sizes; (void)n_in; (void)out_size;

    const float* x    = (const float*)d_in[0];
    const float* Wcc1 = (const float*)d_in[1];
    const float* bcc1 = (const float*)d_in[2];
    const float* Wcc2 = (const float*)d_in[3];
    const float* bcc2 = (const float*)d_in[4];
    const float* Wcd1 = (const float*)d_in[5];
    const float* bcd1 = (const float*)d_in[6];
    const float* gln  = (const float*)d_in[7];
    const float* beln = (const float*)d_in[8];
    const float* Wcd2 = (const float*)d_in[9];
    const float* bcd2 = (const float*)d_in[10];
    const float* Wbe1 = (const float*)d_in[11];
    const float* bbe1 = (const float*)d_in[12];
    const float* Wbe2 = (const float*)d_in[13];
    const float* bbe2 = (const float*)d_in[14];
    const float* Wcr1 = (const float*)d_in[15];
    const float* bcr1 = (const float*)d_in[16];
    const float* Wcr2 = (const float*)d_in[17];
    const float* bcr2 = (const float*)d_in[18];

    float* out_x    = (float*)d_out;
    float* out_ct   = out_x + (size_t)kM * kD;
    float* out_enh  = out_ct + (size_t)kM * kC;
    float* out_wb   = out_enh + kM;
    float* out_rel  = out_wb + kM;
    float* out_cred = out_rel + kM;

    __half *xh, *ctxh, *wth, *bigp, *hp;
    float *biasA;
    cudaGetSymbolAddress((void**)&xh,    g_xh);
    cudaGetSymbolAddress((void**)&ctxh,  g_ctxh);
    cudaGetSymbolAddress((void**)&wth,   g_wth);
    cudaGetSymbolAddress((void**)&bigp,  g_bigh);
    cudaGetSymbolAddress((void**)&hp,    g_hh);
    cudaGetSymbolAddress((void**)&biasA, g_biasA);

    cudaFuncSetAttribute(gemm_fused, cudaFuncAttributeMaxDynamicSharedMemorySize, SMEM_SZ);

    // fused: out_x copy + xh convert + chunk partials (x read once)
    fuse_head<<<dim3(kB, NCH), 256>>>(x, out_x, xh);

    // ONE transpose/bias-assembly launch
    transpose_all<<<3329, 256>>>(Wcc1, Wbe1, Wcr1, Wcd1, bcc1, bbe1, bcr1, wth, biasA);

    // ctx scan
    ctx_emit<<<dim3(kB, NCH), 256>>>(xh);

    // ONE fused GEMM launch: G3 (x<8) + merged (x in 8..17), 2 CTAs/SM
    gemm_fused<<<dim3(18, kM/BM), 128, SMEM_SZ>>>(
        xh, ctxh,
        wth + WTH_MERGED, biasA,
        wth + WTH_CD1, bcd1,
        bigp, hp);

    // ONE mega epilogue
    epilogue_kernel<<<kM/8, 256>>>(
        Wcc2, bcc2, Wbe2, bbe2,
        Wcr1 + (size_t)1024 * 512, Wcr2, bcr2,
        gln, beln, Wcd2, bcd2,
        out_ct, out_enh, out_wb, out_rel, out_cred);
}

// round 11
// speedup vs baseline: 9.7404x; 1.0651x over previous
#include <cuda_runtime.h>
#include <cuda_fp16.h>
#include <math.h>
#include <stdint.h>

// Problem constants
#define kB 8
#define kS 2048
#define kD 1024
#define kC 5
#define kM (kB * kS)  // 16384

// ---------------------------------------------------------------------------
// Scratch (device globals)
// ---------------------------------------------------------------------------
__device__ __half g_xh  [(size_t)kM * kD];     // 32 MB
__device__ __half g_ctxh[(size_t)kM * kD];     // 32 MB
__device__ __half g_bigh[(size_t)kM * 1280];   // 42 MB  merged G1|G4|G6
__device__ __half g_hh  [(size_t)kM * kD];     // 32 MB  G3 out
__device__ float  g_part[(size_t)kB * 64 * kD];
__device__ __half g_wth[(size_t)1280*1024 + (size_t)1024*2048];
__device__ float  g_biasA[1280];

#define WTH_MERGED 0
#define WTH_CD1 ((size_t)1280 * 1024)

// ---------------------------------------------------------------------------
// helpers
// ---------------------------------------------------------------------------
__device__ __forceinline__ uint32_t smem_u32(const void* p) {
    uint32_t a;
    asm("{ .reg .u64 t; cvta.to.shared.u64 t, %1; cvt.u32.u64 %0, t; }"
        : "=r"(a) : "l"(p));
    return a;
}
__device__ __forceinline__ void cp_async16(uint32_t dst, const void* src) {
    asm volatile("cp.async.cg.shared.global [%0], [%1], 16;"
                 :: "r"(dst), "l"(src));
}
__device__ __forceinline__ void cp_commit() {
    asm volatile("cp.async.commit_group;" ::: "memory");
}
template <int N>
__device__ __forceinline__ void cp_wait() {
    asm volatile("cp.async.wait_group %0;" :: "n"(N) : "memory");
}
__device__ __forceinline__ void ldsm_x4(uint32_t* r, uint32_t addr) {
    asm volatile("ldmatrix.sync.aligned.m8n8.x4.shared.b16 {%0,%1,%2,%3}, [%4];"
                 : "=r"(r[0]), "=r"(r[1]), "=r"(r[2]), "=r"(r[3]) : "r"(addr));
}
__device__ __forceinline__ void mma_f16(float* d, const uint32_t* a, const uint32_t* b) {
    asm volatile(
        "mma.sync.aligned.m16n8k16.row.col.f32.f16.f16.f32 "
        "{%0,%1,%2,%3}, {%4,%5,%6,%7}, {%8,%9}, {%0,%1,%2,%3};"
        : "+f"(d[0]), "+f"(d[1]), "+f"(d[2]), "+f"(d[3])
        : "r"(a[0]), "r"(a[1]), "r"(a[2]), "r"(a[3]),
          "r"(b[0]), "r"(b[1]));
}

// ---------------------------------------------------------------------------
// FUSED fp16 mma GEMM, 2 CTAs/SM, 64x64 warp tiles, LPT 1-D grid.
//   bid in [0,1024):    G3   h = [xh|ctxh] @ Wcd1^T + bcd1  (long: 32 iters)
//   bid in [1024,2304): MRG  big = act(xh @ Wm^T + bm)      (short: 16 iters)
// CTA tile 128x128, BK=64, 128 threads (2x2 warps), warp tile 64x64.
// ---------------------------------------------------------------------------
#define BM 128
#define BN 128
#define BK 64
#define LDAH 72
#define ROWB (LDAH * 2)              // 144 bytes
#define NS 3
#define ASZB (BM * ROWB)             // 18432
#define TILEB ((BM + BN) * ROWB)     // 36864
#define SMEM_SZ (NS * TILEB)         // 110592 -> 2 CTAs/SM

__global__ __launch_bounds__(128, 2) void gemm_fused(
    const __half* __restrict__ xh, const __half* __restrict__ ctxh,
    const __half* __restrict__ WtM, const float* __restrict__ biasM,
    const __half* __restrict__ Wt3, const float* __restrict__ bias3,
    __half* __restrict__ outM, __half* __restrict__ out3)
{
    extern __shared__ char sm[];
    const uint32_t smb = smem_u32(sm);

    const int tid  = threadIdx.x;
    const int lane = tid & 31;
    const int wid  = tid >> 5;
    const int wm   = wid >> 1;
    const int wn   = wid & 1;

    const int  bid  = blockIdx.x;
    const bool isG3 = bid < 1024;
    int brow, bcol;
    if (isG3) { brow = (bid >> 3) * BM; bcol = (bid & 7) * BN; }
    else      { const int t = bid - 1024; brow = (t / 10) * BM; bcol = (t % 10) * BN; }

    const int  N    = isG3 ? 1024 : 1280;
    const int  K1   = 1024;
    const int  K    = isG3 ? 2048 : 1024;
    const int  relu_upto = isG3 ? 0 : 768;
    const __half* A2  = ctxh;
    const __half* Bt  = isG3 ? Wt3 : WtM;
    const float*  bias = isG3 ? bias3 : biasM;
    __half* C = isG3 ? out3 : outM;

    const int iters = K / BK;

    const int a_row = wm * 64 + ((lane >> 3) & 1) * 8 + (lane & 7);
    const int a_k   = (lane >> 4) * 8;
    const int b_row = wn * 64 + (lane >> 4) * 8 + (lane & 7);
    const int b_k   = ((lane >> 3) & 1) * 8;

    auto load_tile = [&](int stage, int kt) {
        const uint32_t sbase = smb + (uint32_t)(stage * TILEB);
#pragma unroll
        for (int j = 0; j < 16; j++) {
            const int c = tid + 128 * j;
            const int row = c >> 3;
            const int col = (c & 7) * 8;
            const uint32_t dst = sbase + (uint32_t)(row * ROWB + col * 2);
            const __half* src;
            if (row < BM) {
                src = (kt < K1)
                    ? xh + (size_t)(brow + row) * K1 + kt + col
                    : A2 + (size_t)(brow + row) * K1 + (kt - K1) + col;
            } else {
                src = Bt + (size_t)(bcol + row - BM) * K + kt + col;
            }
            cp_async16(dst, src);
        }
    };

    float acc[4][8][4];
#pragma unroll
    for (int i = 0; i < 4; i++)
#pragma unroll
        for (int j = 0; j < 8; j++)
#pragma unroll
            for (int q = 0; q < 4; q++) acc[i][j][q] = 0.f;

#pragma unroll
    for (int s = 0; s < NS - 1; s++) {
        load_tile(s, s * BK);
        cp_commit();
    }

    for (int i = 0; i < iters; i++) {
        cp_wait<NS - 2>();
        __syncthreads();
        if (i + NS - 1 < iters) load_tile((i + NS - 1) % NS, (i + NS - 1) * BK);
        cp_commit();

        const uint32_t sa  = smb + (uint32_t)((i % NS) * TILEB);
        const uint32_t sbB = sa + ASZB;

        uint32_t af[2][4][4], bf[2][4][4];
#pragma unroll
        for (int mt = 0; mt < 4; mt++)
            ldsm_x4(af[0][mt], sa + (uint32_t)((a_row + mt * 16) * ROWB + a_k * 2));
#pragma unroll
        for (int np = 0; np < 4; np++)
            ldsm_x4(bf[0][np], sbB + (uint32_t)((b_row + np * 16) * ROWB + b_k * 2));

#pragma unroll
        for (int ks = 0; ks < 4; ks++) {
            const int cur = ks & 1, nxt = cur ^ 1;
            if (ks < 3) {
#pragma unroll
                for (int mt = 0; mt < 4; mt++)
                    ldsm_x4(af[nxt][mt], sa + (uint32_t)((a_row + mt * 16) * ROWB + ((ks + 1) * 16 + a_k) * 2));
#pragma unroll
                for (int np = 0; np < 4; np++)
                    ldsm_x4(bf[nxt][np], sbB + (uint32_t)((b_row + np * 16) * ROWB + ((ks + 1) * 16 + b_k) * 2));
            }
#pragma unroll
            for (int mt = 0; mt < 4; mt++)
#pragma unroll
                for (int nt = 0; nt < 8; nt++)
                    mma_f16(acc[mt][nt], af[cur][mt], &bf[cur][nt >> 1][(nt & 1) * 2]);
        }
    }

    // Epilogue
#pragma unroll
    for (int mt = 0; mt < 4; mt++) {
        const int gr0 = brow + wm * 64 + mt * 16 + (lane >> 2);
#pragma unroll
        for (int h = 0; h < 2; h++) {
            const int row = gr0 + 8 * h;
#pragma unroll
            for (int nt = 0; nt < 8; nt++) {
                const int gc = bcol + wn * 64 + nt * 8 + (lane & 3) * 2;
                float v0 = acc[mt][nt][2 * h]     + bias[gc];
                float v1 = acc[mt][nt][2 * h + 1] + bias[gc + 1];
                if (gc < relu_upto) { v0 = fmaxf(v0, 0.f); v1 = fmaxf(v1, 0.f); }
                *reinterpret_cast<__half2*>(C + (size_t)row * N + gc) =
                    __floats2half2_rn(v0, v1);
            }
        }
    }
}

// ---------------------------------------------------------------------------
// head_all: blocks [0,512)   = fused x copy + fp16 convert + chunk partials
//           blocks [512,3841)= weight transposes (+ bias assembly @3840)
// All vectorized.
// ---------------------------------------------------------------------------
#define NCH 64
#define CH 32

__global__ __launch_bounds__(256) void head_all(
    const float* __restrict__ x, float* __restrict__ out_x, __half* __restrict__ xh,
    const float* __restrict__ Wcc1, const float* __restrict__ Wbe1,
    const float* __restrict__ Wcr1, const float* __restrict__ Wcd1,
    const float* __restrict__ bcc1, const float* __restrict__ bbe1,
    const float* __restrict__ bcr1,
    __half* __restrict__ wth, float* __restrict__ biasA)
{
    if (blockIdx.x < 512) {
        // ---- fuse_head part (vectorized float4) ----
        const int b = blockIdx.x >> 6, ch = blockIdx.x & 63;
        const int d0 = threadIdx.x * 4;
        const size_t base = ((size_t)b * kS + (size_t)ch * CH) * kD + d0;
        float4 s = {0.f, 0.f, 0.f, 0.f};
        for (int t = 0; t < CH; t++) {
            const size_t idx = base + (size_t)t * kD;
            const float4 v = *reinterpret_cast<const float4*>(x + idx);
            *reinterpret_cast<float4*>(out_x + idx) = v;
            __half2* hp = reinterpret_cast<__half2*>(xh + idx);
            hp[0] = __floats2half2_rn(v.x, v.y);
            hp[1] = __floats2half2_rn(v.z, v.w);
            s.x += v.x; s.y += v.y; s.z += v.z; s.w += v.w;
        }
        *reinterpret_cast<float4*>(g_part + ((size_t)b * NCH + ch) * kD + d0) = s;
        return;
    }

    const int t = blockIdx.x - 512;
    if (t == 3328) {
        const int i = threadIdx.x;
        biasA[i]        = bcc1[i];
        biasA[i + 256]  = bcc1[i + 256];
        biasA[i + 512]  = bbe1[i];
        biasA[i + 768]  = bcr1[i];
        biasA[i + 1024] = bcr1[i + 256];
        return;
    }
    __shared__ float tile[32][33];
    const float* W; __half* Wt; int K, N, tn, tk;
    if (t < 512)       { W = Wcc1; Wt = wth;                      K = 1024; N = 512;  int lt = t;        tn = lt % 16; tk = lt / 16; }
    else if (t < 768)  { W = Wbe1; Wt = wth + (size_t)512 * 1024; K = 1024; N = 256;  int lt = t - 512;  tn = lt % 8;  tk = lt / 8;  }
    else if (t < 1280) { W = Wcr1; Wt = wth + (size_t)768 * 1024; K = 1024; N = 512;  int lt = t - 768;  tn = lt % 16; tk = lt / 16; }
    else               { W = Wcd1; Wt = wth + WTH_CD1;            K = 2048; N = 1024; int lt = t - 1280; tn = lt % 32; tk = lt / 32; }

    const int n0 = tn * 32, k0 = tk * 32;
    const int tx = threadIdx.x & 31, ty = threadIdx.x >> 5;
#pragma unroll
    for (int i = ty; i < 32; i += 8)
        tile[i][tx] = W[(size_t)(k0 + i) * N + n0 + tx];
    __syncthreads();
#pragma unroll
    for (int i = ty; i < 32; i += 8)
        Wt[(size_t)(n0 + i) * K + k0 + tx] = __float2half(tile[tx][i]);
}

// ---------------------------------------------------------------------------
// ctx_emit: exclusive scan over chunk partials + in-chunk scan (vectorized)
// ---------------------------------------------------------------------------
__global__ __launch_bounds__(256) void ctx_emit(const __half* __restrict__ xh) {
    const int b = blockIdx.x, ch = blockIdx.y;
    const int d0 = threadIdx.x * 4;
    float pre[4] = {0, 0, 0, 0}, tot[4] = {0, 0, 0, 0};
    for (int c = 0; c < NCH; c++) {
        const float4 p = *reinterpret_cast<const float4*>(
            g_part + ((size_t)b * NCH + c) * kD + d0);
        if (c < ch) { pre[0] += p.x; pre[1] += p.y; pre[2] += p.z; pre[3] += p.w; }
        tot[0] += p.x; tot[1] += p.y; tot[2] += p.z; tot[3] += p.w;
    }
    const float inv_edge = 1.f / (float)(kS - 1);
    const size_t base = ((size_t)b * kS + (size_t)ch * CH) * kD + d0;
    for (int t = 0; t < CH; t++) {
        const int tg = ch * CH + t;
        const bool edge = (tg == 0) || (tg == kS - 1);
        const float ip = edge ? inv_edge : (0.5f / fmaxf((float)tg, 1.f));
        const float is = edge ? inv_edge : (0.5f / fmaxf((float)(kS - 1 - tg), 1.f));
        const size_t idx = base + (size_t)t * kD;
        const __half2* xp = reinterpret_cast<const __half2*>(xh + idx);
        const float2 v01 = __half22float2(xp[0]);
        const float2 v23 = __half22float2(xp[1]);
        float xv[4] = {v01.x, v01.y, v23.x, v23.y};
        float ov[4];
#pragma unroll
        for (int dd = 0; dd < 4; dd++) {
            float prefix = pre[dd];
            pre[dd] += xv[dd];
            float suffix = tot[dd] - pre[dd];
            ov[dd] = prefix * ip + suffix * is;
        }
        __half2* cp = reinterpret_cast<__half2*>(g_ctxh + idx);
        cp[0] = __floats2half2_rn(ov[0], ov[1]);
        cp[1] = __floats2half2_rn(ov[2], ov[3]);
    }
}

// ---------------------------------------------------------------------------
// MEGA epilogue: warp-per-row computes everything downstream of the GEMMs.
// ---------------------------------------------------------------------------
__global__ __launch_bounds__(256) void epilogue_kernel(
    const float* __restrict__ Wcc2, const float* __restrict__ bcc2,
    const float* __restrict__ Wbe2, const float* __restrict__ bbe2,
    const float* __restrict__ Wtail, const float* __restrict__ Wcr2,
    const float* __restrict__ bcr2,
    const float* __restrict__ gln, const float* __restrict__ beln,
    const float* __restrict__ Wcd2, const float* __restrict__ bcd2,
    float* __restrict__ out_ct, float* __restrict__ out_enh,
    float* __restrict__ out_wb, float* __restrict__ out_rel,
    float* __restrict__ out_cred)
{
    __shared__ float s_cc2[512 * 5];
    __shared__ float s_be2[256];
    __shared__ float s_tl[5 * 512];
    __shared__ float s_cr2[512];
    __shared__ float s_g[1024], s_b[1024], s_w2[1024];

    for (int i = threadIdx.x; i < 512 * 5; i += 256) s_cc2[i] = Wcc2[i];
    for (int i = threadIdx.x; i < 256; i += 256) s_be2[i] = Wbe2[i];
    for (int i = threadIdx.x; i < 5 * 512; i += 256) s_tl[i] = Wtail[i];
    for (int i = threadIdx.x; i < 512; i += 256) s_cr2[i] = Wcr2[i];
    for (int i = threadIdx.x; i < 1024; i += 256) {
        s_g[i] = gln[i]; s_b[i] = beln[i]; s_w2[i] = Wcd2[i];
    }
    __syncthreads();

    const int w = threadIdx.x >> 5;
    const int l = threadIdx.x & 31;
    const int m = blockIdx.x * 8 + w;

    const __half2* big2 = reinterpret_cast<const __half2*>(g_bigh + (size_t)m * 1280);

    // content: dot-5 over cols [0,512)
    float acc[5] = {0, 0, 0, 0, 0};
#pragma unroll
    for (int i = 0; i < 8; i++) {
        const int k2 = l + 32 * i;
        const float2 v = __half22float2(big2[k2]);
        const int k = k2 * 2;
#pragma unroll
        for (int c = 0; c < 5; c++)
            acc[c] = fmaf(v.x, s_cc2[k * 5 + c], fmaf(v.y, s_cc2[(k + 1) * 5 + c], acc[c]));
    }
#pragma unroll
    for (int c = 0; c < 5; c++)
#pragma unroll
        for (int o = 16; o; o >>= 1) acc[c] += __shfl_xor_sync(0xffffffffu, acc[c], o);

    float t5[5];
#pragma unroll
    for (int c = 0; c < 5; c++) t5[c] = acc[c] + bcc2[c];
    float mx = t5[0];
#pragma unroll
    for (int c = 1; c < 5; c++) mx = fmaxf(mx, t5[c]);
    float e[5], sum = 0.f;
#pragma unroll
    for (int c = 0; c < 5; c++) { e[c] = expf(t5[c] - mx); sum += e[c]; }
    const float inv = 1.f / sum;
    float ct[5];
#pragma unroll
    for (int c = 0; c < 5; c++) ct[c] = e[c] * inv;

    if (l < 5) out_ct[(size_t)m * 5 + l] = ct[l];
    if (l == 0) out_rel[m] = 1.f - ct[3];
    const float ctbw = 0.1f * ct[0] + 1.0f * ct[1] + 0.8f * ct[2] + 0.3f * ct[3] + 0.5f * ct[4];

    // bias head: cols [512,768)
    float ba = 0.f;
#pragma unroll
    for (int i = 0; i < 4; i++) {
        const int j2 = l + 32 * i;
        const float2 v = __half22float2(big2[256 + j2]);
        const int j = j2 * 2;
        ba = fmaf(v.x, s_be2[j], fmaf(v.y, s_be2[j + 1], ba));
    }
#pragma unroll
    for (int o = 16; o; o >>= 1) ba += __shfl_xor_sync(0xffffffffu, ba, o);
    if (l == 0) {
        float bs = 1.f / (1.f + expf(-(ba + bbe2[0])));
        out_wb[m] = bs * ctbw;
    }

    // cred head: cols [768,1280) + ct@Wtail, relu, dot
    float ca = 0.f;
#pragma unroll
    for (int i = 0; i < 8; i++) {
        const int j2 = l + 32 * i;
        const float2 v = __half22float2(big2[384 + j2]);
        const int j = j2 * 2;
        float v0 = v.x, v1 = v.y;
#pragma unroll
        for (int c = 0; c < 5; c++) {
            v0 = fmaf(ct[c], s_tl[c * 512 + j],     v0);
            v1 = fmaf(ct[c], s_tl[c * 512 + j + 1], v1);
        }
        v0 = fmaxf(v0, 0.f); v1 = fmaxf(v1, 0.f);
        ca = fmaf(v0, s_cr2[j], fmaf(v1, s_cr2[j + 1], ca));
    }
#pragma unroll
    for (int o = 16; o; o >>= 1) ca += __shfl_xor_sync(0xffffffffu, ca, o);
    if (l == 0) out_cred[m] = 1.f / (1.f + expf(-(ca + bcr2[0])));

    // LN + GELU + head
    const __half2* hh2 = reinterpret_cast<const __half2*>(g_hh + (size_t)m * kD);
    float hv[32];
    float sm1 = 0.f, sq = 0.f;
#pragma unroll
    for (int i = 0; i < 16; i++) {
        const float2 v = __half22float2(hh2[l + 32 * i]);
        hv[2 * i] = v.x; hv[2 * i + 1] = v.y;
        sm1 += v.x + v.y;
        sq  += v.x * v.x + v.y * v.y;
    }
#pragma unroll
    for (int o = 16; o; o >>= 1) {
        sm1 += __shfl_xor_sync(0xffffffffu, sm1, o);
        sq  += __shfl_xor_sync(0xffffffffu, sq,  o);
    }
    const float mu  = sm1 * (1.f / (float)kD);
    const float var = sq * (1.f / (float)kD) - mu * mu;
    const float rstd = rsqrtf(var + 1e-5f);
    const float kInvSqrt2 = 0.70710678118654752f;
    float dot = 0.f;
#pragma unroll
    for (int i = 0; i < 16; i++) {
        const int j = (l + 32 * i) * 2;
#pragma unroll
        for (int q = 0; q < 2; q++) {
            float y = (hv[2 * i + q] - mu) * rstd * s_g[j + q] + s_b[j + q];
            y = 0.5f * y * (1.f + erff(y * kInvSqrt2));
            dot = fmaf(y, s_w2[j + q], dot);
        }
    }
#pragma unroll
    for (int o = 16; o; o >>= 1) dot += __shfl_xor_sync(0xffffffffu, dot, o);
    if (l == 0) {
        float cont = 1.f / (1.f + expf(-(dot + bcd2[0])));
        out_enh[m] = fmaxf(cont, ct[2]);
    }
}

// ---------------------------------------------------------------------------
// Launch
// ---------------------------------------------------------------------------
extern "C" void kernel_launch(void* const* d_in, const int* in_sizes, int n_in,
                              void* d_out, int out_size)
{
    (void)in_sizes; (void)n_in; (void)out_size;

    const float* x    = (const float*)d_in[0];
    const float* Wcc1 = (const float*)d_in[1];
    const float* bcc1 = (const float*)d_in[2];
    const float* Wcc2 = (const float*)d_in[3];
    const float* bcc2 = (const float*)d_in[4];
    const float* Wcd1 = (const float*)d_in[5];
    const float* bcd1 = (const float*)d_in[6];
    const float* gln  = (const float*)d_in[7];
    const float* beln = (const float*)d_in[8];
    const float* Wcd2 = (const float*)d_in[9];
    const float* bcd2 = (const float*)d_in[10];
    const float* Wbe1 = (const float*)d_in[11];
    const float* bbe1 = (const float*)d_in[12];
    const float* Wbe2 = (const float*)d_in[13];
    const float* bbe2 = (const float*)d_in[14];
    const float* Wcr1 = (const float*)d_in[15];
    const float* bcr1 = (const float*)d_in[16];
    const float* Wcr2 = (const float*)d_in[17];
    const float* bcr2 = (const float*)d_in[18];

    float* out_x    = (float*)d_out;
    float* out_ct   = out_x + (size_t)kM * kD;
    float* out_enh  = out_ct + (size_t)kM * kC;
    float* out_wb   = out_enh + kM;
    float* out_rel  = out_wb + kM;
    float* out_cred = out_rel + kM;

    __half *xh, *ctxh, *wth, *bigp, *hp;
    float *biasA;
    cudaGetSymbolAddress((void**)&xh,    g_xh);
    cudaGetSymbolAddress((void**)&ctxh,  g_ctxh);
    cudaGetSymbolAddress((void**)&wth,   g_wth);
    cudaGetSymbolAddress((void**)&bigp,  g_bigh);
    cudaGetSymbolAddress((void**)&hp,    g_hh);
    cudaGetSymbolAddress((void**)&biasA, g_biasA);

    cudaFuncSetAttribute(gemm_fused, cudaFuncAttributeMaxDynamicSharedMemorySize, SMEM_SZ);

    // fused head: x copy/convert/partials (blocks 0..511) + transposes (512..3840)
    head_all<<<3841, 256>>>(x, out_x, xh,
                            Wcc1, Wbe1, Wcr1, Wcd1, bcc1, bbe1, bcr1,
                            wth, biasA);

    // ctx scan
    ctx_emit<<<dim3(kB, NCH), 256>>>(xh);

    // ONE fused GEMM launch, LPT order (long G3 CTAs first), 2 CTAs/SM
    gemm_fused<<<2304, 128, SMEM_SZ>>>(
        xh, ctxh,
        wth + WTH_MERGED, biasA,
        wth + WTH_CD1, bcd1,
        bigp, hp);

    // ONE mega epilogue
    epilogue_kernel<<<kM/8, 256>>>(
        Wcc2, bcc2, Wbe2, bbe2,
        Wcr1 + (size_t)1024 * 512, Wcr2, bcr2,
        gln, beln, Wcd2, bcd2,
        out_ct, out_enh, out_wb, out_rel, out_cred);
}

// round 12
// speedup vs baseline: 9.7731x; 1.0034x over previous
#include <cuda_runtime.h>
#include <cuda_fp16.h>
#include <math.h>
#include <stdint.h>

// Problem constants
#define kB 8
#define kS 2048
#define kD 1024
#define kC 5
#define kM (kB * kS)  // 16384

// ---------------------------------------------------------------------------
// Scratch (device globals)
// ---------------------------------------------------------------------------
__device__ __half g_xh  [(size_t)kM * kD];     // 32 MB
__device__ __half g_ctxh[(size_t)kM * kD];     // 32 MB
__device__ __half g_bigh[(size_t)kM * 1280];   // 42 MB  merged G1|G4|G6
__device__ __half g_hh  [(size_t)kM * kD];     // 32 MB  G3 out
__device__ float  g_part[(size_t)kB * 64 * kD];
__device__ __half g_wth[(size_t)1280*1024 + (size_t)1024*2048];
__device__ float  g_biasA[1280];

#define WTH_MERGED 0
#define WTH_CD1 ((size_t)1280 * 1024)

// ---------------------------------------------------------------------------
// helpers
// ---------------------------------------------------------------------------
__device__ __forceinline__ uint32_t smem_u32(const void* p) {
    uint32_t a;
    asm("{ .reg .u64 t; cvta.to.shared.u64 t, %1; cvt.u32.u64 %0, t; }"
        : "=r"(a) : "l"(p));
    return a;
}
__device__ __forceinline__ void cp_async16(uint32_t dst, const void* src) {
    asm volatile("cp.async.cg.shared.global [%0], [%1], 16;"
                 :: "r"(dst), "l"(src));
}
__device__ __forceinline__ void cp_commit() {
    asm volatile("cp.async.commit_group;" ::: "memory");
}
template <int N>
__device__ __forceinline__ void cp_wait() {
    asm volatile("cp.async.wait_group %0;" :: "n"(N) : "memory");
}
__device__ __forceinline__ void ldsm_x4(uint32_t* r, uint32_t addr) {
    asm volatile("ldmatrix.sync.aligned.m8n8.x4.shared.b16 {%0,%1,%2,%3}, [%4];"
                 : "=r"(r[0]), "=r"(r[1]), "=r"(r[2]), "=r"(r[3]) : "r"(addr));
}
__device__ __forceinline__ void mma_f16(float* d, const uint32_t* a, const uint32_t* b) {
    asm volatile(
        "mma.sync.aligned.m16n8k16.row.col.f32.f16.f16.f32 "
        "{%0,%1,%2,%3}, {%4,%5,%6,%7}, {%8,%9}, {%0,%1,%2,%3};"
        : "+f"(d[0]), "+f"(d[1]), "+f"(d[2]), "+f"(d[3])
        : "r"(a[0]), "r"(a[1]), "r"(a[2]), "r"(a[3]),
          "r"(b[0]), "r"(b[1]));
}

// ---------------------------------------------------------------------------
// FUSED fp16 mma GEMM, 2 CTAs/SM, 64x64 warp tiles, LPT 1-D grid.
//   bid in [0,1024):    G3   h = [xh|ctxh] @ Wcd1^T + bcd1  (long: 32 iters)
//   bid in [1024,2304): MRG  big = act(xh @ Wm^T + bm)      (short: 16 iters)
// CTA tile 128x128, BK=64, 128 threads (2x2 warps), warp tile 64x64.
// ---------------------------------------------------------------------------
#define BM 128
#define BN 128
#define BK 64
#define LDAH 72
#define ROWB (LDAH * 2)              // 144 bytes
#define NS 3
#define ASZB (BM * ROWB)             // 18432
#define TILEB ((BM + BN) * ROWB)     // 36864
#define SMEM_SZ (NS * TILEB)         // 110592 -> 2 CTAs/SM

__global__ __launch_bounds__(128, 2) void gemm_fused(
    const __half* __restrict__ xh, const __half* __restrict__ ctxh,
    const __half* __restrict__ WtM, const float* __restrict__ biasM,
    const __half* __restrict__ Wt3, const float* __restrict__ bias3,
    __half* __restrict__ outM, __half* __restrict__ out3)
{
    extern __shared__ char sm[];
    const uint32_t smb = smem_u32(sm);

    const int tid  = threadIdx.x;
    const int lane = tid & 31;
    const int wid  = tid >> 5;
    const int wm   = wid >> 1;
    const int wn   = wid & 1;

    const int  bid  = blockIdx.x;
    const bool isG3 = bid < 1024;
    int brow, bcol;
    if (isG3) { brow = (bid >> 3) * BM; bcol = (bid & 7) * BN; }
    else      { const int t = bid - 1024; brow = (t / 10) * BM; bcol = (t % 10) * BN; }

    const int  N    = isG3 ? 1024 : 1280;
    const int  K1   = 1024;
    const int  K    = isG3 ? 2048 : 1024;
    const int  relu_upto = isG3 ? 0 : 768;
    const __half* A2  = ctxh;
    const __half* Bt  = isG3 ? Wt3 : WtM;
    const float*  bias = isG3 ? bias3 : biasM;
    __half* C = isG3 ? out3 : outM;

    const int iters = K / BK;

    const int a_row = wm * 64 + ((lane >> 3) & 1) * 8 + (lane & 7);
    const int a_k   = (lane >> 4) * 8;
    const int b_row = wn * 64 + (lane >> 4) * 8 + (lane & 7);
    const int b_k   = ((lane >> 3) & 1) * 8;

    auto load_tile = [&](int stage, int kt) {
        const uint32_t sbase = smb + (uint32_t)(stage * TILEB);
#pragma unroll
        for (int j = 0; j < 16; j++) {
            const int c = tid + 128 * j;
            const int row = c >> 3;
            const int col = (c & 7) * 8;
            const uint32_t dst = sbase + (uint32_t)(row * ROWB + col * 2);
            const __half* src;
            if (row < BM) {
                src = (kt < K1)
                    ? xh + (size_t)(brow + row) * K1 + kt + col
                    : A2 + (size_t)(brow + row) * K1 + (kt - K1) + col;
            } else {
                src = Bt + (size_t)(bcol + row - BM) * K + kt + col;
            }
            cp_async16(dst, src);
        }
    };

    float acc[4][8][4];
#pragma unroll
    for (int i = 0; i < 4; i++)
#pragma unroll
        for (int j = 0; j < 8; j++)
#pragma unroll
            for (int q = 0; q < 4; q++) acc[i][j][q] = 0.f;

#pragma unroll
    for (int s = 0; s < NS - 1; s++) {
        load_tile(s, s * BK);
        cp_commit();
    }

    for (int i = 0; i < iters; i++) {
        cp_wait<NS - 2>();
        __syncthreads();
        if (i + NS - 1 < iters) load_tile((i + NS - 1) % NS, (i + NS - 1) * BK);
        cp_commit();

        const uint32_t sa  = smb + (uint32_t)((i % NS) * TILEB);
        const uint32_t sbB = sa + ASZB;

        uint32_t af[2][4][4], bf[2][4][4];
#pragma unroll
        for (int mt = 0; mt < 4; mt++)
            ldsm_x4(af[0][mt], sa + (uint32_t)((a_row + mt * 16) * ROWB + a_k * 2));
#pragma unroll
        for (int np = 0; np < 4; np++)
            ldsm_x4(bf[0][np], sbB + (uint32_t)((b_row + np * 16) * ROWB + b_k * 2));

#pragma unroll
        for (int ks = 0; ks < 4; ks++) {
            const int cur = ks & 1, nxt = cur ^ 1;
            if (ks < 3) {
#pragma unroll
                for (int mt = 0; mt < 4; mt++)
                    ldsm_x4(af[nxt][mt], sa + (uint32_t)((a_row + mt * 16) * ROWB + ((ks + 1) * 16 + a_k) * 2));
#pragma unroll
                for (int np = 0; np < 4; np++)
                    ldsm_x4(bf[nxt][np], sbB + (uint32_t)((b_row + np * 16) * ROWB + ((ks + 1) * 16 + b_k) * 2));
            }
#pragma unroll
            for (int mt = 0; mt < 4; mt++)
#pragma unroll
                for (int nt = 0; nt < 8; nt++)
                    mma_f16(acc[mt][nt], af[cur][mt], &bf[cur][nt >> 1][(nt & 1) * 2]);
        }
    }

    // Epilogue
#pragma unroll
    for (int mt = 0; mt < 4; mt++) {
        const int gr0 = brow + wm * 64 + mt * 16 + (lane >> 2);
#pragma unroll
        for (int h = 0; h < 2; h++) {
            const int row = gr0 + 8 * h;
#pragma unroll
            for (int nt = 0; nt < 8; nt++) {
                const int gc = bcol + wn * 64 + nt * 8 + (lane & 3) * 2;
                float v0 = acc[mt][nt][2 * h]     + bias[gc];
                float v1 = acc[mt][nt][2 * h + 1] + bias[gc + 1];
                if (gc < relu_upto) { v0 = fmaxf(v0, 0.f); v1 = fmaxf(v1, 0.f); }
                *reinterpret_cast<__half2*>(C + (size_t)row * N + gc) =
                    __floats2half2_rn(v0, v1);
            }
        }
    }
}

// ---------------------------------------------------------------------------
// head_all: blocks [0,512)   = fused x copy + fp16 convert + chunk partials
//           blocks [512,3841)= weight transposes (+ bias assembly @3840)
// ---------------------------------------------------------------------------
#define NCH 64
#define CH 32

__global__ __launch_bounds__(256) void head_all(
    const float* __restrict__ x, float* __restrict__ out_x, __half* __restrict__ xh,
    const float* __restrict__ Wcc1, const float* __restrict__ Wbe1,
    const float* __restrict__ Wcr1, const float* __restrict__ Wcd1,
    const float* __restrict__ bcc1, const float* __restrict__ bbe1,
    const float* __restrict__ bcr1,
    __half* __restrict__ wth, float* __restrict__ biasA)
{
    if (blockIdx.x < 512) {
        const int b = blockIdx.x >> 6, ch = blockIdx.x & 63;
        const int d0 = threadIdx.x * 4;
        const size_t base = ((size_t)b * kS + (size_t)ch * CH) * kD + d0;
        float4 s = {0.f, 0.f, 0.f, 0.f};
        for (int t = 0; t < CH; t++) {
            const size_t idx = base + (size_t)t * kD;
            const float4 v = *reinterpret_cast<const float4*>(x + idx);
            *reinterpret_cast<float4*>(out_x + idx) = v;
            __half2* hp = reinterpret_cast<__half2*>(xh + idx);
            hp[0] = __floats2half2_rn(v.x, v.y);
            hp[1] = __floats2half2_rn(v.z, v.w);
            s.x += v.x; s.y += v.y; s.z += v.z; s.w += v.w;
        }
        *reinterpret_cast<float4*>(g_part + ((size_t)b * NCH + ch) * kD + d0) = s;
        return;
    }

    const int t = blockIdx.x - 512;
    if (t == 3328) {
        const int i = threadIdx.x;
        biasA[i]        = bcc1[i];
        biasA[i + 256]  = bcc1[i + 256];
        biasA[i + 512]  = bbe1[i];
        biasA[i + 768]  = bcr1[i];
        biasA[i + 1024] = bcr1[i + 256];
        return;
    }
    __shared__ float tile[32][33];
    const float* W; __half* Wt; int K, N, tn, tk;
    if (t < 512)       { W = Wcc1; Wt = wth;                      K = 1024; N = 512;  int lt = t;        tn = lt % 16; tk = lt / 16; }
    else if (t < 768)  { W = Wbe1; Wt = wth + (size_t)512 * 1024; K = 1024; N = 256;  int lt = t - 512;  tn = lt % 8;  tk = lt / 8;  }
    else if (t < 1280) { W = Wcr1; Wt = wth + (size_t)768 * 1024; K = 1024; N = 512;  int lt = t - 768;  tn = lt % 16; tk = lt / 16; }
    else               { W = Wcd1; Wt = wth + WTH_CD1;            K = 2048; N = 1024; int lt = t - 1280; tn = lt % 32; tk = lt / 32; }

    const int n0 = tn * 32, k0 = tk * 32;
    const int tx = threadIdx.x & 31, ty = threadIdx.x >> 5;
#pragma unroll
    for (int i = ty; i < 32; i += 8)
        tile[i][tx] = W[(size_t)(k0 + i) * N + n0 + tx];
    __syncthreads();
#pragma unroll
    for (int i = ty; i < 32; i += 8)
        Wt[(size_t)(n0 + i) * K + k0 + tx] = __float2half(tile[tx][i]);
}

// ---------------------------------------------------------------------------
// ctx_emit: exclusive scan over chunk partials + in-chunk scan (vectorized)
// ---------------------------------------------------------------------------
__global__ __launch_bounds__(256) void ctx_emit(const __half* __restrict__ xh) {
    const int b = blockIdx.x, ch = blockIdx.y;
    const int d0 = threadIdx.x * 4;
    float pre[4] = {0, 0, 0, 0}, tot[4] = {0, 0, 0, 0};
    for (int c = 0; c < NCH; c++) {
        const float4 p = *reinterpret_cast<const float4*>(
            g_part + ((size_t)b * NCH + c) * kD + d0);
        if (c < ch) { pre[0] += p.x; pre[1] += p.y; pre[2] += p.z; pre[3] += p.w; }
        tot[0] += p.x; tot[1] += p.y; tot[2] += p.z; tot[3] += p.w;
    }
    const float inv_edge = 1.f / (float)(kS - 1);
    const size_t base = ((size_t)b * kS + (size_t)ch * CH) * kD + d0;
    for (int t = 0; t < CH; t++) {
        const int tg = ch * CH + t;
        const bool edge = (tg == 0) || (tg == kS - 1);
        const float ip = edge ? inv_edge : (0.5f / fmaxf((float)tg, 1.f));
        const float is = edge ? inv_edge : (0.5f / fmaxf((float)(kS - 1 - tg), 1.f));
        const size_t idx = base + (size_t)t * kD;
        const __half2* xp = reinterpret_cast<const __half2*>(xh + idx);
        const float2 v01 = __half22float2(xp[0]);
        const float2 v23 = __half22float2(xp[1]);
        float xv[4] = {v01.x, v01.y, v23.x, v23.y};
        float ov[4];
#pragma unroll
        for (int dd = 0; dd < 4; dd++) {
            float prefix = pre[dd];
            pre[dd] += xv[dd];
            float suffix = tot[dd] - pre[dd];
            ov[dd] = prefix * ip + suffix * is;
        }
        __half2* cp = reinterpret_cast<__half2*>(g_ctxh + idx);
        cp[0] = __floats2half2_rn(ov[0], ov[1]);
        cp[1] = __floats2half2_rn(ov[2], ov[3]);
    }
}

// ---------------------------------------------------------------------------
// MEGA epilogue v2: TWO warps per row (task-split).
//   task 0: content softmax -> ct/rel/ctbw, bias head -> wb, cred head -> cred
//   task 1: LN + exact GELU + W_cd2 dot -> enhanced (uses ct[2] via smem)
// block = 512 thr (16 warps = 8 rows x 2 tasks), grid = kM/8.
// ---------------------------------------------------------------------------
__global__ __launch_bounds__(512) void epilogue_kernel(
    const float* __restrict__ Wcc2, const float* __restrict__ bcc2,
    const float* __restrict__ Wbe2, const float* __restrict__ bbe2,
    const float* __restrict__ Wtail, const float* __restrict__ Wcr2,
    const float* __restrict__ bcr2,
    const float* __restrict__ gln, const float* __restrict__ beln,
    const float* __restrict__ Wcd2, const float* __restrict__ bcd2,
    float* __restrict__ out_ct, float* __restrict__ out_enh,
    float* __restrict__ out_wb, float* __restrict__ out_rel,
    float* __restrict__ out_cred)
{
    __shared__ float s_cc2[512 * 5];
    __shared__ float s_be2[256];
    __shared__ float s_tl[5 * 512];
    __shared__ float s_cr2[512];
    __shared__ float s_g[1024], s_b[1024], s_w2[1024];
    __shared__ float s_ct2[8];

    for (int i = threadIdx.x; i < 512 * 5; i += 512) s_cc2[i] = Wcc2[i];
    for (int i = threadIdx.x; i < 256; i += 512) s_be2[i] = Wbe2[i];
    for (int i = threadIdx.x; i < 5 * 512; i += 512) s_tl[i] = Wtail[i];
    for (int i = threadIdx.x; i < 512; i += 512) s_cr2[i] = Wcr2[i];
    for (int i = threadIdx.x; i < 1024; i += 512) {
        s_g[i] = gln[i]; s_b[i] = beln[i]; s_w2[i] = Wcd2[i];
    }
    __syncthreads();

    const int w    = threadIdx.x >> 5;
    const int l    = threadIdx.x & 31;
    const int row  = w >> 1;
    const int task = w & 1;
    const int m    = blockIdx.x * 8 + row;

    float cont = 0.f;   // task 1 result

    if (task == 0) {
        const __half2* big2 = reinterpret_cast<const __half2*>(g_bigh + (size_t)m * 1280);

        // content: dot-5 over cols [0,512)
        float acc[5] = {0, 0, 0, 0, 0};
#pragma unroll
        for (int i = 0; i < 8; i++) {
            const int k2 = l + 32 * i;
            const float2 v = __half22float2(big2[k2]);
            const int k = k2 * 2;
#pragma unroll
            for (int c = 0; c < 5; c++)
                acc[c] = fmaf(v.x, s_cc2[k * 5 + c], fmaf(v.y, s_cc2[(k + 1) * 5 + c], acc[c]));
        }
#pragma unroll
        for (int c = 0; c < 5; c++)
#pragma unroll
            for (int o = 16; o; o >>= 1) acc[c] += __shfl_xor_sync(0xffffffffu, acc[c], o);

        float t5[5];
#pragma unroll
        for (int c = 0; c < 5; c++) t5[c] = acc[c] + bcc2[c];
        float mx = t5[0];
#pragma unroll
        for (int c = 1; c < 5; c++) mx = fmaxf(mx, t5[c]);
        float e[5], sum = 0.f;
#pragma unroll
        for (int c = 0; c < 5; c++) { e[c] = expf(t5[c] - mx); sum += e[c]; }
        const float inv = 1.f / sum;
        float ct[5];
#pragma unroll
        for (int c = 0; c < 5; c++) ct[c] = e[c] * inv;

        if (l < 5) out_ct[(size_t)m * 5 + l] = ct[l];
        if (l == 0) { out_rel[m] = 1.f - ct[3]; s_ct2[row] = ct[2]; }
        const float ctbw = 0.1f * ct[0] + 1.0f * ct[1] + 0.8f * ct[2] + 0.3f * ct[3] + 0.5f * ct[4];

        // bias head: cols [512,768)
        float ba = 0.f;
#pragma unroll
        for (int i = 0; i < 4; i++) {
            const int j2 = l + 32 * i;
            const float2 v = __half22float2(big2[256 + j2]);
            const int j = j2 * 2;
            ba = fmaf(v.x, s_be2[j], fmaf(v.y, s_be2[j + 1], ba));
        }
#pragma unroll
        for (int o = 16; o; o >>= 1) ba += __shfl_xor_sync(0xffffffffu, ba, o);
        if (l == 0) {
            float bs = 1.f / (1.f + expf(-(ba + bbe2[0])));
            out_wb[m] = bs * ctbw;
        }

        // cred head: cols [768,1280) + ct@Wtail, relu, dot
        float ca = 0.f;
#pragma unroll
        for (int i = 0; i < 8; i++) {
            const int j2 = l + 32 * i;
            const float2 v = __half22float2(big2[384 + j2]);
            const int j = j2 * 2;
            float v0 = v.x, v1 = v.y;
#pragma unroll
            for (int c = 0; c < 5; c++) {
                v0 = fmaf(ct[c], s_tl[c * 512 + j],     v0);
                v1 = fmaf(ct[c], s_tl[c * 512 + j + 1], v1);
            }
            v0 = fmaxf(v0, 0.f); v1 = fmaxf(v1, 0.f);
            ca = fmaf(v0, s_cr2[j], fmaf(v1, s_cr2[j + 1], ca));
        }
#pragma unroll
        for (int o = 16; o; o >>= 1) ca += __shfl_xor_sync(0xffffffffu, ca, o);
        if (l == 0) out_cred[m] = 1.f / (1.f + expf(-(ca + bcr2[0])));
    } else {
        // LN + GELU + head on g_hh row
        const __half2* hh2 = reinterpret_cast<const __half2*>(g_hh + (size_t)m * kD);
        float hv[32];
        float sm1 = 0.f, sq = 0.f;
#pragma unroll
        for (int i = 0; i < 16; i++) {
            const float2 v = __half22float2(hh2[l + 32 * i]);
            hv[2 * i] = v.x; hv[2 * i + 1] = v.y;
            sm1 += v.x + v.y;
            sq  += v.x * v.x + v.y * v.y;
        }
#pragma unroll
        for (int o = 16; o; o >>= 1) {
            sm1 += __shfl_xor_sync(0xffffffffu, sm1, o);
            sq  += __shfl_xor_sync(0xffffffffu, sq,  o);
        }
        const float mu  = sm1 * (1.f / (float)kD);
        const float var = sq * (1.f / (float)kD) - mu * mu;
        const float rstd = rsqrtf(var + 1e-5f);
        const float kInvSqrt2 = 0.70710678118654752f;
        float dot = 0.f;
#pragma unroll
        for (int i = 0; i < 16; i++) {
            const int j = (l + 32 * i) * 2;
#pragma unroll
            for (int q = 0; q < 2; q++) {
                float y = (hv[2 * i + q] - mu) * rstd * s_g[j + q] + s_b[j + q];
                y = 0.5f * y * (1.f + erff(y * kInvSqrt2));
                dot = fmaf(y, s_w2[j + q], dot);
            }
        }
#pragma unroll
        for (int o = 16; o; o >>= 1) dot += __shfl_xor_sync(0xffffffffu, dot, o);
        cont = 1.f / (1.f + expf(-(dot + bcd2[0])));
    }

    __syncthreads();
    if (task == 1 && l == 0)
        out_enh[m] = fmaxf(cont, s_ct2[row]);
}

// ---------------------------------------------------------------------------
// Launch
// ---------------------------------------------------------------------------
extern "C" void kernel_launch(void* const* d_in, const int* in_sizes, int n_in,
                              void* d_out, int out_size)
{
    (void)in_sizes; (void)n_in; (void)out_size;

    const float* x    = (const float*)d_in[0];
    const float* Wcc1 = (const float*)d_in[1];
    const float* bcc1 = (const float*)d_in[2];
    const float* Wcc2 = (const float*)d_in[3];
    const float* bcc2 = (const float*)d_in[4];
    const float* Wcd1 = (const float*)d_in[5];
    const float* bcd1 = (const float*)d_in[6];
    const float* gln  = (const float*)d_in[7];
    const float* beln = (const float*)d_in[8];
    const float* Wcd2 = (const float*)d_in[9];
    const float* bcd2 = (const float*)d_in[10];
    const float* Wbe1 = (const float*)d_in[11];
    const float* bbe1 = (const float*)d_in[12];
    const float* Wbe2 = (const float*)d_in[13];
    const float* bbe2 = (const float*)d_in[14];
    const float* Wcr1 = (const float*)d_in[15];
    const float* bcr1 = (const float*)d_in[16];
    const float* Wcr2 = (const float*)d_in[17];
    const float* bcr2 = (const float*)d_in[18];

    float* out_x    = (float*)d_out;
    float* out_ct   = out_x + (size_t)kM * kD;
    float* out_enh  = out_ct + (size_t)kM * kC;
    float* out_wb   = out_enh + kM;
    float* out_rel  = out_wb + kM;
    float* out_cred = out_rel + kM;

    __half *xh, *ctxh, *wth, *bigp, *hp;
    float *biasA;
    cudaGetSymbolAddress((void**)&xh,    g_xh);
    cudaGetSymbolAddress((void**)&ctxh,  g_ctxh);
    cudaGetSymbolAddress((void**)&wth,   g_wth);
    cudaGetSymbolAddress((void**)&bigp,  g_bigh);
    cudaGetSymbolAddress((void**)&hp,    g_hh);
    cudaGetSymbolAddress((void**)&biasA, g_biasA);

    cudaFuncSetAttribute(gemm_fused, cudaFuncAttributeMaxDynamicSharedMemorySize, SMEM_SZ);

    // fused head: x copy/convert/partials (blocks 0..511) + transposes (512..3840)
    head_all<<<3841, 256>>>(x, out_x, xh,
                            Wcc1, Wbe1, Wcr1, Wcd1, bcc1, bbe1, bcr1,
                            wth, biasA);

    // ctx scan
    ctx_emit<<<dim3(kB, NCH), 256>>>(xh);

    // ONE fused GEMM launch, LPT order (long G3 CTAs first), 2 CTAs/SM
    gemm_fused<<<2304, 128, SMEM_SZ>>>(
        xh, ctxh,
        wth + WTH_MERGED, biasA,
        wth + WTH_CD1, bcd1,
        bigp, hp);

    // mega epilogue (2 warps per row, task-split)
    epilogue_kernel<<<kM/8, 512>>>(
        Wcc2, bcc2, Wbe2, bbe2,
        Wcr1 + (size_t)1024 * 512, Wcr2, bcr2,
        gln, beln, Wcd2, bcd2,
        out_ct, out_enh, out_wb, out_rel, out_cred);
}